// round 5
// baseline (speedup 1.0000x reference)
#include <cuda_runtime.h>
#include <cuda_bf16.h>
#include <cuda_fp16.h>
#include <cstdint>

#define NB   8
#define CIN  512
#define COUT 1024
#define PP   2048
#define NH   8
#define DH   128

typedef __nv_bfloat16 bf16;

// ---------------- device scratch (static: no allocation allowed) -------------
__device__ float g_Y[(size_t)3 * NB * COUT * PP];                    // 192 MB
__device__ float g_scale[3][COUT];
__device__ float g_shift[3][COUT];
__device__ bf16  g_Whi[3][COUT * CIN], g_Wlo[3][COUT * CIN];
__device__ bf16  g_xThi[(size_t)NB * PP * CIN], g_xTlo[(size_t)NB * PP * CIN];
__device__ half  g_Qhi[(size_t)NB * COUT * PP], g_Qlo[(size_t)NB * COUT * PP];   // fp16
__device__ half  g_KT[(size_t)NB * PP * COUT];                                   // fp16 single
__device__ half  g_VT[(size_t)NB * PP * COUT];                                   // fp16 single

// ---------------- PTX helpers (baseline PTX only) ----------------------------
__device__ __forceinline__ uint32_t smem_u32(const void* p) {
    uint32_t a;
    asm("{ .reg .u64 t; cvta.to.shared.u64 t, %1; cvt.u32.u64 %0, t; }" : "=r"(a) : "l"(p));
    return a;
}
__device__ __forceinline__ void cp16(uint32_t saddr, const void* g) {
    asm volatile("cp.async.cg.shared.global [%0], [%1], 16;" :: "r"(saddr), "l"(g));
}
#define CP_COMMIT() asm volatile("cp.async.commit_group;" ::: "memory")
template <int N>
__device__ __forceinline__ void cp_wait() {
    asm volatile("cp.async.wait_group %0;" :: "n"(N) : "memory");
}
__device__ __forceinline__ void lma4(uint32_t* r, uint32_t addr) {
    asm volatile("ldmatrix.sync.aligned.m8n8.x4.shared.b16 {%0,%1,%2,%3}, [%4];"
                 : "=r"(r[0]), "=r"(r[1]), "=r"(r[2]), "=r"(r[3]) : "r"(addr));
}
__device__ __forceinline__ void mma16816(float* d, const uint32_t* a, const uint32_t* b) {
    asm volatile("mma.sync.aligned.m16n8k16.row.col.f32.bf16.bf16.f32 "
                 "{%0,%1,%2,%3}, {%4,%5,%6,%7}, {%8,%9}, {%0,%1,%2,%3};"
                 : "+f"(d[0]), "+f"(d[1]), "+f"(d[2]), "+f"(d[3])
                 : "r"(a[0]), "r"(a[1]), "r"(a[2]), "r"(a[3]), "r"(b[0]), "r"(b[1]));
}
__device__ __forceinline__ void mma16816h(float* d, const uint32_t* a, const uint32_t* b) {
    asm volatile("mma.sync.aligned.m16n8k16.row.col.f32.f16.f16.f32 "
                 "{%0,%1,%2,%3}, {%4,%5,%6,%7}, {%8,%9}, {%0,%1,%2,%3};"
                 : "+f"(d[0]), "+f"(d[1]), "+f"(d[2]), "+f"(d[3])
                 : "r"(a[0]), "r"(a[1]), "r"(a[2]), "r"(a[3]), "r"(b[0]), "r"(b[1]));
}

// =============================================================================
// Projection GEMM (bf16 3-term, unchanged): 128x128 tile, K-chunks of 32
// =============================================================================
#define ROWB   80
#define MATB   (128 * ROWB)
#define STAGEB (4 * MATB)
#define OFF_AH 0
#define OFF_AL MATB
#define OFF_BH (2 * MATB)
#define OFF_BL (3 * MATB)
#define SMEM_BYTES (2 * STAGEB)

__device__ __forceinline__ void gemm_core(const bf16* __restrict__ Ah,
                                          const bf16* __restrict__ Al,
                                          const bf16* __restrict__ Bh,
                                          const bf16* __restrict__ Bl,
                                          size_t lda, size_t ldb, int K,
                                          float* __restrict__ C, size_t ldc,
                                          float alpha, int m0, int n0)
{
    extern __shared__ __align__(128) char smem[];
    const uint32_t sb = smem_u32(smem);
    const int tid = threadIdx.x;
    const int L = tid & 31;
    const int w = tid >> 5;
    const int wm = w >> 2, wn = w & 3;

    const int ck0 = tid * 2, ck1 = tid * 2 + 1;
    const int lr0 = ck0 >> 2, lc0 = ck0 & 3;
    const int lr1 = ck1 >> 2, lc1 = ck1 & 3;

    const bf16* pAh0 = Ah + (size_t)(m0 + lr0) * lda + lc0 * 8;
    const bf16* pAh1 = Ah + (size_t)(m0 + lr1) * lda + lc1 * 8;
    const bf16* pAl0 = Al + (size_t)(m0 + lr0) * lda + lc0 * 8;
    const bf16* pAl1 = Al + (size_t)(m0 + lr1) * lda + lc1 * 8;
    const bf16* pBh0 = Bh + (size_t)(n0 + lr0) * ldb + lc0 * 8;
    const bf16* pBh1 = Bh + (size_t)(n0 + lr1) * ldb + lc1 * 8;
    const bf16* pBl0 = Bl + (size_t)(n0 + lr0) * ldb + lc0 * 8;
    const bf16* pBl1 = Bl + (size_t)(n0 + lr1) * ldb + lc1 * 8;
    const uint32_t so0 = lr0 * ROWB + lc0 * 16;
    const uint32_t so1 = lr1 * ROWB + lc1 * 16;

    float acc[4][4][4];
#pragma unroll
    for (int mt = 0; mt < 4; mt++)
#pragma unroll
        for (int nt = 0; nt < 4; nt++)
#pragma unroll
            for (int i = 0; i < 4; i++) acc[mt][nt][i] = 0.0f;

    const int nch = K >> 5;
    {
        uint32_t base = sb;
        cp16(base + OFF_AH + so0, pAh0); cp16(base + OFF_AH + so1, pAh1);
        cp16(base + OFF_AL + so0, pAl0); cp16(base + OFF_AL + so1, pAl1);
        cp16(base + OFF_BH + so0, pBh0); cp16(base + OFF_BH + so1, pBh1);
        cp16(base + OFF_BL + so0, pBl0); cp16(base + OFF_BL + so1, pBl1);
        CP_COMMIT();
    }

    const uint32_t a_row = (uint32_t)(wm * 64 + ((L >> 3) & 1) * 8 + (L & 7));
    const uint32_t a_cc  = (uint32_t)(L >> 4);
    const uint32_t b_row = (uint32_t)(wn * 32 + ((L >> 4) << 3) + (L & 7));
    const uint32_t b_cc  = (uint32_t)((L >> 3) & 1);

    for (int ch = 0; ch < nch; ch++) {
        if (ch + 1 < nch) {
            uint32_t base = sb + ((ch + 1) & 1) * STAGEB;
            int kc = (ch + 1) * 32;
            cp16(base + OFF_AH + so0, pAh0 + kc); cp16(base + OFF_AH + so1, pAh1 + kc);
            cp16(base + OFF_AL + so0, pAl0 + kc); cp16(base + OFF_AL + so1, pAl1 + kc);
            cp16(base + OFF_BH + so0, pBh0 + kc); cp16(base + OFF_BH + so1, pBh1 + kc);
            cp16(base + OFF_BL + so0, pBl0 + kc); cp16(base + OFF_BL + so1, pBl1 + kc);
            CP_COMMIT();
            cp_wait<1>();
        } else {
            cp_wait<0>();
        }
        __syncthreads();

        uint32_t base = sb + (ch & 1) * STAGEB;
#pragma unroll
        for (int ks = 0; ks < 2; ks++) {
            uint32_t afh[4][4], afl[4][4], bfh[4][2], bfl[4][2];
            uint32_t acol = (a_cc + ks * 2) * 16;
            uint32_t bcol = (b_cc + ks * 2) * 16;
#pragma unroll
            for (int mt = 0; mt < 4; mt++) {
                uint32_t ro = (a_row + mt * 16) * ROWB;
                lma4(afh[mt], base + OFF_AH + ro + acol);
                lma4(afl[mt], base + OFF_AL + ro + acol);
            }
#pragma unroll
            for (int np = 0; np < 2; np++) {
                uint32_t ro = (b_row + np * 16) * ROWB;
                uint32_t t4[4];
                lma4(t4, base + OFF_BH + ro + bcol);
                bfh[2 * np][0] = t4[0]; bfh[2 * np][1] = t4[1];
                bfh[2 * np + 1][0] = t4[2]; bfh[2 * np + 1][1] = t4[3];
                lma4(t4, base + OFF_BL + ro + bcol);
                bfl[2 * np][0] = t4[0]; bfl[2 * np][1] = t4[1];
                bfl[2 * np + 1][0] = t4[2]; bfl[2 * np + 1][1] = t4[3];
            }
#pragma unroll
            for (int mt = 0; mt < 4; mt++)
#pragma unroll
                for (int nt = 0; nt < 4; nt++) {
                    mma16816(acc[mt][nt], afh[mt], bfh[nt]);
                    mma16816(acc[mt][nt], afh[mt], bfl[nt]);
                    mma16816(acc[mt][nt], afl[mt], bfh[nt]);
                }
        }
        __syncthreads();
    }

    const int tg = L >> 2, tp = L & 3;
#pragma unroll
    for (int mt = 0; mt < 4; mt++) {
        int r0 = m0 + wm * 64 + mt * 16 + tg;
#pragma unroll
        for (int nt = 0; nt < 4; nt++) {
            int c = n0 + wn * 32 + nt * 8 + tp * 2;
            float2 v0 = make_float2(alpha * acc[mt][nt][0], alpha * acc[mt][nt][1]);
            float2 v1 = make_float2(alpha * acc[mt][nt][2], alpha * acc[mt][nt][3]);
            *(float2*)&C[(size_t)r0 * ldc + c]       = v0;
            *(float2*)&C[(size_t)(r0 + 8) * ldc + c] = v1;
        }
    }
}

__global__ __launch_bounds__(256) void proj_gemm(void) {
    int z = blockIdx.z, proj = z >> 3, b = z & 7;
    gemm_core(g_Whi[proj], g_Wlo[proj],
              g_xThi + (size_t)b * PP * CIN, g_xTlo + (size_t)b * PP * CIN,
              CIN, CIN, CIN,
              g_Y + (size_t)z * COUT * PP, PP, 1.0f,
              blockIdx.y * 128, blockIdx.x * 128);
}

// =============================================================================
// Fused flash attention, fp16: S = K^T V (1 MMA term); O = P (Qh+Ql) (2 terms)
// One CTA per (b, h, i-tile of 128). 8 warps. V double-buffered, Q prefetched.
// =============================================================================
#define APITCH 272                       // 128 halves (256B) + 16B pad
#define TILEB  (128 * APITCH)            // 34816 per plane
#define SM_K   0
#define SM_V0  (1 * TILEB)
#define SM_V1  (2 * TILEB)
#define SM_QH  (3 * TILEB)
#define SM_QL  (4 * TILEB)
#define SM_P   (5 * TILEB)
#define SM_RM  (6 * TILEB)
#define SM_RS  (SM_RM + 2048)
#define SMEM_ATTN (SM_RS + 2048)         // 212992

__device__ __forceinline__ void load_plane(uint32_t sb, uint32_t off,
                                           const half* __restrict__ src,
                                           size_t stride, int tid) {
#pragma unroll
    for (int i = 0; i < 8; i++) {
        int idx = tid + i * 256;
        int r = idx >> 4, cc = idx & 15;
        cp16(sb + off + r * APITCH + cc * 16, src + (size_t)r * stride + cc * 8);
    }
}

__global__ __launch_bounds__(256, 1) void attn_fused(float* __restrict__ out) {
    extern __shared__ __align__(128) char smem[];
    const uint32_t sb = smem_u32(smem);
    const int tid = threadIdx.x;
    const int L = tid & 31, w = tid >> 5;
    const int wm = w >> 2, wn = w & 3;
    const int tg = L >> 2, tp = L & 3;
    const int it = blockIdx.x;
    const int z = blockIdx.y, b = z >> 3, h = z & 7;

    const half* Kp  = g_KT + ((size_t)b * PP + it * 128) * COUT + h * DH;
    const half* Vp  = g_VT + (size_t)b * PP * COUT + h * DH;
    const half* Qhp = g_Qhi + ((size_t)b * COUT + h * DH) * PP;
    const half* Qlp = g_Qlo + ((size_t)b * COUT + h * DH) * PP;

    // prologue: group0 = K + V(0); group1 = Q(0) hi/lo
    load_plane(sb, SM_K, Kp, COUT, tid);
    load_plane(sb, SM_V0, Vp, COUT, tid);
    CP_COMMIT();
    load_plane(sb, SM_QH, Qhp, PP, tid);
    load_plane(sb, SM_QL, Qlp, PP, tid);
    CP_COMMIT();

    const uint32_t a_row = (uint32_t)(wm * 64 + ((L >> 3) & 1) * 8 + (L & 7));
    const uint32_t a_cc  = (uint32_t)(L >> 4);
    const uint32_t b_row = (uint32_t)(wn * 32 + ((L >> 4) << 3) + (L & 7));
    const uint32_t b_cc  = (uint32_t)((L >> 3) & 1);

    const float cS = 1.4426950408889634f * 0.08838834764831845f;  // log2e / sqrt(128)

    float oacc[4][4][4];
    float mrow[4][2], lrow[4][2];
#pragma unroll
    for (int mt = 0; mt < 4; mt++) {
        mrow[mt][0] = mrow[mt][1] = -1e30f;
        lrow[mt][0] = lrow[mt][1] = 0.0f;
#pragma unroll
        for (int nt = 0; nt < 4; nt++)
#pragma unroll
            for (int i = 0; i < 4; i++) oacc[mt][nt][i] = 0.0f;
    }

    for (int jt = 0; jt < 16; jt++) {
        // V(jt) ready (all but newest group); Q(jt) may still be in flight
        cp_wait<1>();
        __syncthreads();

        const uint32_t vbase = sb + SM_V0 + (uint32_t)(jt & 1) * TILEB;

        // ---- S = K^T V (fp16, 1 term, k = 128) ----
        float sacc[4][4][4];
#pragma unroll
        for (int mt = 0; mt < 4; mt++)
#pragma unroll
            for (int nt = 0; nt < 4; nt++)
#pragma unroll
                for (int i = 0; i < 4; i++) sacc[mt][nt][i] = 0.0f;

#pragma unroll
        for (int ks = 0; ks < 8; ks++) {
            uint32_t af[4][4], bf[4][2];
            uint32_t acol = (a_cc + ks * 2) * 16;
            uint32_t bcol = (b_cc + ks * 2) * 16;
#pragma unroll
            for (int mt = 0; mt < 4; mt++)
                lma4(af[mt], sb + SM_K + (a_row + mt * 16) * APITCH + acol);
#pragma unroll
            for (int np = 0; np < 2; np++) {
                uint32_t t4[4];
                lma4(t4, vbase + (b_row + np * 16) * APITCH + bcol);
                bf[2 * np][0] = t4[0]; bf[2 * np][1] = t4[1];
                bf[2 * np + 1][0] = t4[2]; bf[2 * np + 1][1] = t4[3];
            }
#pragma unroll
            for (int mt = 0; mt < 4; mt++)
#pragma unroll
                for (int nt = 0; nt < 4; nt++)
                    mma16816h(sacc[mt][nt], af[mt], bf[nt]);
        }

        // prefetch V(jt+1) into the other buffer (hide behind softmax + O-MMA)
        if (jt + 1 < 16) {
            load_plane(sb, SM_V0 + (uint32_t)((jt + 1) & 1) * TILEB,
                       Vp + (size_t)(jt + 1) * 128 * COUT, COUT, tid);
            CP_COMMIT();
        }

        // scale into log2 domain, warp-level row maxes
        float wmax[4][2];
#pragma unroll
        for (int mt = 0; mt < 4; mt++) {
#pragma unroll
            for (int half_ = 0; half_ < 2; half_++) {
                float mv = -1e30f;
#pragma unroll
                for (int nt = 0; nt < 4; nt++) {
                    sacc[mt][nt][2 * half_]     *= cS;
                    sacc[mt][nt][2 * half_ + 1] *= cS;
                    mv = fmaxf(mv, fmaxf(sacc[mt][nt][2 * half_], sacc[mt][nt][2 * half_ + 1]));
                }
                mv = fmaxf(mv, __shfl_xor_sync(0xffffffffu, mv, 1));
                mv = fmaxf(mv, __shfl_xor_sync(0xffffffffu, mv, 2));
                wmax[mt][half_] = mv;
            }
        }
        if (tp == 0) {
#pragma unroll
            for (int mt = 0; mt < 4; mt++) {
                int r = wm * 64 + mt * 16 + tg;
                *(float*)(smem + SM_RM + (wn * 128 + r) * 4)     = wmax[mt][0];
                *(float*)(smem + SM_RM + (wn * 128 + r + 8) * 4) = wmax[mt][1];
            }
        }
        __syncthreads();                 // partial maxes visible (V buffer not touched)

        // block row max, online update, exp, P write (fp16 single plane), sums
        float wsum[4][2];
#pragma unroll
        for (int mt = 0; mt < 4; mt++) {
#pragma unroll
            for (int half_ = 0; half_ < 2; half_++) {
                int r = wm * 64 + mt * 16 + tg + half_ * 8;
                float bm = *(float*)(smem + SM_RM + r * 4);
                bm = fmaxf(bm, *(float*)(smem + SM_RM + (128 + r) * 4));
                bm = fmaxf(bm, *(float*)(smem + SM_RM + (256 + r) * 4));
                bm = fmaxf(bm, *(float*)(smem + SM_RM + (384 + r) * 4));
                float mn = fmaxf(mrow[mt][half_], bm);
                float sc = exp2f(mrow[mt][half_] - mn);
                mrow[mt][half_] = mn;
                lrow[mt][half_] *= sc;
                float rs = 0.0f;
#pragma unroll
                for (int nt = 0; nt < 4; nt++) {
                    oacc[mt][nt][2 * half_]     *= sc;
                    oacc[mt][nt][2 * half_ + 1] *= sc;
                    float p0 = exp2f(sacc[mt][nt][2 * half_]     - mn);
                    float p1 = exp2f(sacc[mt][nt][2 * half_ + 1] - mn);
                    rs += p0 + p1;
                    uint32_t col = wn * 32 + nt * 8 + 2 * tp;
                    *(half2*)(smem + SM_P + r * APITCH + col * 2) =
                        __halves2half2(__float2half_rn(p0), __float2half_rn(p1));
                }
                rs += __shfl_xor_sync(0xffffffffu, rs, 1);
                rs += __shfl_xor_sync(0xffffffffu, rs, 2);
                wsum[mt][half_] = rs;
            }
        }
        if (tp == 0) {
#pragma unroll
            for (int mt = 0; mt < 4; mt++) {
                int r = wm * 64 + mt * 16 + tg;
                *(float*)(smem + SM_RS + (wn * 128 + r) * 4)     = wsum[mt][0];
                *(float*)(smem + SM_RS + (wn * 128 + r + 8) * 4) = wsum[mt][1];
            }
        }
        // Q(jt) done (allow V(jt+1) still in flight)
        if (jt + 1 < 16) cp_wait<1>(); else cp_wait<0>();
        __syncthreads();                 // P + sums visible, Q ready

#pragma unroll
        for (int mt = 0; mt < 4; mt++) {
#pragma unroll
            for (int half_ = 0; half_ < 2; half_++) {
                int r = wm * 64 + mt * 16 + tg + half_ * 8;
                float bs = *(float*)(smem + SM_RS + r * 4)
                         + *(float*)(smem + SM_RS + (128 + r) * 4)
                         + *(float*)(smem + SM_RS + (256 + r) * 4)
                         + *(float*)(smem + SM_RS + (384 + r) * 4);
                lrow[mt][half_] += bs;
            }
        }

        // ---- O += P (Qh + Ql)  (fp16, 2 terms, k = 128) ----
#pragma unroll
        for (int ks = 0; ks < 8; ks++) {
            uint32_t af[4][4], bfh[4][2], bfl[4][2];
            uint32_t acol = (a_cc + ks * 2) * 16;
            uint32_t bcol = (b_cc + ks * 2) * 16;
#pragma unroll
            for (int mt = 0; mt < 4; mt++)
                lma4(af[mt], sb + SM_P + (a_row + mt * 16) * APITCH + acol);
#pragma unroll
            for (int np = 0; np < 2; np++) {
                uint32_t ro = (b_row + np * 16) * APITCH;
                uint32_t t4[4];
                lma4(t4, sb + SM_QH + ro + bcol);
                bfh[2 * np][0] = t4[0]; bfh[2 * np][1] = t4[1];
                bfh[2 * np + 1][0] = t4[2]; bfh[2 * np + 1][1] = t4[3];
                lma4(t4, sb + SM_QL + ro + bcol);
                bfl[2 * np][0] = t4[0]; bfl[2 * np][1] = t4[1];
                bfl[2 * np + 1][0] = t4[2]; bfl[2 * np + 1][1] = t4[3];
            }
#pragma unroll
            for (int mt = 0; mt < 4; mt++)
#pragma unroll
                for (int nt = 0; nt < 4; nt++) {
                    mma16816h(oacc[mt][nt], af[mt], bfh[nt]);
                    mma16816h(oacc[mt][nt], af[mt], bfl[nt]);
                }
        }
        __syncthreads();                 // Q/P free for next iteration

        // prefetch Q(jt+1)
        if (jt + 1 < 16) {
            load_plane(sb, SM_QH, Qhp + (size_t)(jt + 1) * 128, PP, tid);
            load_plane(sb, SM_QL, Qlp + (size_t)(jt + 1) * 128, PP, tid);
            CP_COMMIT();
        }
    }

    // ---- normalize and transpose O[i][c] -> out[c][i] via SMEM ----
    float* fbuf = (float*)(smem + TILEB);          // 128 x 132 floats in V planes
#pragma unroll
    for (int mt = 0; mt < 4; mt++) {
#pragma unroll
        for (int half_ = 0; half_ < 2; half_++) {
            int r = wm * 64 + mt * 16 + tg + half_ * 8;
            float inv = 1.0f / lrow[mt][half_];
#pragma unroll
            for (int nt = 0; nt < 4; nt++) {
                int c = wn * 32 + nt * 8 + 2 * tp;
                fbuf[(size_t)c * 132 + r]       = oacc[mt][nt][2 * half_] * inv;
                fbuf[(size_t)(c + 1) * 132 + r] = oacc[mt][nt][2 * half_ + 1] * inv;
            }
        }
    }
    __syncthreads();
    const size_t obase = ((size_t)b * COUT + h * DH) * PP + (size_t)it * 128;
#pragma unroll
    for (int rr = 0; rr < 16; rr++) {
        int r = w * 16 + rr;
        float4 v = *(float4*)&fbuf[(size_t)r * 132 + L * 4];
        *(float4*)&out[obase + (size_t)r * PP + L * 4] = v;
    }
}

// ---------------- conversions ------------------------------------------------
__device__ __forceinline__ void split1(float v, bf16& h, bf16& l) {
    h = __float2bfloat16(v);
    l = __float2bfloat16(v - __bfloat162float(h));
}
__device__ __forceinline__ void split1h(float v, half& h, half& l) {
    h = __float2half_rn(v);
    l = __float2half_rn(v - __half2float(h));
}

__global__ __launch_bounds__(256) void convert_w(const float* __restrict__ Wq,
                                                 const float* __restrict__ Wk,
                                                 const float* __restrict__ Wv) {
    int proj = blockIdx.z;
    const float* W = (proj == 0) ? Wq : ((proj == 1) ? Wk : Wv);
    size_t e = ((size_t)blockIdx.x * 256 + threadIdx.x) * 4;
    float4 v = *(const float4*)(W + e);
    bf16 h0, h1, h2, h3, l0, l1, l2, l3;
    split1(v.x, h0, l0); split1(v.y, h1, l1); split1(v.z, h2, l2); split1(v.w, h3, l3);
    ((__nv_bfloat162*)&g_Whi[proj][e])[0] = __halves2bfloat162(h0, h1);
    ((__nv_bfloat162*)&g_Whi[proj][e])[1] = __halves2bfloat162(h2, h3);
    ((__nv_bfloat162*)&g_Wlo[proj][e])[0] = __halves2bfloat162(l0, l1);
    ((__nv_bfloat162*)&g_Wlo[proj][e])[1] = __halves2bfloat162(l2, l3);
}

__global__ __launch_bounds__(256) void transpose_x(const float* __restrict__ x) {
    __shared__ float t[32][33];
    int b = blockIdx.z;
    int p0 = blockIdx.x * 32, c0 = blockIdx.y * 32;
    int tx = threadIdx.x & 31, ty = threadIdx.x >> 5;
#pragma unroll
    for (int j = 0; j < 4; j++)
        t[ty + 8 * j][tx] = x[((size_t)b * CIN + c0 + ty + 8 * j) * PP + p0 + tx];
    __syncthreads();
#pragma unroll
    for (int j = 0; j < 4; j++) {
        float v = t[tx][ty + 8 * j];
        bf16 h, l; split1(v, h, l);
        size_t o = ((size_t)b * PP + p0 + ty + 8 * j) * CIN + c0 + tx;
        g_xThi[o] = h; g_xTlo[o] = l;
    }
}

// ---------------- BN stats ---------------------------------------------------
__global__ __launch_bounds__(256) void stats_kernel(const float* __restrict__ gq,
                                                    const float* __restrict__ bq,
                                                    const float* __restrict__ gk,
                                                    const float* __restrict__ bk,
                                                    const float* __restrict__ gv,
                                                    const float* __restrict__ bv) {
    int ch = blockIdx.x & (COUT - 1);
    int proj = blockIdx.x >> 10;
    const float* base = g_Y + ((size_t)proj * NB) * COUT * PP + (size_t)ch * PP;
    float s = 0.0f, sq = 0.0f;
    for (int b = 0; b < NB; b++) {
        const float* p = base + (size_t)b * COUT * PP;
        for (int i = threadIdx.x; i < PP; i += 256) {
            float v = p[i]; s += v; sq += v * v;
        }
    }
#pragma unroll
    for (int o = 16; o; o >>= 1) {
        s  += __shfl_xor_sync(0xffffffffu, s, o);
        sq += __shfl_xor_sync(0xffffffffu, sq, o);
    }
    __shared__ float rs[8], rq[8];
    if ((threadIdx.x & 31) == 0) { rs[threadIdx.x >> 5] = s; rq[threadIdx.x >> 5] = sq; }
    __syncthreads();
    if (threadIdx.x == 0) {
        float S = 0.0f, Q = 0.0f;
#pragma unroll
        for (int w = 0; w < 8; w++) { S += rs[w]; Q += rq[w]; }
        const float inv_n = 1.0f / (float)(NB * PP);
        float mean = S * inv_n;
        float var  = Q * inv_n - mean * mean;
        const float* g  = (proj == 0) ? gq : ((proj == 1) ? gk : gv);
        const float* bb = (proj == 0) ? bq : ((proj == 1) ? bk : bv);
        float sc = g[ch] * rsqrtf(var + 1e-5f);
        g_scale[proj][ch] = sc;
        g_shift[proj][ch] = bb[ch] - mean * sc;
    }
}

// ---------------- BN apply: Q path (keep [c][p] layout, fp16 hi/lo) ----------
__global__ __launch_bounds__(256) void bn_apply_q(void) {
    size_t e = ((size_t)blockIdx.x * 256 + threadIdx.x) * 4;
    int ch = (int)((e >> 11) & (COUT - 1));
    float sc = g_scale[0][ch], sh = g_shift[0][ch];
    float4 y = *(float4*)&g_Y[e];
    y.x = sc * y.x + sh; y.x = (y.x < 0.0f) ? 0.1f * y.x : y.x;
    y.y = sc * y.y + sh; y.y = (y.y < 0.0f) ? 0.1f * y.y : y.y;
    y.z = sc * y.z + sh; y.z = (y.z < 0.0f) ? 0.1f * y.z : y.z;
    y.w = sc * y.w + sh; y.w = (y.w < 0.0f) ? 0.1f * y.w : y.w;
    half h0, h1, h2, h3, l0, l1, l2, l3;
    split1h(y.x, h0, l0); split1h(y.y, h1, l1);
    split1h(y.z, h2, l2); split1h(y.w, h3, l3);
    ((half2*)&g_Qhi[e])[0] = __halves2half2(h0, h1);
    ((half2*)&g_Qhi[e])[1] = __halves2half2(h2, h3);
    ((half2*)&g_Qlo[e])[0] = __halves2half2(l0, l1);
    ((half2*)&g_Qlo[e])[1] = __halves2half2(l2, l3);
}

// ---------------- BN apply + transpose: K/V ([c][p] -> [p][c], fp16 single) --
__global__ __launch_bounds__(256) void bn_apply_t(void) {
    __shared__ float t[32][33];
    int z = blockIdx.z;
    int proj = 1 + (z >> 3), b = z & 7;
    int p0 = blockIdx.x * 32, c0 = blockIdx.y * 32;
    int tx = threadIdx.x & 31, ty = threadIdx.x >> 5;
#pragma unroll
    for (int j = 0; j < 4; j++) {
        int c = c0 + ty + 8 * j;
        float sc = g_scale[proj][c], sh = g_shift[proj][c];
        float v = g_Y[(((size_t)proj * NB + b) * COUT + c) * PP + p0 + tx];
        v = sc * v + sh;
        v = (v < 0.0f) ? 0.1f * v : v;
        t[ty + 8 * j][tx] = v;
    }
    __syncthreads();
    half* T = (proj == 1) ? g_KT : g_VT;
#pragma unroll
    for (int j = 0; j < 4; j++) {
        float v = t[tx][ty + 8 * j];
        size_t o = ((size_t)b * PP + p0 + ty + 8 * j) * COUT + c0 + tx;
        T[o] = __float2half_rn(v);
    }
}

// ---------------- launch -----------------------------------------------------
extern "C" void kernel_launch(void* const* d_in, const int* in_sizes, int n_in,
                              void* d_out, int out_size)
{
    (void)in_sizes; (void)n_in; (void)out_size;
    const float* x  = (const float*)d_in[0];
    const float* Wq = (const float*)d_in[1];
    const float* gq = (const float*)d_in[2];
    const float* bq = (const float*)d_in[3];
    const float* Wk = (const float*)d_in[4];
    const float* gk = (const float*)d_in[5];
    const float* bk = (const float*)d_in[6];
    const float* Wv = (const float*)d_in[7];
    const float* gv = (const float*)d_in[8];
    const float* bv = (const float*)d_in[9];
    float* out = (float*)d_out;

    cudaFuncSetAttribute(proj_gemm,  cudaFuncAttributeMaxDynamicSharedMemorySize, SMEM_BYTES);
    cudaFuncSetAttribute(attn_fused, cudaFuncAttributeMaxDynamicSharedMemorySize, SMEM_ATTN);

    // 1) input conversions
    convert_w<<<dim3(COUT * CIN / 4 / 256, 1, 3), 256>>>(Wq, Wk, Wv);
    transpose_x<<<dim3(PP / 32, CIN / 32, NB), 256>>>(x);
    // 2) Y = W x (bf16 3-term)
    proj_gemm<<<dim3(PP / 128, COUT / 128, 24), 256, SMEM_BYTES>>>();
    // 3) BN stats
    stats_kernel<<<3 * COUT, 256>>>(gq, bq, gk, bk, gv, bv);
    // 4) BN + LeakyReLU, emit Q fp16 hi/lo and K^T/V^T fp16
    bn_apply_q<<<(unsigned)((size_t)NB * COUT * PP / 4 / 256), 256>>>();
    bn_apply_t<<<dim3(PP / 32, COUT / 32, 16), 256>>>();
    // 5) fused S -> softmax -> O (fp16)
    attn_fused<<<dim3(16, 64), 256, SMEM_ATTN>>>(out);
}

// round 6
// speedup vs baseline: 1.4346x; 1.4346x over previous
#include <cuda_runtime.h>
#include <cuda_bf16.h>
#include <cstdint>

#define NB   8
#define CIN  512
#define COUT 1024
#define PP   2048
#define NH   8
#define DH   128

typedef __nv_bfloat16 bf16;

// ---------------- device scratch (static: no allocation allowed) -------------
__device__ float g_Y[(size_t)3 * NB * COUT * PP];                    // 192 MB
__device__ float g_scale[3][COUT];
__device__ float g_shift[3][COUT];
__device__ bf16  g_Whi[3][COUT * CIN], g_Wlo[3][COUT * CIN];
__device__ bf16  g_xThi[(size_t)NB * PP * CIN], g_xTlo[(size_t)NB * PP * CIN];
__device__ bf16  g_Qhi[(size_t)NB * COUT * PP], g_Qlo[(size_t)NB * COUT * PP];
__device__ bf16  g_KT[(size_t)NB * PP * COUT];        // single plane
__device__ bf16  g_VT[(size_t)NB * PP * COUT];        // single plane

// ---------------- PTX helpers (baseline PTX only) ----------------------------
__device__ __forceinline__ uint32_t smem_u32(const void* p) {
    uint32_t a;
    asm("{ .reg .u64 t; cvta.to.shared.u64 t, %1; cvt.u32.u64 %0, t; }" : "=r"(a) : "l"(p));
    return a;
}
__device__ __forceinline__ void cp16(uint32_t saddr, const void* g) {
    asm volatile("cp.async.cg.shared.global [%0], [%1], 16;" :: "r"(saddr), "l"(g));
}
#define CP_COMMIT() asm volatile("cp.async.commit_group;" ::: "memory")
template <int N>
__device__ __forceinline__ void cp_wait() {
    asm volatile("cp.async.wait_group %0;" :: "n"(N) : "memory");
}
__device__ __forceinline__ void lma4(uint32_t* r, uint32_t addr) {
    asm volatile("ldmatrix.sync.aligned.m8n8.x4.shared.b16 {%0,%1,%2,%3}, [%4];"
                 : "=r"(r[0]), "=r"(r[1]), "=r"(r[2]), "=r"(r[3]) : "r"(addr));
}
__device__ __forceinline__ void mma16816(float* d, const uint32_t* a, const uint32_t* b) {
    asm volatile("mma.sync.aligned.m16n8k16.row.col.f32.bf16.bf16.f32 "
                 "{%0,%1,%2,%3}, {%4,%5,%6,%7}, {%8,%9}, {%0,%1,%2,%3};"
                 : "+f"(d[0]), "+f"(d[1]), "+f"(d[2]), "+f"(d[3])
                 : "r"(a[0]), "r"(a[1]), "r"(a[2]), "r"(a[3]), "r"(b[0]), "r"(b[1]));
}

// =============================================================================
// Projection GEMM (bf16 3-term, unchanged): 128x128 tile, K-chunks of 32
// =============================================================================
#define ROWB   80
#define MATB   (128 * ROWB)
#define STAGEB (4 * MATB)
#define OFF_AH 0
#define OFF_AL MATB
#define OFF_BH (2 * MATB)
#define OFF_BL (3 * MATB)
#define SMEM_BYTES (2 * STAGEB)

__device__ __forceinline__ void gemm_core(const bf16* __restrict__ Ah,
                                          const bf16* __restrict__ Al,
                                          const bf16* __restrict__ Bh,
                                          const bf16* __restrict__ Bl,
                                          size_t lda, size_t ldb, int K,
                                          float* __restrict__ C, size_t ldc,
                                          float alpha, int m0, int n0)
{
    extern __shared__ __align__(128) char smem[];
    const uint32_t sb = smem_u32(smem);
    const int tid = threadIdx.x;
    const int L = tid & 31;
    const int w = tid >> 5;
    const int wm = w >> 2, wn = w & 3;

    const int ck0 = tid * 2, ck1 = tid * 2 + 1;
    const int lr0 = ck0 >> 2, lc0 = ck0 & 3;
    const int lr1 = ck1 >> 2, lc1 = ck1 & 3;

    const bf16* pAh0 = Ah + (size_t)(m0 + lr0) * lda + lc0 * 8;
    const bf16* pAh1 = Ah + (size_t)(m0 + lr1) * lda + lc1 * 8;
    const bf16* pAl0 = Al + (size_t)(m0 + lr0) * lda + lc0 * 8;
    const bf16* pAl1 = Al + (size_t)(m0 + lr1) * lda + lc1 * 8;
    const bf16* pBh0 = Bh + (size_t)(n0 + lr0) * ldb + lc0 * 8;
    const bf16* pBh1 = Bh + (size_t)(n0 + lr1) * ldb + lc1 * 8;
    const bf16* pBl0 = Bl + (size_t)(n0 + lr0) * ldb + lc0 * 8;
    const bf16* pBl1 = Bl + (size_t)(n0 + lr1) * ldb + lc1 * 8;
    const uint32_t so0 = lr0 * ROWB + lc0 * 16;
    const uint32_t so1 = lr1 * ROWB + lc1 * 16;

    float acc[4][4][4];
#pragma unroll
    for (int mt = 0; mt < 4; mt++)
#pragma unroll
        for (int nt = 0; nt < 4; nt++)
#pragma unroll
            for (int i = 0; i < 4; i++) acc[mt][nt][i] = 0.0f;

    const int nch = K >> 5;
    {
        uint32_t base = sb;
        cp16(base + OFF_AH + so0, pAh0); cp16(base + OFF_AH + so1, pAh1);
        cp16(base + OFF_AL + so0, pAl0); cp16(base + OFF_AL + so1, pAl1);
        cp16(base + OFF_BH + so0, pBh0); cp16(base + OFF_BH + so1, pBh1);
        cp16(base + OFF_BL + so0, pBl0); cp16(base + OFF_BL + so1, pBl1);
        CP_COMMIT();
    }

    const uint32_t a_row = (uint32_t)(wm * 64 + ((L >> 3) & 1) * 8 + (L & 7));
    const uint32_t a_cc  = (uint32_t)(L >> 4);
    const uint32_t b_row = (uint32_t)(wn * 32 + ((L >> 4) << 3) + (L & 7));
    const uint32_t b_cc  = (uint32_t)((L >> 3) & 1);

    for (int ch = 0; ch < nch; ch++) {
        if (ch + 1 < nch) {
            uint32_t base = sb + ((ch + 1) & 1) * STAGEB;
            int kc = (ch + 1) * 32;
            cp16(base + OFF_AH + so0, pAh0 + kc); cp16(base + OFF_AH + so1, pAh1 + kc);
            cp16(base + OFF_AL + so0, pAl0 + kc); cp16(base + OFF_AL + so1, pAl1 + kc);
            cp16(base + OFF_BH + so0, pBh0 + kc); cp16(base + OFF_BH + so1, pBh1 + kc);
            cp16(base + OFF_BL + so0, pBl0 + kc); cp16(base + OFF_BL + so1, pBl1 + kc);
            CP_COMMIT();
            cp_wait<1>();
        } else {
            cp_wait<0>();
        }
        __syncthreads();

        uint32_t base = sb + (ch & 1) * STAGEB;
#pragma unroll
        for (int ks = 0; ks < 2; ks++) {
            uint32_t afh[4][4], afl[4][4], bfh[4][2], bfl[4][2];
            uint32_t acol = (a_cc + ks * 2) * 16;
            uint32_t bcol = (b_cc + ks * 2) * 16;
#pragma unroll
            for (int mt = 0; mt < 4; mt++) {
                uint32_t ro = (a_row + mt * 16) * ROWB;
                lma4(afh[mt], base + OFF_AH + ro + acol);
                lma4(afl[mt], base + OFF_AL + ro + acol);
            }
#pragma unroll
            for (int np = 0; np < 2; np++) {
                uint32_t ro = (b_row + np * 16) * ROWB;
                uint32_t t4[4];
                lma4(t4, base + OFF_BH + ro + bcol);
                bfh[2 * np][0] = t4[0]; bfh[2 * np][1] = t4[1];
                bfh[2 * np + 1][0] = t4[2]; bfh[2 * np + 1][1] = t4[3];
                lma4(t4, base + OFF_BL + ro + bcol);
                bfl[2 * np][0] = t4[0]; bfl[2 * np][1] = t4[1];
                bfl[2 * np + 1][0] = t4[2]; bfl[2 * np + 1][1] = t4[3];
            }
#pragma unroll
            for (int mt = 0; mt < 4; mt++)
#pragma unroll
                for (int nt = 0; nt < 4; nt++) {
                    mma16816(acc[mt][nt], afh[mt], bfh[nt]);
                    mma16816(acc[mt][nt], afh[mt], bfl[nt]);
                    mma16816(acc[mt][nt], afl[mt], bfh[nt]);
                }
        }
        __syncthreads();
    }

    const int tg = L >> 2, tp = L & 3;
#pragma unroll
    for (int mt = 0; mt < 4; mt++) {
        int r0 = m0 + wm * 64 + mt * 16 + tg;
#pragma unroll
        for (int nt = 0; nt < 4; nt++) {
            int c = n0 + wn * 32 + nt * 8 + tp * 2;
            float2 v0 = make_float2(alpha * acc[mt][nt][0], alpha * acc[mt][nt][1]);
            float2 v1 = make_float2(alpha * acc[mt][nt][2], alpha * acc[mt][nt][3]);
            *(float2*)&C[(size_t)r0 * ldc + c]       = v0;
            *(float2*)&C[(size_t)(r0 + 8) * ldc + c] = v1;
        }
    }
}

__global__ __launch_bounds__(256) void proj_gemm(void) {
    int z = blockIdx.z, proj = z >> 3, b = z & 7;
    gemm_core(g_Whi[proj], g_Wlo[proj],
              g_xThi + (size_t)b * PP * CIN, g_xTlo + (size_t)b * PP * CIN,
              CIN, CIN, CIN,
              g_Y + (size_t)z * COUT * PP, PP, 1.0f,
              blockIdx.y * 128, blockIdx.x * 128);
}

// =============================================================================
// Fused flash attention (R4 structure; single-plane K/V/P, Q hi/lo)
// One CTA per (b, h, i-tile of 128). 8 warps (wm 2 x wn 4).
// =============================================================================
#define APITCH 272                       // 128 bf16 (256B) + 16B pad
#define TILEB  (128 * APITCH)            // 34816 per plane
#define SM_K   0                         // K: 1 plane
#define SM_VQ  TILEB                     // V (plane 0) then Q hi/lo (planes 0,1)
#define SM_P   (3 * TILEB)               // P: 1 plane
#define SM_RM  (4 * TILEB)               // row-max partials: 4 x 128 floats
#define SM_RS  (SM_RM + 2048)            // row-sum partials: 4 x 128 floats
#define SMEM_ATTN (SM_RS + 2048)         // 143360

__device__ __forceinline__ void load_plane(uint32_t sb, uint32_t off,
                                           const bf16* __restrict__ src,
                                           size_t stride, int tid) {
#pragma unroll
    for (int i = 0; i < 8; i++) {
        int idx = tid + i * 256;
        int r = idx >> 4, cc = idx & 15;
        cp16(sb + off + r * APITCH + cc * 16, src + (size_t)r * stride + cc * 8);
    }
}

__global__ __launch_bounds__(256, 1) void attn_fused(float* __restrict__ out) {
    extern __shared__ __align__(128) char smem[];
    const uint32_t sb = smem_u32(smem);
    const int tid = threadIdx.x;
    const int L = tid & 31, w = tid >> 5;
    const int wm = w >> 2, wn = w & 3;
    const int tg = L >> 2, tp = L & 3;
    const int it = blockIdx.x;
    const int z = blockIdx.y, b = z >> 3, h = z & 7;

    const bf16* Kp  = g_KT + ((size_t)b * PP + it * 128) * COUT + h * DH;
    const bf16* Vp  = g_VT + (size_t)b * PP * COUT + h * DH;
    const bf16* Qhp = g_Qhi + ((size_t)b * COUT + h * DH) * PP;
    const bf16* Qlp = g_Qlo + ((size_t)b * COUT + h * DH) * PP;

    // K tile resident in SMEM for the whole kernel
    load_plane(sb, SM_K, Kp, COUT, tid);
    CP_COMMIT(); cp_wait<0>(); __syncthreads();

    const uint32_t a_row = (uint32_t)(wm * 64 + ((L >> 3) & 1) * 8 + (L & 7));
    const uint32_t a_cc  = (uint32_t)(L >> 4);
    const uint32_t b_row = (uint32_t)(wn * 32 + ((L >> 4) << 3) + (L & 7));
    const uint32_t b_cc  = (uint32_t)((L >> 3) & 1);

    const float cS = 1.4426950408889634f * 0.08838834764831845f;  // log2e / sqrt(128)

    float oacc[4][4][4];
    float mrow[4][2], lrow[4][2];
#pragma unroll
    for (int mt = 0; mt < 4; mt++) {
        mrow[mt][0] = mrow[mt][1] = -1e30f;
        lrow[mt][0] = lrow[mt][1] = 0.0f;
#pragma unroll
        for (int nt = 0; nt < 4; nt++)
#pragma unroll
            for (int i = 0; i < 4; i++) oacc[mt][nt][i] = 0.0f;
    }

    for (int jt = 0; jt < 16; jt++) {
        // ---- load V_J (single plane) ----
        load_plane(sb, SM_VQ, Vp + (size_t)jt * 128 * COUT, COUT, tid);
        CP_COMMIT(); cp_wait<0>(); __syncthreads();

        // ---- S = K_I^T V_J (bf16 1-term, k = 128) ----
        float sacc[4][4][4];
#pragma unroll
        for (int mt = 0; mt < 4; mt++)
#pragma unroll
            for (int nt = 0; nt < 4; nt++)
#pragma unroll
                for (int i = 0; i < 4; i++) sacc[mt][nt][i] = 0.0f;

#pragma unroll
        for (int ks = 0; ks < 8; ks++) {
            uint32_t af[4][4], bf[4][2];
            uint32_t acol = (a_cc + ks * 2) * 16;
            uint32_t bcol = (b_cc + ks * 2) * 16;
#pragma unroll
            for (int mt = 0; mt < 4; mt++)
                lma4(af[mt], sb + SM_K + (a_row + mt * 16) * APITCH + acol);
#pragma unroll
            for (int np = 0; np < 2; np++) {
                uint32_t t4[4];
                lma4(t4, sb + SM_VQ + (b_row + np * 16) * APITCH + bcol);
                bf[2 * np][0] = t4[0]; bf[2 * np][1] = t4[1];
                bf[2 * np + 1][0] = t4[2]; bf[2 * np + 1][1] = t4[3];
            }
#pragma unroll
            for (int mt = 0; mt < 4; mt++)
#pragma unroll
                for (int nt = 0; nt < 4; nt++)
                    mma16816(sacc[mt][nt], af[mt], bf[nt]);
        }

        // scale into log2 domain, warp-level row maxes
        float wmax[4][2];
#pragma unroll
        for (int mt = 0; mt < 4; mt++) {
#pragma unroll
            for (int half = 0; half < 2; half++) {
                float mv = -1e30f;
#pragma unroll
                for (int nt = 0; nt < 4; nt++) {
                    sacc[mt][nt][2 * half]     *= cS;
                    sacc[mt][nt][2 * half + 1] *= cS;
                    mv = fmaxf(mv, fmaxf(sacc[mt][nt][2 * half], sacc[mt][nt][2 * half + 1]));
                }
                mv = fmaxf(mv, __shfl_xor_sync(0xffffffffu, mv, 1));
                mv = fmaxf(mv, __shfl_xor_sync(0xffffffffu, mv, 2));
                wmax[mt][half] = mv;
            }
        }
        if (tp == 0) {
#pragma unroll
            for (int mt = 0; mt < 4; mt++) {
                int r = wm * 64 + mt * 16 + tg;
                *(float*)(smem + SM_RM + (wn * 128 + r) * 4)     = wmax[mt][0];
                *(float*)(smem + SM_RM + (wn * 128 + r + 8) * 4) = wmax[mt][1];
            }
        }
        __syncthreads();                 // V reads done + partial maxes visible

        // prefetch Q_J hi/lo into the V buffer (overlaps softmax math)
        load_plane(sb, SM_VQ,         Qhp + (size_t)jt * 128, PP, tid);
        load_plane(sb, SM_VQ + TILEB, Qlp + (size_t)jt * 128, PP, tid);
        CP_COMMIT();

        // block row max, online update, exp, P write (single bf16), sums
        float wsum[4][2];
#pragma unroll
        for (int mt = 0; mt < 4; mt++) {
#pragma unroll
            for (int half = 0; half < 2; half++) {
                int r = wm * 64 + mt * 16 + tg + half * 8;
                float bm = *(float*)(smem + SM_RM + r * 4);
                bm = fmaxf(bm, *(float*)(smem + SM_RM + (128 + r) * 4));
                bm = fmaxf(bm, *(float*)(smem + SM_RM + (256 + r) * 4));
                bm = fmaxf(bm, *(float*)(smem + SM_RM + (384 + r) * 4));
                float mn = fmaxf(mrow[mt][half], bm);
                float sc = exp2f(mrow[mt][half] - mn);
                mrow[mt][half] = mn;
                lrow[mt][half] *= sc;
                float rs = 0.0f;
#pragma unroll
                for (int nt = 0; nt < 4; nt++) {
                    oacc[mt][nt][2 * half]     *= sc;
                    oacc[mt][nt][2 * half + 1] *= sc;
                    float p0 = exp2f(sacc[mt][nt][2 * half]     - mn);
                    float p1 = exp2f(sacc[mt][nt][2 * half + 1] - mn);
                    rs += p0 + p1;
                    uint32_t col = wn * 32 + nt * 8 + 2 * tp;
                    *(__nv_bfloat162*)(smem + SM_P + r * APITCH + col * 2) =
                        __halves2bfloat162(__float2bfloat16(p0), __float2bfloat16(p1));
                }
                rs += __shfl_xor_sync(0xffffffffu, rs, 1);
                rs += __shfl_xor_sync(0xffffffffu, rs, 2);
                wsum[mt][half] = rs;
            }
        }
        if (tp == 0) {
#pragma unroll
            for (int mt = 0; mt < 4; mt++) {
                int r = wm * 64 + mt * 16 + tg;
                *(float*)(smem + SM_RS + (wn * 128 + r) * 4)     = wsum[mt][0];
                *(float*)(smem + SM_RS + (wn * 128 + r + 8) * 4) = wsum[mt][1];
            }
        }
        cp_wait<0>();
        __syncthreads();                 // P + partial sums visible, Q loaded

#pragma unroll
        for (int mt = 0; mt < 4; mt++) {
#pragma unroll
            for (int half = 0; half < 2; half++) {
                int r = wm * 64 + mt * 16 + tg + half * 8;
                float bs = *(float*)(smem + SM_RS + r * 4)
                         + *(float*)(smem + SM_RS + (128 + r) * 4)
                         + *(float*)(smem + SM_RS + (256 + r) * 4)
                         + *(float*)(smem + SM_RS + (384 + r) * 4);
                lrow[mt][half] += bs;
            }
        }

        // ---- O += P (Qh + Ql)  (bf16 2-term, k = 128) ----
#pragma unroll
        for (int ks = 0; ks < 8; ks++) {
            uint32_t af[4][4], bfh[4][2], bfl[4][2];
            uint32_t acol = (a_cc + ks * 2) * 16;
            uint32_t bcol = (b_cc + ks * 2) * 16;
#pragma unroll
            for (int mt = 0; mt < 4; mt++)
                lma4(af[mt], sb + SM_P + (a_row + mt * 16) * APITCH + acol);
#pragma unroll
            for (int np = 0; np < 2; np++) {
                uint32_t ro = (b_row + np * 16) * APITCH;
                uint32_t t4[4];
                lma4(t4, sb + SM_VQ + ro + bcol);
                bfh[2 * np][0] = t4[0]; bfh[2 * np][1] = t4[1];
                bfh[2 * np + 1][0] = t4[2]; bfh[2 * np + 1][1] = t4[3];
                lma4(t4, sb + SM_VQ + TILEB + ro + bcol);
                bfl[2 * np][0] = t4[0]; bfl[2 * np][1] = t4[1];
                bfl[2 * np + 1][0] = t4[2]; bfl[2 * np + 1][1] = t4[3];
            }
#pragma unroll
            for (int mt = 0; mt < 4; mt++)
#pragma unroll
                for (int nt = 0; nt < 4; nt++) {
                    mma16816(oacc[mt][nt], af[mt], bfh[nt]);
                    mma16816(oacc[mt][nt], af[mt], bfl[nt]);
                }
        }
        __syncthreads();                 // Q/P buffers free for next iteration
    }

    // ---- normalize by 1/l and transpose O[i][c] -> out[c][i] via SMEM ----
    float* fbuf = (float*)smem;          // 128 x 132 floats (K + V planes)
#pragma unroll
    for (int mt = 0; mt < 4; mt++) {
#pragma unroll
        for (int half = 0; half < 2; half++) {
            int r = wm * 64 + mt * 16 + tg + half * 8;
            float inv = 1.0f / lrow[mt][half];
#pragma unroll
            for (int nt = 0; nt < 4; nt++) {
                int c = wn * 32 + nt * 8 + 2 * tp;
                fbuf[(size_t)c * 132 + r]       = oacc[mt][nt][2 * half] * inv;
                fbuf[(size_t)(c + 1) * 132 + r] = oacc[mt][nt][2 * half + 1] * inv;
            }
        }
    }
    __syncthreads();
    const size_t obase = ((size_t)b * COUT + h * DH) * PP + (size_t)it * 128;
#pragma unroll
    for (int rr = 0; rr < 16; rr++) {
        int r = w * 16 + rr;
        float4 v = *(float4*)&fbuf[(size_t)r * 132 + L * 4];
        *(float4*)&out[obase + (size_t)r * PP + L * 4] = v;
    }
}

// ---------------- conversions ------------------------------------------------
__device__ __forceinline__ void split1(float v, bf16& h, bf16& l) {
    h = __float2bfloat16(v);
    l = __float2bfloat16(v - __bfloat162float(h));
}
__device__ __forceinline__ void split4_store(float4 v, bf16* hi, bf16* lo) {
    bf16 h0, h1, h2, h3, l0, l1, l2, l3;
    split1(v.x, h0, l0); split1(v.y, h1, l1); split1(v.z, h2, l2); split1(v.w, h3, l3);
    ((__nv_bfloat162*)hi)[0] = __halves2bfloat162(h0, h1);
    ((__nv_bfloat162*)hi)[1] = __halves2bfloat162(h2, h3);
    ((__nv_bfloat162*)lo)[0] = __halves2bfloat162(l0, l1);
    ((__nv_bfloat162*)lo)[1] = __halves2bfloat162(l2, l3);
}

__global__ __launch_bounds__(256) void convert_w(const float* __restrict__ Wq,
                                                 const float* __restrict__ Wk,
                                                 const float* __restrict__ Wv) {
    int proj = blockIdx.z;
    const float* W = (proj == 0) ? Wq : ((proj == 1) ? Wk : Wv);
    size_t e = ((size_t)blockIdx.x * 256 + threadIdx.x) * 4;
    float4 v = *(const float4*)(W + e);
    split4_store(v, &g_Whi[proj][e], &g_Wlo[proj][e]);
}

__global__ __launch_bounds__(256) void transpose_x(const float* __restrict__ x) {
    __shared__ float t[32][33];
    int b = blockIdx.z;
    int p0 = blockIdx.x * 32, c0 = blockIdx.y * 32;
    int tx = threadIdx.x & 31, ty = threadIdx.x >> 5;
#pragma unroll
    for (int j = 0; j < 4; j++)
        t[ty + 8 * j][tx] = x[((size_t)b * CIN + c0 + ty + 8 * j) * PP + p0 + tx];
    __syncthreads();
#pragma unroll
    for (int j = 0; j < 4; j++) {
        float v = t[tx][ty + 8 * j];
        bf16 h, l; split1(v, h, l);
        size_t o = ((size_t)b * PP + p0 + ty + 8 * j) * CIN + c0 + tx;
        g_xThi[o] = h; g_xTlo[o] = l;
    }
}

// ---------------- BN stats ---------------------------------------------------
__global__ __launch_bounds__(256) void stats_kernel(const float* __restrict__ gq,
                                                    const float* __restrict__ bq,
                                                    const float* __restrict__ gk,
                                                    const float* __restrict__ bk,
                                                    const float* __restrict__ gv,
                                                    const float* __restrict__ bv) {
    int ch = blockIdx.x & (COUT - 1);
    int proj = blockIdx.x >> 10;
    const float* base = g_Y + ((size_t)proj * NB) * COUT * PP + (size_t)ch * PP;
    float s = 0.0f, sq = 0.0f;
    for (int b = 0; b < NB; b++) {
        const float* p = base + (size_t)b * COUT * PP;
        for (int i = threadIdx.x; i < PP; i += 256) {
            float v = p[i]; s += v; sq += v * v;
        }
    }
#pragma unroll
    for (int o = 16; o; o >>= 1) {
        s  += __shfl_xor_sync(0xffffffffu, s, o);
        sq += __shfl_xor_sync(0xffffffffu, sq, o);
    }
    __shared__ float rs[8], rq[8];
    if ((threadIdx.x & 31) == 0) { rs[threadIdx.x >> 5] = s; rq[threadIdx.x >> 5] = sq; }
    __syncthreads();
    if (threadIdx.x == 0) {
        float S = 0.0f, Q = 0.0f;
#pragma unroll
        for (int w = 0; w < 8; w++) { S += rs[w]; Q += rq[w]; }
        const float inv_n = 1.0f / (float)(NB * PP);
        float mean = S * inv_n;
        float var  = Q * inv_n - mean * mean;
        const float* g  = (proj == 0) ? gq : ((proj == 1) ? gk : gv);
        const float* bb = (proj == 0) ? bq : ((proj == 1) ? bk : bv);
        float sc = g[ch] * rsqrtf(var + 1e-5f);
        g_scale[proj][ch] = sc;
        g_shift[proj][ch] = bb[ch] - mean * sc;
    }
}

// ---------------- BN apply: Q path (keep [c][p] layout, bf16 hi/lo) ----------
__global__ __launch_bounds__(256) void bn_apply_q(void) {
    size_t e = ((size_t)blockIdx.x * 256 + threadIdx.x) * 4;
    int ch = (int)((e >> 11) & (COUT - 1));
    float sc = g_scale[0][ch], sh = g_shift[0][ch];
    float4 y = *(float4*)&g_Y[e];
    y.x = sc * y.x + sh; y.x = (y.x < 0.0f) ? 0.1f * y.x : y.x;
    y.y = sc * y.y + sh; y.y = (y.y < 0.0f) ? 0.1f * y.y : y.y;
    y.z = sc * y.z + sh; y.z = (y.z < 0.0f) ? 0.1f * y.z : y.z;
    y.w = sc * y.w + sh; y.w = (y.w < 0.0f) ? 0.1f * y.w : y.w;
    split4_store(y, &g_Qhi[e], &g_Qlo[e]);
}

// ---------------- BN apply + transpose: K/V ([c][p] -> [p][c], bf16 single) --
__global__ __launch_bounds__(256) void bn_apply_t(void) {
    __shared__ float t[32][33];
    int z = blockIdx.z;
    int proj = 1 + (z >> 3), b = z & 7;
    int p0 = blockIdx.x * 32, c0 = blockIdx.y * 32;
    int tx = threadIdx.x & 31, ty = threadIdx.x >> 5;
#pragma unroll
    for (int j = 0; j < 4; j++) {
        int c = c0 + ty + 8 * j;
        float sc = g_scale[proj][c], sh = g_shift[proj][c];
        float v = g_Y[(((size_t)proj * NB + b) * COUT + c) * PP + p0 + tx];
        v = sc * v + sh;
        v = (v < 0.0f) ? 0.1f * v : v;
        t[ty + 8 * j][tx] = v;
    }
    __syncthreads();
    bf16* T = (proj == 1) ? g_KT : g_VT;
#pragma unroll
    for (int j = 0; j < 4; j++) {
        float v = t[tx][ty + 8 * j];
        size_t o = ((size_t)b * PP + p0 + ty + 8 * j) * COUT + c0 + tx;
        T[o] = __float2bfloat16(v);
    }
}

// ---------------- launch -----------------------------------------------------
extern "C" void kernel_launch(void* const* d_in, const int* in_sizes, int n_in,
                              void* d_out, int out_size)
{
    (void)in_sizes; (void)n_in; (void)out_size;
    const float* x  = (const float*)d_in[0];
    const float* Wq = (const float*)d_in[1];
    const float* gq = (const float*)d_in[2];
    const float* bq = (const float*)d_in[3];
    const float* Wk = (const float*)d_in[4];
    const float* gk = (const float*)d_in[5];
    const float* bk = (const float*)d_in[6];
    const float* Wv = (const float*)d_in[7];
    const float* gv = (const float*)d_in[8];
    const float* bv = (const float*)d_in[9];
    float* out = (float*)d_out;

    cudaFuncSetAttribute(proj_gemm,  cudaFuncAttributeMaxDynamicSharedMemorySize, SMEM_BYTES);
    cudaFuncSetAttribute(attn_fused, cudaFuncAttributeMaxDynamicSharedMemorySize, SMEM_ATTN);

    // 1) input conversions
    convert_w<<<dim3(COUT * CIN / 4 / 256, 1, 3), 256>>>(Wq, Wk, Wv);
    transpose_x<<<dim3(PP / 32, CIN / 32, NB), 256>>>(x);
    // 2) Y = W x (bf16 3-term)
    proj_gemm<<<dim3(PP / 128, COUT / 128, 24), 256, SMEM_BYTES>>>();
    // 3) BN stats
    stats_kernel<<<3 * COUT, 256>>>(gq, bq, gk, bk, gv, bv);
    // 4) BN + LeakyReLU, emit Q bf16 hi/lo and K^T/V^T bf16 single
    bn_apply_q<<<(unsigned)((size_t)NB * COUT * PP / 4 / 256), 256>>>();
    bn_apply_t<<<dim3(PP / 32, COUT / 32, 16), 256>>>();
    // 5) fused S -> softmax -> O
    attn_fused<<<dim3(16, 64), 256, SMEM_ATTN>>>(out);
}

// round 8
// speedup vs baseline: 1.8625x; 1.2982x over previous
#include <cuda_runtime.h>
#include <cuda_bf16.h>
#include <cstdint>

#define NB   8
#define CIN  512
#define COUT 1024
#define PP   2048
#define NH   8
#define DH   128

typedef __nv_bfloat16 bf16;

// ---------------- device scratch (static: no allocation allowed) -------------
__device__ float g_Y[(size_t)3 * NB * COUT * PP];                    // 192 MB
__device__ float g_scale[3][COUT];
__device__ float g_shift[3][COUT];
__device__ bf16  g_Whi[3][COUT * CIN], g_Wlo[3][COUT * CIN];
__device__ bf16  g_xT[(size_t)NB * PP * CIN];                        // single plane
__device__ bf16  g_Q[(size_t)NB * COUT * PP];                        // single plane
__device__ bf16  g_KT[(size_t)NB * PP * COUT];                       // single plane
__device__ bf16  g_VT[(size_t)NB * PP * COUT];                       // single plane

// ---------------- PTX helpers (baseline PTX only) ----------------------------
__device__ __forceinline__ uint32_t smem_u32(const void* p) {
    uint32_t a;
    asm("{ .reg .u64 t; cvta.to.shared.u64 t, %1; cvt.u32.u64 %0, t; }" : "=r"(a) : "l"(p));
    return a;
}
__device__ __forceinline__ void cp16(uint32_t saddr, const void* g) {
    asm volatile("cp.async.cg.shared.global [%0], [%1], 16;" :: "r"(saddr), "l"(g));
}
#define CP_COMMIT() asm volatile("cp.async.commit_group;" ::: "memory")
template <int N>
__device__ __forceinline__ void cp_wait() {
    asm volatile("cp.async.wait_group %0;" :: "n"(N) : "memory");
}
__device__ __forceinline__ void lma4(uint32_t* r, uint32_t addr) {
    asm volatile("ldmatrix.sync.aligned.m8n8.x4.shared.b16 {%0,%1,%2,%3}, [%4];"
                 : "=r"(r[0]), "=r"(r[1]), "=r"(r[2]), "=r"(r[3]) : "r"(addr));
}
__device__ __forceinline__ void mma16816(float* d, const uint32_t* a, const uint32_t* b) {
    asm volatile("mma.sync.aligned.m16n8k16.row.col.f32.bf16.bf16.f32 "
                 "{%0,%1,%2,%3}, {%4,%5,%6,%7}, {%8,%9}, {%0,%1,%2,%3};"
                 : "+f"(d[0]), "+f"(d[1]), "+f"(d[2]), "+f"(d[3])
                 : "r"(a[0]), "r"(a[1]), "r"(a[2]), "r"(a[3]), "r"(b[0]), "r"(b[1]));
}

// =============================================================================
// Projection GEMM (W hi/lo x single-plane x = 2 terms): 128x128 tile, K-chunk 32
// =============================================================================
#define ROWB   80
#define MATB   (128 * ROWB)
#define STAGEB (3 * MATB)
#define OFF_AH 0
#define OFF_AL MATB
#define OFF_B  (2 * MATB)
#define SMEM_BYTES (2 * STAGEB)          // 61440

__device__ __forceinline__ void gemm_core(const bf16* __restrict__ Ah,
                                          const bf16* __restrict__ Al,
                                          const bf16* __restrict__ Bm,
                                          size_t lda, size_t ldb, int K,
                                          float* __restrict__ C, size_t ldc,
                                          float alpha, int m0, int n0)
{
    extern __shared__ __align__(128) char smem[];
    const uint32_t sb = smem_u32(smem);
    const int tid = threadIdx.x;
    const int L = tid & 31;
    const int w = tid >> 5;
    const int wm = w >> 2, wn = w & 3;

    const int ck0 = tid * 2, ck1 = tid * 2 + 1;
    const int lr0 = ck0 >> 2, lc0 = ck0 & 3;
    const int lr1 = ck1 >> 2, lc1 = ck1 & 3;

    const bf16* pAh0 = Ah + (size_t)(m0 + lr0) * lda + lc0 * 8;
    const bf16* pAh1 = Ah + (size_t)(m0 + lr1) * lda + lc1 * 8;
    const bf16* pAl0 = Al + (size_t)(m0 + lr0) * lda + lc0 * 8;
    const bf16* pAl1 = Al + (size_t)(m0 + lr1) * lda + lc1 * 8;
    const bf16* pB0  = Bm + (size_t)(n0 + lr0) * ldb + lc0 * 8;
    const bf16* pB1  = Bm + (size_t)(n0 + lr1) * ldb + lc1 * 8;
    const uint32_t so0 = lr0 * ROWB + lc0 * 16;
    const uint32_t so1 = lr1 * ROWB + lc1 * 16;

    float acc[4][4][4];
#pragma unroll
    for (int mt = 0; mt < 4; mt++)
#pragma unroll
        for (int nt = 0; nt < 4; nt++)
#pragma unroll
            for (int i = 0; i < 4; i++) acc[mt][nt][i] = 0.0f;

    const int nch = K >> 5;
    {
        uint32_t base = sb;
        cp16(base + OFF_AH + so0, pAh0); cp16(base + OFF_AH + so1, pAh1);
        cp16(base + OFF_AL + so0, pAl0); cp16(base + OFF_AL + so1, pAl1);
        cp16(base + OFF_B  + so0, pB0);  cp16(base + OFF_B  + so1, pB1);
        CP_COMMIT();
    }

    const uint32_t a_row = (uint32_t)(wm * 64 + ((L >> 3) & 1) * 8 + (L & 7));
    const uint32_t a_cc  = (uint32_t)(L >> 4);
    const uint32_t b_row = (uint32_t)(wn * 32 + ((L >> 4) << 3) + (L & 7));
    const uint32_t b_cc  = (uint32_t)((L >> 3) & 1);

    for (int ch = 0; ch < nch; ch++) {
        if (ch + 1 < nch) {
            uint32_t base = sb + ((ch + 1) & 1) * STAGEB;
            int kc = (ch + 1) * 32;
            cp16(base + OFF_AH + so0, pAh0 + kc); cp16(base + OFF_AH + so1, pAh1 + kc);
            cp16(base + OFF_AL + so0, pAl0 + kc); cp16(base + OFF_AL + so1, pAl1 + kc);
            cp16(base + OFF_B  + so0, pB0 + kc);  cp16(base + OFF_B  + so1, pB1 + kc);
            CP_COMMIT();
            cp_wait<1>();
        } else {
            cp_wait<0>();
        }
        __syncthreads();

        uint32_t base = sb + (ch & 1) * STAGEB;
#pragma unroll
        for (int ks = 0; ks < 2; ks++) {
            uint32_t afh[4][4], afl[4][4], bf[4][2];
            uint32_t acol = (a_cc + ks * 2) * 16;
            uint32_t bcol = (b_cc + ks * 2) * 16;
#pragma unroll
            for (int mt = 0; mt < 4; mt++) {
                uint32_t ro = (a_row + mt * 16) * ROWB;
                lma4(afh[mt], base + OFF_AH + ro + acol);
                lma4(afl[mt], base + OFF_AL + ro + acol);
            }
#pragma unroll
            for (int np = 0; np < 2; np++) {
                uint32_t ro = (b_row + np * 16) * ROWB;
                uint32_t t4[4];
                lma4(t4, base + OFF_B + ro + bcol);
                bf[2 * np][0] = t4[0]; bf[2 * np][1] = t4[1];
                bf[2 * np + 1][0] = t4[2]; bf[2 * np + 1][1] = t4[3];
            }
#pragma unroll
            for (int mt = 0; mt < 4; mt++)
#pragma unroll
                for (int nt = 0; nt < 4; nt++) {
                    mma16816(acc[mt][nt], afh[mt], bf[nt]);
                    mma16816(acc[mt][nt], afl[mt], bf[nt]);
                }
        }
        __syncthreads();
    }

    const int tg = L >> 2, tp = L & 3;
#pragma unroll
    for (int mt = 0; mt < 4; mt++) {
        int r0 = m0 + wm * 64 + mt * 16 + tg;
#pragma unroll
        for (int nt = 0; nt < 4; nt++) {
            int c = n0 + wn * 32 + nt * 8 + tp * 2;
            float2 v0 = make_float2(alpha * acc[mt][nt][0], alpha * acc[mt][nt][1]);
            float2 v1 = make_float2(alpha * acc[mt][nt][2], alpha * acc[mt][nt][3]);
            *(float2*)&C[(size_t)r0 * ldc + c]       = v0;
            *(float2*)&C[(size_t)(r0 + 8) * ldc + c] = v1;
        }
    }
}

__global__ __launch_bounds__(256) void proj_gemm(void) {
    int z = blockIdx.z, proj = z >> 3, b = z & 7;
    gemm_core(g_Whi[proj], g_Wlo[proj],
              g_xT + (size_t)b * PP * CIN,
              CIN, CIN, CIN,
              g_Y + (size_t)z * COUT * PP, PP, 1.0f,
              blockIdx.y * 128, blockIdx.x * 128);
}

// =============================================================================
// Fused flash attention (R4/R6 structure; all operands single bf16 plane)
// One CTA per (b, h, i-tile of 128). 8 warps (wm 2 x wn 4).
// =============================================================================
#define APITCH 272                       // 128 bf16 (256B) + 16B pad
#define TILEB  (128 * APITCH)            // 34816 per plane
#define SM_K   0                         // K: 1 plane
#define SM_VQ  TILEB                     // V then Q (1 plane, shared)
#define SM_P   (2 * TILEB)               // P: 1 plane
#define SM_RM  (3 * TILEB)               // row-max partials: 4 x 128 floats
#define SM_RS  (SM_RM + 2048)            // row-sum partials: 4 x 128 floats
#define SMEM_ATTN (SM_RS + 2048)         // 108544

__device__ __forceinline__ void load_plane(uint32_t sb, uint32_t off,
                                           const bf16* __restrict__ src,
                                           size_t stride, int tid) {
#pragma unroll
    for (int i = 0; i < 8; i++) {
        int idx = tid + i * 256;
        int r = idx >> 4, cc = idx & 15;
        cp16(sb + off + r * APITCH + cc * 16, src + (size_t)r * stride + cc * 8);
    }
}

__global__ __launch_bounds__(256, 1) void attn_fused(float* __restrict__ out) {
    extern __shared__ __align__(128) char smem[];
    const uint32_t sb = smem_u32(smem);
    const int tid = threadIdx.x;
    const int L = tid & 31, w = tid >> 5;
    const int wm = w >> 2, wn = w & 3;
    const int tg = L >> 2, tp = L & 3;
    const int it = blockIdx.x;
    const int z = blockIdx.y, b = z >> 3, h = z & 7;

    const bf16* Kp = g_KT + ((size_t)b * PP + it * 128) * COUT + h * DH;
    const bf16* Vp = g_VT + (size_t)b * PP * COUT + h * DH;
    const bf16* Qp = g_Q + ((size_t)b * COUT + h * DH) * PP;

    // K tile resident in SMEM for the whole kernel
    load_plane(sb, SM_K, Kp, COUT, tid);
    CP_COMMIT(); cp_wait<0>(); __syncthreads();

    const uint32_t a_row = (uint32_t)(wm * 64 + ((L >> 3) & 1) * 8 + (L & 7));
    const uint32_t a_cc  = (uint32_t)(L >> 4);
    const uint32_t b_row = (uint32_t)(wn * 32 + ((L >> 4) << 3) + (L & 7));
    const uint32_t b_cc  = (uint32_t)((L >> 3) & 1);

    const float cS = 1.4426950408889634f * 0.08838834764831845f;  // log2e / sqrt(128)

    float oacc[4][4][4];
    float mrow[4][2], lrow[4][2];
#pragma unroll
    for (int mt = 0; mt < 4; mt++) {
        mrow[mt][0] = mrow[mt][1] = -1e30f;
        lrow[mt][0] = lrow[mt][1] = 0.0f;
#pragma unroll
        for (int nt = 0; nt < 4; nt++)
#pragma unroll
            for (int i = 0; i < 4; i++) oacc[mt][nt][i] = 0.0f;
    }

    for (int jt = 0; jt < 16; jt++) {
        // ---- load V_J (single plane) ----
        load_plane(sb, SM_VQ, Vp + (size_t)jt * 128 * COUT, COUT, tid);
        CP_COMMIT(); cp_wait<0>(); __syncthreads();

        // ---- S = K_I^T V_J (bf16 1-term, k = 128) ----
        float sacc[4][4][4];
#pragma unroll
        for (int mt = 0; mt < 4; mt++)
#pragma unroll
            for (int nt = 0; nt < 4; nt++)
#pragma unroll
                for (int i = 0; i < 4; i++) sacc[mt][nt][i] = 0.0f;

#pragma unroll
        for (int ks = 0; ks < 8; ks++) {
            uint32_t af[4][4], bf[4][2];
            uint32_t acol = (a_cc + ks * 2) * 16;
            uint32_t bcol = (b_cc + ks * 2) * 16;
#pragma unroll
            for (int mt = 0; mt < 4; mt++)
                lma4(af[mt], sb + SM_K + (a_row + mt * 16) * APITCH + acol);
#pragma unroll
            for (int np = 0; np < 2; np++) {
                uint32_t t4[4];
                lma4(t4, sb + SM_VQ + (b_row + np * 16) * APITCH + bcol);
                bf[2 * np][0] = t4[0]; bf[2 * np][1] = t4[1];
                bf[2 * np + 1][0] = t4[2]; bf[2 * np + 1][1] = t4[3];
            }
#pragma unroll
            for (int mt = 0; mt < 4; mt++)
#pragma unroll
                for (int nt = 0; nt < 4; nt++)
                    mma16816(sacc[mt][nt], af[mt], bf[nt]);
        }

        // scale into log2 domain, warp-level row maxes
        float wmax[4][2];
#pragma unroll
        for (int mt = 0; mt < 4; mt++) {
#pragma unroll
            for (int half = 0; half < 2; half++) {
                float mv = -1e30f;
#pragma unroll
                for (int nt = 0; nt < 4; nt++) {
                    sacc[mt][nt][2 * half]     *= cS;
                    sacc[mt][nt][2 * half + 1] *= cS;
                    mv = fmaxf(mv, fmaxf(sacc[mt][nt][2 * half], sacc[mt][nt][2 * half + 1]));
                }
                mv = fmaxf(mv, __shfl_xor_sync(0xffffffffu, mv, 1));
                mv = fmaxf(mv, __shfl_xor_sync(0xffffffffu, mv, 2));
                wmax[mt][half] = mv;
            }
        }
        if (tp == 0) {
#pragma unroll
            for (int mt = 0; mt < 4; mt++) {
                int r = wm * 64 + mt * 16 + tg;
                *(float*)(smem + SM_RM + (wn * 128 + r) * 4)     = wmax[mt][0];
                *(float*)(smem + SM_RM + (wn * 128 + r + 8) * 4) = wmax[mt][1];
            }
        }
        __syncthreads();                 // V reads done + partial maxes visible

        // prefetch Q_J (single plane) into the V buffer
        load_plane(sb, SM_VQ, Qp + (size_t)jt * 128, PP, tid);
        CP_COMMIT();

        // block row max, online update, exp, P write (single bf16), sums
        float wsum[4][2];
#pragma unroll
        for (int mt = 0; mt < 4; mt++) {
#pragma unroll
            for (int half = 0; half < 2; half++) {
                int r = wm * 64 + mt * 16 + tg + half * 8;
                float bm = *(float*)(smem + SM_RM + r * 4);
                bm = fmaxf(bm, *(float*)(smem + SM_RM + (128 + r) * 4));
                bm = fmaxf(bm, *(float*)(smem + SM_RM + (256 + r) * 4));
                bm = fmaxf(bm, *(float*)(smem + SM_RM + (384 + r) * 4));
                float mn = fmaxf(mrow[mt][half], bm);
                float sc = exp2f(mrow[mt][half] - mn);
                mrow[mt][half] = mn;
                lrow[mt][half] *= sc;
                float rs = 0.0f;
#pragma unroll
                for (int nt = 0; nt < 4; nt++) {
                    oacc[mt][nt][2 * half]     *= sc;
                    oacc[mt][nt][2 * half + 1] *= sc;
                    float p0 = exp2f(sacc[mt][nt][2 * half]     - mn);
                    float p1 = exp2f(sacc[mt][nt][2 * half + 1] - mn);
                    rs += p0 + p1;
                    uint32_t col = wn * 32 + nt * 8 + 2 * tp;
                    *(__nv_bfloat162*)(smem + SM_P + r * APITCH + col * 2) =
                        __halves2bfloat162(__float2bfloat16(p0), __float2bfloat16(p1));
                }
                rs += __shfl_xor_sync(0xffffffffu, rs, 1);
                rs += __shfl_xor_sync(0xffffffffu, rs, 2);
                wsum[mt][half] = rs;
            }
        }
        if (tp == 0) {
#pragma unroll
            for (int mt = 0; mt < 4; mt++) {
                int r = wm * 64 + mt * 16 + tg;
                *(float*)(smem + SM_RS + (wn * 128 + r) * 4)     = wsum[mt][0];
                *(float*)(smem + SM_RS + (wn * 128 + r + 8) * 4) = wsum[mt][1];
            }
        }
        cp_wait<0>();
        __syncthreads();                 // P + partial sums visible, Q loaded

#pragma unroll
        for (int mt = 0; mt < 4; mt++) {
#pragma unroll
            for (int half = 0; half < 2; half++) {
                int r = wm * 64 + mt * 16 + tg + half * 8;
                float bs = *(float*)(smem + SM_RS + r * 4)
                         + *(float*)(smem + SM_RS + (128 + r) * 4)
                         + *(float*)(smem + SM_RS + (256 + r) * 4)
                         + *(float*)(smem + SM_RS + (384 + r) * 4);
                lrow[mt][half] += bs;
            }
        }

        // ---- O += P Q  (bf16 1-term, k = 128) ----
#pragma unroll
        for (int ks = 0; ks < 8; ks++) {
            uint32_t af[4][4], bf[4][2];
            uint32_t acol = (a_cc + ks * 2) * 16;
            uint32_t bcol = (b_cc + ks * 2) * 16;
#pragma unroll
            for (int mt = 0; mt < 4; mt++)
                lma4(af[mt], sb + SM_P + (a_row + mt * 16) * APITCH + acol);
#pragma unroll
            for (int np = 0; np < 2; np++) {
                uint32_t t4[4];
                lma4(t4, sb + SM_VQ + (b_row + np * 16) * APITCH + bcol);
                bf[2 * np][0] = t4[0]; bf[2 * np][1] = t4[1];
                bf[2 * np + 1][0] = t4[2]; bf[2 * np + 1][1] = t4[3];
            }
#pragma unroll
            for (int mt = 0; mt < 4; mt++)
#pragma unroll
                for (int nt = 0; nt < 4; nt++)
                    mma16816(oacc[mt][nt], af[mt], bf[nt]);
        }
        __syncthreads();                 // Q/P buffers free for next iteration
    }

    // ---- normalize by 1/l and transpose O[i][c] -> out[c][i] via SMEM ----
    float* fbuf = (float*)smem;          // 128 x 132 floats (K + V planes)
#pragma unroll
    for (int mt = 0; mt < 4; mt++) {
#pragma unroll
        for (int half = 0; half < 2; half++) {
            int r = wm * 64 + mt * 16 + tg + half * 8;
            float inv = 1.0f / lrow[mt][half];
#pragma unroll
            for (int nt = 0; nt < 4; nt++) {
                int c = wn * 32 + nt * 8 + 2 * tp;
                fbuf[(size_t)c * 132 + r]       = oacc[mt][nt][2 * half] * inv;
                fbuf[(size_t)(c + 1) * 132 + r] = oacc[mt][nt][2 * half + 1] * inv;
            }
        }
    }
    __syncthreads();
    const size_t obase = ((size_t)b * COUT + h * DH) * PP + (size_t)it * 128;
#pragma unroll
    for (int rr = 0; rr < 16; rr++) {
        int r = w * 16 + rr;
        float4 v = *(float4*)&fbuf[(size_t)r * 132 + L * 4];
        *(float4*)&out[obase + (size_t)r * PP + L * 4] = v;
    }
}

// ---------------- conversions ------------------------------------------------
__device__ __forceinline__ void split1(float v, bf16& h, bf16& l) {
    h = __float2bfloat16(v);
    l = __float2bfloat16(v - __bfloat162float(h));
}

__global__ __launch_bounds__(256) void convert_w(const float* __restrict__ Wq,
                                                 const float* __restrict__ Wk,
                                                 const float* __restrict__ Wv) {
    int proj = blockIdx.z;
    const float* W = (proj == 0) ? Wq : ((proj == 1) ? Wk : Wv);
    size_t e = ((size_t)blockIdx.x * 256 + threadIdx.x) * 4;
    float4 v = *(const float4*)(W + e);
    bf16 h0, h1, h2, h3, l0, l1, l2, l3;
    split1(v.x, h0, l0); split1(v.y, h1, l1); split1(v.z, h2, l2); split1(v.w, h3, l3);
    ((__nv_bfloat162*)&g_Whi[proj][e])[0] = __halves2bfloat162(h0, h1);
    ((__nv_bfloat162*)&g_Whi[proj][e])[1] = __halves2bfloat162(h2, h3);
    ((__nv_bfloat162*)&g_Wlo[proj][e])[0] = __halves2bfloat162(l0, l1);
    ((__nv_bfloat162*)&g_Wlo[proj][e])[1] = __halves2bfloat162(l2, l3);
}

__global__ __launch_bounds__(256) void transpose_x(const float* __restrict__ x) {
    __shared__ float t[32][33];
    int b = blockIdx.z;
    int p0 = blockIdx.x * 32, c0 = blockIdx.y * 32;
    int tx = threadIdx.x & 31, ty = threadIdx.x >> 5;
#pragma unroll
    for (int j = 0; j < 4; j++)
        t[ty + 8 * j][tx] = x[((size_t)b * CIN + c0 + ty + 8 * j) * PP + p0 + tx];
    __syncthreads();
#pragma unroll
    for (int j = 0; j < 4; j++) {
        float v = t[tx][ty + 8 * j];
        size_t o = ((size_t)b * PP + p0 + ty + 8 * j) * CIN + c0 + tx;
        g_xT[o] = __float2bfloat16(v);
    }
}

// ---------------- BN stats ---------------------------------------------------
__global__ __launch_bounds__(256) void stats_kernel(const float* __restrict__ gq,
                                                    const float* __restrict__ bq,
                                                    const float* __restrict__ gk,
                                                    const float* __restrict__ bk,
                                                    const float* __restrict__ gv,
                                                    const float* __restrict__ bv) {
    int ch = blockIdx.x & (COUT - 1);
    int proj = blockIdx.x >> 10;
    const float* base = g_Y + ((size_t)proj * NB) * COUT * PP + (size_t)ch * PP;
    float s = 0.0f, sq = 0.0f;
    for (int b = 0; b < NB; b++) {
        const float* p = base + (size_t)b * COUT * PP;
        for (int i = threadIdx.x; i < PP; i += 256) {
            float v = p[i]; s += v; sq += v * v;
        }
    }
#pragma unroll
    for (int o = 16; o; o >>= 1) {
        s  += __shfl_xor_sync(0xffffffffu, s, o);
        sq += __shfl_xor_sync(0xffffffffu, sq, o);
    }
    __shared__ float rs[8], rq[8];
    if ((threadIdx.x & 31) == 0) { rs[threadIdx.x >> 5] = s; rq[threadIdx.x >> 5] = sq; }
    __syncthreads();
    if (threadIdx.x == 0) {
        float S = 0.0f, Q = 0.0f;
#pragma unroll
        for (int w = 0; w < 8; w++) { S += rs[w]; Q += rq[w]; }
        const float inv_n = 1.0f / (float)(NB * PP);
        float mean = S * inv_n;
        float var  = Q * inv_n - mean * mean;
        const float* g  = (proj == 0) ? gq : ((proj == 1) ? gk : gv);
        const float* bb = (proj == 0) ? bq : ((proj == 1) ? bk : bv);
        float sc = g[ch] * rsqrtf(var + 1e-5f);
        g_scale[proj][ch] = sc;
        g_shift[proj][ch] = bb[ch] - mean * sc;
    }
}

// ---------------- BN apply: Q path (keep [c][p] layout, single bf16) ---------
__global__ __launch_bounds__(256) void bn_apply_q(void) {
    size_t e = ((size_t)blockIdx.x * 256 + threadIdx.x) * 4;
    int ch = (int)((e >> 11) & (COUT - 1));
    float sc = g_scale[0][ch], sh = g_shift[0][ch];
    float4 y = *(float4*)&g_Y[e];
    y.x = sc * y.x + sh; y.x = (y.x < 0.0f) ? 0.1f * y.x : y.x;
    y.y = sc * y.y + sh; y.y = (y.y < 0.0f) ? 0.1f * y.y : y.y;
    y.z = sc * y.z + sh; y.z = (y.z < 0.0f) ? 0.1f * y.z : y.z;
    y.w = sc * y.w + sh; y.w = (y.w < 0.0f) ? 0.1f * y.w : y.w;
    ((__nv_bfloat162*)&g_Q[e])[0] = __halves2bfloat162(__float2bfloat16(y.x), __float2bfloat16(y.y));
    ((__nv_bfloat162*)&g_Q[e])[1] = __halves2bfloat162(__float2bfloat16(y.z), __float2bfloat16(y.w));
}

// ---------------- BN apply + transpose: K/V ([c][p] -> [p][c], bf16 single) --
__global__ __launch_bounds__(256) void bn_apply_t(void) {
    __shared__ float t[32][33];
    int z = blockIdx.z;
    int proj = 1 + (z >> 3), b = z & 7;
    int p0 = blockIdx.x * 32, c0 = blockIdx.y * 32;
    int tx = threadIdx.x & 31, ty = threadIdx.x >> 5;
#pragma unroll
    for (int j = 0; j < 4; j++) {
        int c = c0 + ty + 8 * j;
        float sc = g_scale[proj][c], sh = g_shift[proj][c];
        float v = g_Y[(((size_t)proj * NB + b) * COUT + c) * PP + p0 + tx];
        v = sc * v + sh;
        v = (v < 0.0f) ? 0.1f * v : v;
        t[ty + 8 * j][tx] = v;
    }
    __syncthreads();
    bf16* T = (proj == 1) ? g_KT : g_VT;
#pragma unroll
    for (int j = 0; j < 4; j++) {
        float v = t[tx][ty + 8 * j];
        size_t o = ((size_t)b * PP + p0 + ty + 8 * j) * COUT + c0 + tx;
        T[o] = __float2bfloat16(v);
    }
}

// ---------------- launch -----------------------------------------------------
extern "C" void kernel_launch(void* const* d_in, const int* in_sizes, int n_in,
                              void* d_out, int out_size)
{
    (void)in_sizes; (void)n_in; (void)out_size;
    const float* x  = (const float*)d_in[0];
    const float* Wq = (const float*)d_in[1];
    const float* gq = (const float*)d_in[2];
    const float* bq = (const float*)d_in[3];
    const float* Wk = (const float*)d_in[4];
    const float* gk = (const float*)d_in[5];
    const float* bk = (const float*)d_in[6];
    const float* Wv = (const float*)d_in[7];
    const float* gv = (const float*)d_in[8];
    const float* bv = (const float*)d_in[9];
    float* out = (float*)d_out;

    cudaFuncSetAttribute(proj_gemm,  cudaFuncAttributeMaxDynamicSharedMemorySize, SMEM_BYTES);
    cudaFuncSetAttribute(attn_fused, cudaFuncAttributeMaxDynamicSharedMemorySize, SMEM_ATTN);

    // 1) input conversions: W -> bf16 hi/lo, x -> x^T single bf16
    convert_w<<<dim3(COUT * CIN / 4 / 256, 1, 3), 256>>>(Wq, Wk, Wv);
    transpose_x<<<dim3(PP / 32, CIN / 32, NB), 256>>>(x);
    // 2) Y = W x (bf16 2-term)
    proj_gemm<<<dim3(PP / 128, COUT / 128, 24), 256, SMEM_BYTES>>>();
    // 3) BN stats
    stats_kernel<<<3 * COUT, 256>>>(gq, bq, gk, bk, gv, bv);
    // 4) BN + LeakyReLU, emit Q / K^T / V^T single bf16
    bn_apply_q<<<(unsigned)((size_t)NB * COUT * PP / 4 / 256), 256>>>();
    bn_apply_t<<<dim3(PP / 32, COUT / 32, 16), 256>>>();
    // 5) fused S -> softmax -> O
    attn_fused<<<dim3(16, 64), 256, SMEM_ATTN>>>(out);
}

// round 9
// speedup vs baseline: 2.1375x; 1.1477x over previous
#include <cuda_runtime.h>
#include <cuda_bf16.h>
#include <cstdint>

#define NB   8
#define CIN  512
#define COUT 1024
#define PP   2048
#define NH   8
#define DH   128

typedef __nv_bfloat16 bf16;

// ---------------- device scratch (static: no allocation allowed) -------------
__device__ float g_Y[(size_t)3 * NB * COUT * PP];                    // 192 MB
__device__ float g_scale[3][COUT];
__device__ float g_shift[3][COUT];
__device__ bf16  g_W[3][COUT * CIN];                                 // single plane
__device__ bf16  g_xT[(size_t)NB * PP * CIN];                        // single plane
__device__ bf16  g_Q[(size_t)NB * COUT * PP];                        // single plane
__device__ bf16  g_KT[(size_t)NB * PP * COUT];                       // single plane
__device__ bf16  g_VT[(size_t)NB * PP * COUT];                       // single plane

// ---------------- PTX helpers (baseline PTX only) ----------------------------
__device__ __forceinline__ uint32_t smem_u32(const void* p) {
    uint32_t a;
    asm("{ .reg .u64 t; cvta.to.shared.u64 t, %1; cvt.u32.u64 %0, t; }" : "=r"(a) : "l"(p));
    return a;
}
__device__ __forceinline__ void cp16(uint32_t saddr, const void* g) {
    asm volatile("cp.async.cg.shared.global [%0], [%1], 16;" :: "r"(saddr), "l"(g));
}
#define CP_COMMIT() asm volatile("cp.async.commit_group;" ::: "memory")
template <int N>
__device__ __forceinline__ void cp_wait() {
    asm volatile("cp.async.wait_group %0;" :: "n"(N) : "memory");
}
__device__ __forceinline__ void lma4(uint32_t* r, uint32_t addr) {
    asm volatile("ldmatrix.sync.aligned.m8n8.x4.shared.b16 {%0,%1,%2,%3}, [%4];"
                 : "=r"(r[0]), "=r"(r[1]), "=r"(r[2]), "=r"(r[3]) : "r"(addr));
}
__device__ __forceinline__ void mma16816(float* d, const uint32_t* a, const uint32_t* b) {
    asm volatile("mma.sync.aligned.m16n8k16.row.col.f32.bf16.bf16.f32 "
                 "{%0,%1,%2,%3}, {%4,%5,%6,%7}, {%8,%9}, {%0,%1,%2,%3};"
                 : "+f"(d[0]), "+f"(d[1]), "+f"(d[2]), "+f"(d[3])
                 : "r"(a[0]), "r"(a[1]), "r"(a[2]), "r"(a[3]), "r"(b[0]), "r"(b[1]));
}
// guaranteed-MUFU exp2 (ex2.approx rel err ~2^-22, way inside budget)
__device__ __forceinline__ float ex2f(float x) {
    float y;
    asm("ex2.approx.ftz.f32 %0, %1;" : "=f"(y) : "f"(x));
    return y;
}

// =============================================================================
// Projection GEMM (single-plane W x single-plane x = 1 term): 128x128 tile
// =============================================================================
#define ROWB   80
#define MATB   (128 * ROWB)
#define STAGEB (2 * MATB)
#define OFF_A  0
#define OFF_B  MATB
#define SMEM_BYTES (2 * STAGEB)          // 40960

__device__ __forceinline__ void gemm_core(const bf16* __restrict__ Am,
                                          const bf16* __restrict__ Bm,
                                          size_t lda, size_t ldb, int K,
                                          float* __restrict__ C, size_t ldc,
                                          float alpha, int m0, int n0)
{
    extern __shared__ __align__(128) char smem[];
    const uint32_t sb = smem_u32(smem);
    const int tid = threadIdx.x;
    const int L = tid & 31;
    const int w = tid >> 5;
    const int wm = w >> 2, wn = w & 3;

    const int ck0 = tid * 2, ck1 = tid * 2 + 1;
    const int lr0 = ck0 >> 2, lc0 = ck0 & 3;
    const int lr1 = ck1 >> 2, lc1 = ck1 & 3;

    const bf16* pA0 = Am + (size_t)(m0 + lr0) * lda + lc0 * 8;
    const bf16* pA1 = Am + (size_t)(m0 + lr1) * lda + lc1 * 8;
    const bf16* pB0 = Bm + (size_t)(n0 + lr0) * ldb + lc0 * 8;
    const bf16* pB1 = Bm + (size_t)(n0 + lr1) * ldb + lc1 * 8;
    const uint32_t so0 = lr0 * ROWB + lc0 * 16;
    const uint32_t so1 = lr1 * ROWB + lc1 * 16;

    float acc[4][4][4];
#pragma unroll
    for (int mt = 0; mt < 4; mt++)
#pragma unroll
        for (int nt = 0; nt < 4; nt++)
#pragma unroll
            for (int i = 0; i < 4; i++) acc[mt][nt][i] = 0.0f;

    const int nch = K >> 5;
    {
        uint32_t base = sb;
        cp16(base + OFF_A + so0, pA0); cp16(base + OFF_A + so1, pA1);
        cp16(base + OFF_B + so0, pB0); cp16(base + OFF_B + so1, pB1);
        CP_COMMIT();
    }

    const uint32_t a_row = (uint32_t)(wm * 64 + ((L >> 3) & 1) * 8 + (L & 7));
    const uint32_t a_cc  = (uint32_t)(L >> 4);
    const uint32_t b_row = (uint32_t)(wn * 32 + ((L >> 4) << 3) + (L & 7));
    const uint32_t b_cc  = (uint32_t)((L >> 3) & 1);

    for (int ch = 0; ch < nch; ch++) {
        if (ch + 1 < nch) {
            uint32_t base = sb + ((ch + 1) & 1) * STAGEB;
            int kc = (ch + 1) * 32;
            cp16(base + OFF_A + so0, pA0 + kc); cp16(base + OFF_A + so1, pA1 + kc);
            cp16(base + OFF_B + so0, pB0 + kc); cp16(base + OFF_B + so1, pB1 + kc);
            CP_COMMIT();
            cp_wait<1>();
        } else {
            cp_wait<0>();
        }
        __syncthreads();

        uint32_t base = sb + (ch & 1) * STAGEB;
#pragma unroll
        for (int ks = 0; ks < 2; ks++) {
            uint32_t af[4][4], bf[4][2];
            uint32_t acol = (a_cc + ks * 2) * 16;
            uint32_t bcol = (b_cc + ks * 2) * 16;
#pragma unroll
            for (int mt = 0; mt < 4; mt++)
                lma4(af[mt], base + OFF_A + (a_row + mt * 16) * ROWB + acol);
#pragma unroll
            for (int np = 0; np < 2; np++) {
                uint32_t t4[4];
                lma4(t4, base + OFF_B + (b_row + np * 16) * ROWB + bcol);
                bf[2 * np][0] = t4[0]; bf[2 * np][1] = t4[1];
                bf[2 * np + 1][0] = t4[2]; bf[2 * np + 1][1] = t4[3];
            }
#pragma unroll
            for (int mt = 0; mt < 4; mt++)
#pragma unroll
                for (int nt = 0; nt < 4; nt++)
                    mma16816(acc[mt][nt], af[mt], bf[nt]);
        }
        __syncthreads();
    }

    const int tg = L >> 2, tp = L & 3;
#pragma unroll
    for (int mt = 0; mt < 4; mt++) {
        int r0 = m0 + wm * 64 + mt * 16 + tg;
#pragma unroll
        for (int nt = 0; nt < 4; nt++) {
            int c = n0 + wn * 32 + nt * 8 + tp * 2;
            float2 v0 = make_float2(alpha * acc[mt][nt][0], alpha * acc[mt][nt][1]);
            float2 v1 = make_float2(alpha * acc[mt][nt][2], alpha * acc[mt][nt][3]);
            *(float2*)&C[(size_t)r0 * ldc + c]       = v0;
            *(float2*)&C[(size_t)(r0 + 8) * ldc + c] = v1;
        }
    }
}

__global__ __launch_bounds__(256) void proj_gemm(void) {
    int z = blockIdx.z, proj = z >> 3, b = z & 7;
    gemm_core(g_W[proj],
              g_xT + (size_t)b * PP * CIN,
              CIN, CIN, CIN,
              g_Y + (size_t)z * COUT * PP, PP, 1.0f,
              blockIdx.y * 128, blockIdx.x * 128);
}

// =============================================================================
// Fused flash attention (R4/R6/R7 structure; single bf16 planes; MUFU exp)
// One CTA per (b, h, i-tile of 128). 8 warps (wm 2 x wn 4).
// =============================================================================
#define APITCH 272                       // 128 bf16 (256B) + 16B pad
#define TILEB  (128 * APITCH)            // 34816 per plane
#define SM_K   0                         // K: 1 plane
#define SM_VQ  TILEB                     // V then Q (1 plane, shared)
#define SM_P   (2 * TILEB)               // P: 1 plane
#define SM_RM  (3 * TILEB)               // row-max partials: 4 x 128 floats
#define SM_RS  (SM_RM + 2048)            // row-sum partials: 4 x 128 floats
#define SMEM_ATTN (SM_RS + 2048)         // 108544

__device__ __forceinline__ void load_plane(uint32_t sb, uint32_t off,
                                           const bf16* __restrict__ src,
                                           size_t stride, int tid) {
#pragma unroll
    for (int i = 0; i < 8; i++) {
        int idx = tid + i * 256;
        int r = idx >> 4, cc = idx & 15;
        cp16(sb + off + r * APITCH + cc * 16, src + (size_t)r * stride + cc * 8);
    }
}

__global__ __launch_bounds__(256, 1) void attn_fused(float* __restrict__ out) {
    extern __shared__ __align__(128) char smem[];
    const uint32_t sb = smem_u32(smem);
    const int tid = threadIdx.x;
    const int L = tid & 31, w = tid >> 5;
    const int wm = w >> 2, wn = w & 3;
    const int tg = L >> 2, tp = L & 3;
    const int it = blockIdx.x;
    const int z = blockIdx.y, b = z >> 3, h = z & 7;

    const bf16* Kp = g_KT + ((size_t)b * PP + it * 128) * COUT + h * DH;
    const bf16* Vp = g_VT + (size_t)b * PP * COUT + h * DH;
    const bf16* Qp = g_Q + ((size_t)b * COUT + h * DH) * PP;

    // K tile resident in SMEM for the whole kernel
    load_plane(sb, SM_K, Kp, COUT, tid);
    CP_COMMIT(); cp_wait<0>(); __syncthreads();

    const uint32_t a_row = (uint32_t)(wm * 64 + ((L >> 3) & 1) * 8 + (L & 7));
    const uint32_t a_cc  = (uint32_t)(L >> 4);
    const uint32_t b_row = (uint32_t)(wn * 32 + ((L >> 4) << 3) + (L & 7));
    const uint32_t b_cc  = (uint32_t)((L >> 3) & 1);

    const float cS = 1.4426950408889634f * 0.08838834764831845f;  // log2e / sqrt(128)

    float oacc[4][4][4];
    float mrow[4][2], lrow[4][2];
#pragma unroll
    for (int mt = 0; mt < 4; mt++) {
        mrow[mt][0] = mrow[mt][1] = -1e30f;
        lrow[mt][0] = lrow[mt][1] = 0.0f;
#pragma unroll
        for (int nt = 0; nt < 4; nt++)
#pragma unroll
            for (int i = 0; i < 4; i++) oacc[mt][nt][i] = 0.0f;
    }

    for (int jt = 0; jt < 16; jt++) {
        // ---- load V_J (single plane) ----
        load_plane(sb, SM_VQ, Vp + (size_t)jt * 128 * COUT, COUT, tid);
        CP_COMMIT(); cp_wait<0>(); __syncthreads();

        // ---- S = K_I^T V_J (bf16 1-term, k = 128) ----
        float sacc[4][4][4];
#pragma unroll
        for (int mt = 0; mt < 4; mt++)
#pragma unroll
            for (int nt = 0; nt < 4; nt++)
#pragma unroll
                for (int i = 0; i < 4; i++) sacc[mt][nt][i] = 0.0f;

#pragma unroll
        for (int ks = 0; ks < 8; ks++) {
            uint32_t af[4][4], bf[4][2];
            uint32_t acol = (a_cc + ks * 2) * 16;
            uint32_t bcol = (b_cc + ks * 2) * 16;
#pragma unroll
            for (int mt = 0; mt < 4; mt++)
                lma4(af[mt], sb + SM_K + (a_row + mt * 16) * APITCH + acol);
#pragma unroll
            for (int np = 0; np < 2; np++) {
                uint32_t t4[4];
                lma4(t4, sb + SM_VQ + (b_row + np * 16) * APITCH + bcol);
                bf[2 * np][0] = t4[0]; bf[2 * np][1] = t4[1];
                bf[2 * np + 1][0] = t4[2]; bf[2 * np + 1][1] = t4[3];
            }
#pragma unroll
            for (int mt = 0; mt < 4; mt++)
#pragma unroll
                for (int nt = 0; nt < 4; nt++)
                    mma16816(sacc[mt][nt], af[mt], bf[nt]);
        }

        // scale into log2 domain, warp-level row maxes
        float wmax[4][2];
#pragma unroll
        for (int mt = 0; mt < 4; mt++) {
#pragma unroll
            for (int half = 0; half < 2; half++) {
                float mv = -1e30f;
#pragma unroll
                for (int nt = 0; nt < 4; nt++) {
                    sacc[mt][nt][2 * half]     *= cS;
                    sacc[mt][nt][2 * half + 1] *= cS;
                    mv = fmaxf(mv, fmaxf(sacc[mt][nt][2 * half], sacc[mt][nt][2 * half + 1]));
                }
                mv = fmaxf(mv, __shfl_xor_sync(0xffffffffu, mv, 1));
                mv = fmaxf(mv, __shfl_xor_sync(0xffffffffu, mv, 2));
                wmax[mt][half] = mv;
            }
        }
        if (tp == 0) {
#pragma unroll
            for (int mt = 0; mt < 4; mt++) {
                int r = wm * 64 + mt * 16 + tg;
                *(float*)(smem + SM_RM + (wn * 128 + r) * 4)     = wmax[mt][0];
                *(float*)(smem + SM_RM + (wn * 128 + r + 8) * 4) = wmax[mt][1];
            }
        }
        __syncthreads();                 // V reads done + partial maxes visible

        // prefetch Q_J (single plane) into the V buffer
        load_plane(sb, SM_VQ, Qp + (size_t)jt * 128, PP, tid);
        CP_COMMIT();

        // block row max, online update, exp (MUFU), P write, partial sums
        float wsum[4][2];
#pragma unroll
        for (int mt = 0; mt < 4; mt++) {
#pragma unroll
            for (int half = 0; half < 2; half++) {
                int r = wm * 64 + mt * 16 + tg + half * 8;
                float bm = *(float*)(smem + SM_RM + r * 4);
                bm = fmaxf(bm, *(float*)(smem + SM_RM + (128 + r) * 4));
                bm = fmaxf(bm, *(float*)(smem + SM_RM + (256 + r) * 4));
                bm = fmaxf(bm, *(float*)(smem + SM_RM + (384 + r) * 4));
                float mn = fmaxf(mrow[mt][half], bm);
                float sc = ex2f(mrow[mt][half] - mn);
                mrow[mt][half] = mn;
                lrow[mt][half] *= sc;
                float rs = 0.0f;
#pragma unroll
                for (int nt = 0; nt < 4; nt++) {
                    oacc[mt][nt][2 * half]     *= sc;
                    oacc[mt][nt][2 * half + 1] *= sc;
                    float p0 = ex2f(sacc[mt][nt][2 * half]     - mn);
                    float p1 = ex2f(sacc[mt][nt][2 * half + 1] - mn);
                    rs += p0 + p1;
                    uint32_t col = wn * 32 + nt * 8 + 2 * tp;
                    *(__nv_bfloat162*)(smem + SM_P + r * APITCH + col * 2) =
                        __halves2bfloat162(__float2bfloat16(p0), __float2bfloat16(p1));
                }
                rs += __shfl_xor_sync(0xffffffffu, rs, 1);
                rs += __shfl_xor_sync(0xffffffffu, rs, 2);
                wsum[mt][half] = rs;
            }
        }
        if (tp == 0) {
#pragma unroll
            for (int mt = 0; mt < 4; mt++) {
                int r = wm * 64 + mt * 16 + tg;
                *(float*)(smem + SM_RS + (wn * 128 + r) * 4)     = wsum[mt][0];
                *(float*)(smem + SM_RS + (wn * 128 + r + 8) * 4) = wsum[mt][1];
            }
        }
        cp_wait<0>();
        __syncthreads();                 // P + partial sums visible, Q loaded

#pragma unroll
        for (int mt = 0; mt < 4; mt++) {
#pragma unroll
            for (int half = 0; half < 2; half++) {
                int r = wm * 64 + mt * 16 + tg + half * 8;
                float bs = *(float*)(smem + SM_RS + r * 4)
                         + *(float*)(smem + SM_RS + (128 + r) * 4)
                         + *(float*)(smem + SM_RS + (256 + r) * 4)
                         + *(float*)(smem + SM_RS + (384 + r) * 4);
                lrow[mt][half] += bs;
            }
        }

        // ---- O += P Q  (bf16 1-term, k = 128) ----
#pragma unroll
        for (int ks = 0; ks < 8; ks++) {
            uint32_t af[4][4], bf[4][2];
            uint32_t acol = (a_cc + ks * 2) * 16;
            uint32_t bcol = (b_cc + ks * 2) * 16;
#pragma unroll
            for (int mt = 0; mt < 4; mt++)
                lma4(af[mt], sb + SM_P + (a_row + mt * 16) * APITCH + acol);
#pragma unroll
            for (int np = 0; np < 2; np++) {
                uint32_t t4[4];
                lma4(t4, sb + SM_VQ + (b_row + np * 16) * APITCH + bcol);
                bf[2 * np][0] = t4[0]; bf[2 * np][1] = t4[1];
                bf[2 * np + 1][0] = t4[2]; bf[2 * np + 1][1] = t4[3];
            }
#pragma unroll
            for (int mt = 0; mt < 4; mt++)
#pragma unroll
                for (int nt = 0; nt < 4; nt++)
                    mma16816(oacc[mt][nt], af[mt], bf[nt]);
        }
        __syncthreads();                 // Q/P buffers free for next iteration
    }

    // ---- normalize by 1/l and transpose O[i][c] -> out[c][i] via SMEM ----
    float* fbuf = (float*)smem;          // 128 x 132 floats (K + V planes)
#pragma unroll
    for (int mt = 0; mt < 4; mt++) {
#pragma unroll
        for (int half = 0; half < 2; half++) {
            int r = wm * 64 + mt * 16 + tg + half * 8;
            float inv = 1.0f / lrow[mt][half];
#pragma unroll
            for (int nt = 0; nt < 4; nt++) {
                int c = wn * 32 + nt * 8 + 2 * tp;
                fbuf[(size_t)c * 132 + r]       = oacc[mt][nt][2 * half] * inv;
                fbuf[(size_t)(c + 1) * 132 + r] = oacc[mt][nt][2 * half + 1] * inv;
            }
        }
    }
    __syncthreads();
    const size_t obase = ((size_t)b * COUT + h * DH) * PP + (size_t)it * 128;
#pragma unroll
    for (int rr = 0; rr < 16; rr++) {
        int r = w * 16 + rr;
        float4 v = *(float4*)&fbuf[(size_t)r * 132 + L * 4];
        *(float4*)&out[obase + (size_t)r * PP + L * 4] = v;
    }
}

// ---------------- conversions ------------------------------------------------
__global__ __launch_bounds__(256) void convert_w(const float* __restrict__ Wq,
                                                 const float* __restrict__ Wk,
                                                 const float* __restrict__ Wv) {
    int proj = blockIdx.z;
    const float* W = (proj == 0) ? Wq : ((proj == 1) ? Wk : Wv);
    size_t e = ((size_t)blockIdx.x * 256 + threadIdx.x) * 4;
    float4 v = *(const float4*)(W + e);
    ((__nv_bfloat162*)&g_W[proj][e])[0] =
        __halves2bfloat162(__float2bfloat16(v.x), __float2bfloat16(v.y));
    ((__nv_bfloat162*)&g_W[proj][e])[1] =
        __halves2bfloat162(__float2bfloat16(v.z), __float2bfloat16(v.w));
}

__global__ __launch_bounds__(256) void transpose_x(const float* __restrict__ x) {
    __shared__ float t[32][33];
    int b = blockIdx.z;
    int p0 = blockIdx.x * 32, c0 = blockIdx.y * 32;
    int tx = threadIdx.x & 31, ty = threadIdx.x >> 5;
#pragma unroll
    for (int j = 0; j < 4; j++)
        t[ty + 8 * j][tx] = x[((size_t)b * CIN + c0 + ty + 8 * j) * PP + p0 + tx];
    __syncthreads();
#pragma unroll
    for (int j = 0; j < 4; j++) {
        float v = t[tx][ty + 8 * j];
        size_t o = ((size_t)b * PP + p0 + ty + 8 * j) * CIN + c0 + tx;
        g_xT[o] = __float2bfloat16(v);
    }
}

// ---------------- BN stats ---------------------------------------------------
__global__ __launch_bounds__(256) void stats_kernel(const float* __restrict__ gq,
                                                    const float* __restrict__ bq,
                                                    const float* __restrict__ gk,
                                                    const float* __restrict__ bk,
                                                    const float* __restrict__ gv,
                                                    const float* __restrict__ bv) {
    int ch = blockIdx.x & (COUT - 1);
    int proj = blockIdx.x >> 10;
    const float* base = g_Y + ((size_t)proj * NB) * COUT * PP + (size_t)ch * PP;
    float s = 0.0f, sq = 0.0f;
    for (int b = 0; b < NB; b++) {
        const float* p = base + (size_t)b * COUT * PP;
        for (int i = threadIdx.x; i < PP; i += 256) {
            float v = p[i]; s += v; sq += v * v;
        }
    }
#pragma unroll
    for (int o = 16; o; o >>= 1) {
        s  += __shfl_xor_sync(0xffffffffu, s, o);
        sq += __shfl_xor_sync(0xffffffffu, sq, o);
    }
    __shared__ float rs[8], rq[8];
    if ((threadIdx.x & 31) == 0) { rs[threadIdx.x >> 5] = s; rq[threadIdx.x >> 5] = sq; }
    __syncthreads();
    if (threadIdx.x == 0) {
        float S = 0.0f, Q = 0.0f;
#pragma unroll
        for (int w = 0; w < 8; w++) { S += rs[w]; Q += rq[w]; }
        const float inv_n = 1.0f / (float)(NB * PP);
        float mean = S * inv_n;
        float var  = Q * inv_n - mean * mean;
        const float* g  = (proj == 0) ? gq : ((proj == 1) ? gk : gv);
        const float* bb = (proj == 0) ? bq : ((proj == 1) ? bk : bv);
        float sc = g[ch] * rsqrtf(var + 1e-5f);
        g_scale[proj][ch] = sc;
        g_shift[proj][ch] = bb[ch] - mean * sc;
    }
}

// ---------------- BN apply: Q path (keep [c][p] layout, single bf16) ---------
__global__ __launch_bounds__(256) void bn_apply_q(void) {
    size_t e = ((size_t)blockIdx.x * 256 + threadIdx.x) * 4;
    int ch = (int)((e >> 11) & (COUT - 1));
    float sc = g_scale[0][ch], sh = g_shift[0][ch];
    float4 y = *(float4*)&g_Y[e];
    y.x = sc * y.x + sh; y.x = (y.x < 0.0f) ? 0.1f * y.x : y.x;
    y.y = sc * y.y + sh; y.y = (y.y < 0.0f) ? 0.1f * y.y : y.y;
    y.z = sc * y.z + sh; y.z = (y.z < 0.0f) ? 0.1f * y.z : y.z;
    y.w = sc * y.w + sh; y.w = (y.w < 0.0f) ? 0.1f * y.w : y.w;
    ((__nv_bfloat162*)&g_Q[e])[0] = __halves2bfloat162(__float2bfloat16(y.x), __float2bfloat16(y.y));
    ((__nv_bfloat162*)&g_Q[e])[1] = __halves2bfloat162(__float2bfloat16(y.z), __float2bfloat16(y.w));
}

// ---------------- BN apply + transpose: K/V ([c][p] -> [p][c], bf16 single) --
__global__ __launch_bounds__(256) void bn_apply_t(void) {
    __shared__ float t[32][33];
    int z = blockIdx.z;
    int proj = 1 + (z >> 3), b = z & 7;
    int p0 = blockIdx.x * 32, c0 = blockIdx.y * 32;
    int tx = threadIdx.x & 31, ty = threadIdx.x >> 5;
#pragma unroll
    for (int j = 0; j < 4; j++) {
        int c = c0 + ty + 8 * j;
        float sc = g_scale[proj][c], sh = g_shift[proj][c];
        float v = g_Y[(((size_t)proj * NB + b) * COUT + c) * PP + p0 + tx];
        v = sc * v + sh;
        v = (v < 0.0f) ? 0.1f * v : v;
        t[ty + 8 * j][tx] = v;
    }
    __syncthreads();
    bf16* T = (proj == 1) ? g_KT : g_VT;
#pragma unroll
    for (int j = 0; j < 4; j++) {
        float v = t[tx][ty + 8 * j];
        size_t o = ((size_t)b * PP + p0 + ty + 8 * j) * COUT + c0 + tx;
        T[o] = __float2bfloat16(v);
    }
}

// ---------------- launch -----------------------------------------------------
extern "C" void kernel_launch(void* const* d_in, const int* in_sizes, int n_in,
                              void* d_out, int out_size)
{
    (void)in_sizes; (void)n_in; (void)out_size;
    const float* x  = (const float*)d_in[0];
    const float* Wq = (const float*)d_in[1];
    const float* gq = (const float*)d_in[2];
    const float* bq = (const float*)d_in[3];
    const float* Wk = (const float*)d_in[4];
    const float* gk = (const float*)d_in[5];
    const float* bk = (const float*)d_in[6];
    const float* Wv = (const float*)d_in[7];
    const float* gv = (const float*)d_in[8];
    const float* bv = (const float*)d_in[9];
    float* out = (float*)d_out;

    cudaFuncSetAttribute(proj_gemm,  cudaFuncAttributeMaxDynamicSharedMemorySize, SMEM_BYTES);
    cudaFuncSetAttribute(attn_fused, cudaFuncAttributeMaxDynamicSharedMemorySize, SMEM_ATTN);

    // 1) input conversions: W -> bf16, x -> x^T bf16
    convert_w<<<dim3(COUT * CIN / 4 / 256, 1, 3), 256>>>(Wq, Wk, Wv);
    transpose_x<<<dim3(PP / 32, CIN / 32, NB), 256>>>(x);
    // 2) Y = W x (bf16 1-term)
    proj_gemm<<<dim3(PP / 128, COUT / 128, 24), 256, SMEM_BYTES>>>();
    // 3) BN stats
    stats_kernel<<<3 * COUT, 256>>>(gq, bq, gk, bk, gv, bv);
    // 4) BN + LeakyReLU, emit Q / K^T / V^T single bf16
    bn_apply_q<<<(unsigned)((size_t)NB * COUT * PP / 4 / 256), 256>>>();
    bn_apply_t<<<dim3(PP / 32, COUT / 32, 16), 256>>>();
    // 5) fused S -> softmax -> O (MUFU exp)
    attn_fused<<<dim3(16, 64), 256, SMEM_ATTN>>>(out);
}

// round 10
// speedup vs baseline: 2.2357x; 1.0459x over previous
#include <cuda_runtime.h>
#include <cuda_bf16.h>
#include <cstdint>

#define NB   8
#define CIN  512
#define COUT 1024
#define PP   2048
#define NH   8
#define DH   128

typedef __nv_bfloat16 bf16;

// ---------------- device scratch (static: no allocation allowed) -------------
__device__ float g_Y[(size_t)3 * NB * COUT * PP];                    // 192 MB
__device__ float g_scale[3][COUT];
__device__ float g_shift[3][COUT];
__device__ bf16  g_W[3][COUT * CIN];
__device__ bf16  g_xT[(size_t)NB * PP * CIN];
__device__ bf16  g_Q[(size_t)NB * COUT * PP];
__device__ bf16  g_KT[(size_t)NB * PP * COUT];    // pre-scaled by log2e/sqrt(dh)
__device__ bf16  g_VT[(size_t)NB * PP * COUT];

// ---------------- PTX helpers (baseline PTX only) ----------------------------
__device__ __forceinline__ uint32_t smem_u32(const void* p) {
    uint32_t a;
    asm("{ .reg .u64 t; cvta.to.shared.u64 t, %1; cvt.u32.u64 %0, t; }" : "=r"(a) : "l"(p));
    return a;
}
__device__ __forceinline__ void cp16(uint32_t saddr, const void* g) {
    asm volatile("cp.async.cg.shared.global [%0], [%1], 16;" :: "r"(saddr), "l"(g));
}
#define CP_COMMIT() asm volatile("cp.async.commit_group;" ::: "memory")
template <int N>
__device__ __forceinline__ void cp_wait() {
    asm volatile("cp.async.wait_group %0;" :: "n"(N) : "memory");
}
__device__ __forceinline__ void lma4(uint32_t* r, uint32_t addr) {
    asm volatile("ldmatrix.sync.aligned.m8n8.x4.shared.b16 {%0,%1,%2,%3}, [%4];"
                 : "=r"(r[0]), "=r"(r[1]), "=r"(r[2]), "=r"(r[3]) : "r"(addr));
}
__device__ __forceinline__ void mma16816(float* d, const uint32_t* a, const uint32_t* b) {
    asm volatile("mma.sync.aligned.m16n8k16.row.col.f32.bf16.bf16.f32 "
                 "{%0,%1,%2,%3}, {%4,%5,%6,%7}, {%8,%9}, {%0,%1,%2,%3};"
                 : "+f"(d[0]), "+f"(d[1]), "+f"(d[2]), "+f"(d[3])
                 : "r"(a[0]), "r"(a[1]), "r"(a[2]), "r"(a[3]), "r"(b[0]), "r"(b[1]));
}
__device__ __forceinline__ float ex2f(float x) {
    float y;
    asm("ex2.approx.ftz.f32 %0, %1;" : "=f"(y) : "f"(x));
    return y;
}

// =============================================================================
// Projection GEMM (single-plane bf16, 1 term): 128x128 tile, K-chunks of 32
// =============================================================================
#define ROWB   80
#define MATB   (128 * ROWB)
#define STAGEB (2 * MATB)
#define OFF_A  0
#define OFF_B  MATB
#define SMEM_BYTES (2 * STAGEB)          // 40960

__device__ __forceinline__ void gemm_core(const bf16* __restrict__ Am,
                                          const bf16* __restrict__ Bm,
                                          size_t lda, size_t ldb, int K,
                                          float* __restrict__ C, size_t ldc,
                                          float alpha, int m0, int n0)
{
    extern __shared__ __align__(128) char smem[];
    const uint32_t sb = smem_u32(smem);
    const int tid = threadIdx.x;
    const int L = tid & 31;
    const int w = tid >> 5;
    const int wm = w >> 2, wn = w & 3;

    const int ck0 = tid * 2, ck1 = tid * 2 + 1;
    const int lr0 = ck0 >> 2, lc0 = ck0 & 3;
    const int lr1 = ck1 >> 2, lc1 = ck1 & 3;

    const bf16* pA0 = Am + (size_t)(m0 + lr0) * lda + lc0 * 8;
    const bf16* pA1 = Am + (size_t)(m0 + lr1) * lda + lc1 * 8;
    const bf16* pB0 = Bm + (size_t)(n0 + lr0) * ldb + lc0 * 8;
    const bf16* pB1 = Bm + (size_t)(n0 + lr1) * ldb + lc1 * 8;
    const uint32_t so0 = lr0 * ROWB + lc0 * 16;
    const uint32_t so1 = lr1 * ROWB + lc1 * 16;

    float acc[4][4][4];
#pragma unroll
    for (int mt = 0; mt < 4; mt++)
#pragma unroll
        for (int nt = 0; nt < 4; nt++)
#pragma unroll
            for (int i = 0; i < 4; i++) acc[mt][nt][i] = 0.0f;

    const int nch = K >> 5;
    {
        uint32_t base = sb;
        cp16(base + OFF_A + so0, pA0); cp16(base + OFF_A + so1, pA1);
        cp16(base + OFF_B + so0, pB0); cp16(base + OFF_B + so1, pB1);
        CP_COMMIT();
    }

    const uint32_t a_row = (uint32_t)(wm * 64 + ((L >> 3) & 1) * 8 + (L & 7));
    const uint32_t a_cc  = (uint32_t)(L >> 4);
    const uint32_t b_row = (uint32_t)(wn * 32 + ((L >> 4) << 3) + (L & 7));
    const uint32_t b_cc  = (uint32_t)((L >> 3) & 1);

    for (int ch = 0; ch < nch; ch++) {
        if (ch + 1 < nch) {
            uint32_t base = sb + ((ch + 1) & 1) * STAGEB;
            int kc = (ch + 1) * 32;
            cp16(base + OFF_A + so0, pA0 + kc); cp16(base + OFF_A + so1, pA1 + kc);
            cp16(base + OFF_B + so0, pB0 + kc); cp16(base + OFF_B + so1, pB1 + kc);
            CP_COMMIT();
            cp_wait<1>();
        } else {
            cp_wait<0>();
        }
        __syncthreads();

        uint32_t base = sb + (ch & 1) * STAGEB;
#pragma unroll
        for (int ks = 0; ks < 2; ks++) {
            uint32_t af[4][4], bf[4][2];
            uint32_t acol = (a_cc + ks * 2) * 16;
            uint32_t bcol = (b_cc + ks * 2) * 16;
#pragma unroll
            for (int mt = 0; mt < 4; mt++)
                lma4(af[mt], base + OFF_A + (a_row + mt * 16) * ROWB + acol);
#pragma unroll
            for (int np = 0; np < 2; np++) {
                uint32_t t4[4];
                lma4(t4, base + OFF_B + (b_row + np * 16) * ROWB + bcol);
                bf[2 * np][0] = t4[0]; bf[2 * np][1] = t4[1];
                bf[2 * np + 1][0] = t4[2]; bf[2 * np + 1][1] = t4[3];
            }
#pragma unroll
            for (int mt = 0; mt < 4; mt++)
#pragma unroll
                for (int nt = 0; nt < 4; nt++)
                    mma16816(acc[mt][nt], af[mt], bf[nt]);
        }
        __syncthreads();
    }

    const int tg = L >> 2, tp = L & 3;
#pragma unroll
    for (int mt = 0; mt < 4; mt++) {
        int r0 = m0 + wm * 64 + mt * 16 + tg;
#pragma unroll
        for (int nt = 0; nt < 4; nt++) {
            int c = n0 + wn * 32 + nt * 8 + tp * 2;
            float2 v0 = make_float2(alpha * acc[mt][nt][0], alpha * acc[mt][nt][1]);
            float2 v1 = make_float2(alpha * acc[mt][nt][2], alpha * acc[mt][nt][3]);
            *(float2*)&C[(size_t)r0 * ldc + c]       = v0;
            *(float2*)&C[(size_t)(r0 + 8) * ldc + c] = v1;
        }
    }
}

__global__ __launch_bounds__(256) void proj_gemm(void) {
    int z = blockIdx.z, proj = z >> 3, b = z & 7;
    gemm_core(g_W[proj],
              g_xT + (size_t)b * PP * CIN,
              CIN, CIN, CIN,
              g_Y + (size_t)z * COUT * PP, PP, 1.0f,
              blockIdx.y * 128, blockIdx.x * 128);
}

// =============================================================================
// Fused flash attention — maxless softmax (K pre-scaled by log2e/sqrt(dh)):
//   P = exp2(S'), l accumulated in registers across jt, O = sum P Q, O /= l.
// One CTA per (b, h, i-tile of 128). 8 warps (wm 2 x wn 4).
// =============================================================================
#define APITCH 272                       // 128 bf16 (256B) + 16B pad
#define TILEB  (128 * APITCH)            // 34816 per plane
#define SM_K   0                         // K: 1 plane
#define SM_VQ  TILEB                     // V then Q (1 plane, shared)
#define SM_P   (2 * TILEB)               // P: 1 plane
#define SM_RS  (3 * TILEB)               // row-sum partials: 4 x 128 floats
#define SMEM_ATTN (SM_RS + 2048)         // 106496

__device__ __forceinline__ void load_plane(uint32_t sb, uint32_t off,
                                           const bf16* __restrict__ src,
                                           size_t stride, int tid) {
#pragma unroll
    for (int i = 0; i < 8; i++) {
        int idx = tid + i * 256;
        int r = idx >> 4, cc = idx & 15;
        cp16(sb + off + r * APITCH + cc * 16, src + (size_t)r * stride + cc * 8);
    }
}

__global__ __launch_bounds__(256, 1) void attn_fused(float* __restrict__ out) {
    extern __shared__ __align__(128) char smem[];
    const uint32_t sb = smem_u32(smem);
    const int tid = threadIdx.x;
    const int L = tid & 31, w = tid >> 5;
    const int wm = w >> 2, wn = w & 3;
    const int tg = L >> 2, tp = L & 3;
    const int it = blockIdx.x;
    const int z = blockIdx.y, b = z >> 3, h = z & 7;

    const bf16* Kp = g_KT + ((size_t)b * PP + it * 128) * COUT + h * DH;
    const bf16* Vp = g_VT + (size_t)b * PP * COUT + h * DH;
    const bf16* Qp = g_Q + ((size_t)b * COUT + h * DH) * PP;

    load_plane(sb, SM_K, Kp, COUT, tid);
    CP_COMMIT(); cp_wait<0>(); __syncthreads();

    const uint32_t a_row = (uint32_t)(wm * 64 + ((L >> 3) & 1) * 8 + (L & 7));
    const uint32_t a_cc  = (uint32_t)(L >> 4);
    const uint32_t b_row = (uint32_t)(wn * 32 + ((L >> 4) << 3) + (L & 7));
    const uint32_t b_cc  = (uint32_t)((L >> 3) & 1);

    float oacc[4][4][4];
    float lrow[4][2];
#pragma unroll
    for (int mt = 0; mt < 4; mt++) {
        lrow[mt][0] = lrow[mt][1] = 0.0f;
#pragma unroll
        for (int nt = 0; nt < 4; nt++)
#pragma unroll
            for (int i = 0; i < 4; i++) oacc[mt][nt][i] = 0.0f;
    }

    for (int jt = 0; jt < 16; jt++) {
        // ---- load V_J ----
        load_plane(sb, SM_VQ, Vp + (size_t)jt * 128 * COUT, COUT, tid);
        CP_COMMIT(); cp_wait<0>(); __syncthreads();

        // ---- S' = (cS K_I)^T V_J ----
        float sacc[4][4][4];
#pragma unroll
        for (int mt = 0; mt < 4; mt++)
#pragma unroll
            for (int nt = 0; nt < 4; nt++)
#pragma unroll
                for (int i = 0; i < 4; i++) sacc[mt][nt][i] = 0.0f;

#pragma unroll
        for (int ks = 0; ks < 8; ks++) {
            uint32_t af[4][4], bf[4][2];
            uint32_t acol = (a_cc + ks * 2) * 16;
            uint32_t bcol = (b_cc + ks * 2) * 16;
#pragma unroll
            for (int mt = 0; mt < 4; mt++)
                lma4(af[mt], sb + SM_K + (a_row + mt * 16) * APITCH + acol);
#pragma unroll
            for (int np = 0; np < 2; np++) {
                uint32_t t4[4];
                lma4(t4, sb + SM_VQ + (b_row + np * 16) * APITCH + bcol);
                bf[2 * np][0] = t4[0]; bf[2 * np][1] = t4[1];
                bf[2 * np + 1][0] = t4[2]; bf[2 * np + 1][1] = t4[3];
            }
#pragma unroll
            for (int mt = 0; mt < 4; mt++)
#pragma unroll
                for (int nt = 0; nt < 4; nt++)
                    mma16816(sacc[mt][nt], af[mt], bf[nt]);
        }
        __syncthreads();                 // V reads done; buffer reusable

        // prefetch Q_J into the V buffer (overlaps exp math)
        load_plane(sb, SM_VQ, Qp + (size_t)jt * 128, PP, tid);
        CP_COMMIT();

        // ---- maxless softmax numerator: p = exp2(s'), accumulate row sums ----
#pragma unroll
        for (int mt = 0; mt < 4; mt++) {
#pragma unroll
            for (int half = 0; half < 2; half++) {
                int r = wm * 64 + mt * 16 + tg + half * 8;
                float rs = 0.0f;
#pragma unroll
                for (int nt = 0; nt < 4; nt++) {
                    float p0 = ex2f(sacc[mt][nt][2 * half]);
                    float p1 = ex2f(sacc[mt][nt][2 * half + 1]);
                    rs += p0 + p1;
                    uint32_t col = wn * 32 + nt * 8 + 2 * tp;
                    *(__nv_bfloat162*)(smem + SM_P + r * APITCH + col * 2) =
                        __halves2bfloat162(__float2bfloat16(p0), __float2bfloat16(p1));
                }
                lrow[mt][half] += rs;    // thread-local partial (8 of 128 cols)
            }
        }
        cp_wait<0>();
        __syncthreads();                 // P visible, Q loaded

        // ---- O += P Q ----
#pragma unroll
        for (int ks = 0; ks < 8; ks++) {
            uint32_t af[4][4], bf[4][2];
            uint32_t acol = (a_cc + ks * 2) * 16;
            uint32_t bcol = (b_cc + ks * 2) * 16;
#pragma unroll
            for (int mt = 0; mt < 4; mt++)
                lma4(af[mt], sb + SM_P + (a_row + mt * 16) * APITCH + acol);
#pragma unroll
            for (int np = 0; np < 2; np++) {
                uint32_t t4[4];
                lma4(t4, sb + SM_VQ + (b_row + np * 16) * APITCH + bcol);
                bf[2 * np][0] = t4[0]; bf[2 * np][1] = t4[1];
                bf[2 * np + 1][0] = t4[2]; bf[2 * np + 1][1] = t4[3];
            }
#pragma unroll
            for (int mt = 0; mt < 4; mt++)
#pragma unroll
                for (int nt = 0; nt < 4; nt++)
                    mma16816(oacc[mt][nt], af[mt], bf[nt]);
        }
        __syncthreads();                 // Q/P buffers free for next iteration
    }

    // ---- one-time row-sum reduction: quad lanes then across wn warps ----
#pragma unroll
    for (int mt = 0; mt < 4; mt++) {
#pragma unroll
        for (int half = 0; half < 2; half++) {
            float l = lrow[mt][half];
            l += __shfl_xor_sync(0xffffffffu, l, 1);
            l += __shfl_xor_sync(0xffffffffu, l, 2);
            lrow[mt][half] = l;
            if (tp == 0) {
                int r = wm * 64 + mt * 16 + tg + half * 8;
                *(float*)(smem + SM_RS + (wn * 128 + r) * 4) = l;
            }
        }
    }
    __syncthreads();
#pragma unroll
    for (int mt = 0; mt < 4; mt++) {
#pragma unroll
        for (int half = 0; half < 2; half++) {
            int r = wm * 64 + mt * 16 + tg + half * 8;
            lrow[mt][half] = *(float*)(smem + SM_RS + r * 4)
                           + *(float*)(smem + SM_RS + (128 + r) * 4)
                           + *(float*)(smem + SM_RS + (256 + r) * 4)
                           + *(float*)(smem + SM_RS + (384 + r) * 4);
        }
    }
    __syncthreads();

    // ---- normalize by 1/l and transpose O[i][c] -> out[c][i] via SMEM ----
    float* fbuf = (float*)smem;          // 128 x 132 floats
#pragma unroll
    for (int mt = 0; mt < 4; mt++) {
#pragma unroll
        for (int half = 0; half < 2; half++) {
            int r = wm * 64 + mt * 16 + tg + half * 8;
            float inv = 1.0f / lrow[mt][half];
#pragma unroll
            for (int nt = 0; nt < 4; nt++) {
                int c = wn * 32 + nt * 8 + 2 * tp;
                fbuf[(size_t)c * 132 + r]       = oacc[mt][nt][2 * half] * inv;
                fbuf[(size_t)(c + 1) * 132 + r] = oacc[mt][nt][2 * half + 1] * inv;
            }
        }
    }
    __syncthreads();
    const size_t obase = ((size_t)b * COUT + h * DH) * PP + (size_t)it * 128;
#pragma unroll
    for (int rr = 0; rr < 16; rr++) {
        int r = w * 16 + rr;
        float4 v = *(float4*)&fbuf[(size_t)r * 132 + L * 4];
        *(float4*)&out[obase + (size_t)r * PP + L * 4] = v;
    }
}

// ---------------- conversions ------------------------------------------------
__global__ __launch_bounds__(256) void convert_w(const float* __restrict__ Wq,
                                                 const float* __restrict__ Wk,
                                                 const float* __restrict__ Wv) {
    int proj = blockIdx.z;
    const float* W = (proj == 0) ? Wq : ((proj == 1) ? Wk : Wv);
    size_t e = ((size_t)blockIdx.x * 256 + threadIdx.x) * 4;
    float4 v = *(const float4*)(W + e);
    ((__nv_bfloat162*)&g_W[proj][e])[0] =
        __halves2bfloat162(__float2bfloat16(v.x), __float2bfloat16(v.y));
    ((__nv_bfloat162*)&g_W[proj][e])[1] =
        __halves2bfloat162(__float2bfloat16(v.z), __float2bfloat16(v.w));
}

__global__ __launch_bounds__(256) void transpose_x(const float* __restrict__ x) {
    __shared__ float t[32][33];
    int b = blockIdx.z;
    int p0 = blockIdx.x * 32, c0 = blockIdx.y * 32;
    int tx = threadIdx.x & 31, ty = threadIdx.x >> 5;
#pragma unroll
    for (int j = 0; j < 4; j++)
        t[ty + 8 * j][tx] = x[((size_t)b * CIN + c0 + ty + 8 * j) * PP + p0 + tx];
    __syncthreads();
#pragma unroll
    for (int j = 0; j < 4; j++) {
        float v = t[tx][ty + 8 * j];
        size_t o = ((size_t)b * PP + p0 + ty + 8 * j) * CIN + c0 + tx;
        g_xT[o] = __float2bfloat16(v);
    }
}

// ---------------- BN stats ---------------------------------------------------
__global__ __launch_bounds__(256) void stats_kernel(const float* __restrict__ gq,
                                                    const float* __restrict__ bq,
                                                    const float* __restrict__ gk,
                                                    const float* __restrict__ bk,
                                                    const float* __restrict__ gv,
                                                    const float* __restrict__ bv) {
    int ch = blockIdx.x & (COUT - 1);
    int proj = blockIdx.x >> 10;
    const float* base = g_Y + ((size_t)proj * NB) * COUT * PP + (size_t)ch * PP;
    float s = 0.0f, sq = 0.0f;
    for (int b = 0; b < NB; b++) {
        const float* p = base + (size_t)b * COUT * PP;
        for (int i = threadIdx.x; i < PP; i += 256) {
            float v = p[i]; s += v; sq += v * v;
        }
    }
#pragma unroll
    for (int o = 16; o; o >>= 1) {
        s  += __shfl_xor_sync(0xffffffffu, s, o);
        sq += __shfl_xor_sync(0xffffffffu, sq, o);
    }
    __shared__ float rs[8], rq[8];
    if ((threadIdx.x & 31) == 0) { rs[threadIdx.x >> 5] = s; rq[threadIdx.x >> 5] = sq; }
    __syncthreads();
    if (threadIdx.x == 0) {
        float S = 0.0f, Q = 0.0f;
#pragma unroll
        for (int w = 0; w < 8; w++) { S += rs[w]; Q += rq[w]; }
        const float inv_n = 1.0f / (float)(NB * PP);
        float mean = S * inv_n;
        float var  = Q * inv_n - mean * mean;
        const float* g  = (proj == 0) ? gq : ((proj == 1) ? gk : gv);
        const float* bb = (proj == 0) ? bq : ((proj == 1) ? bk : bv);
        float sc = g[ch] * rsqrtf(var + 1e-5f);
        g_scale[proj][ch] = sc;
        g_shift[proj][ch] = bb[ch] - mean * sc;
    }
}

// ---------------- BN apply: Q path (keep [c][p] layout, single bf16) ---------
__global__ __launch_bounds__(256) void bn_apply_q(void) {
    size_t e = ((size_t)blockIdx.x * 256 + threadIdx.x) * 4;
    int ch = (int)((e >> 11) & (COUT - 1));
    float sc = g_scale[0][ch], sh = g_shift[0][ch];
    float4 y = *(float4*)&g_Y[e];
    y.x = sc * y.x + sh; y.x = (y.x < 0.0f) ? 0.1f * y.x : y.x;
    y.y = sc * y.y + sh; y.y = (y.y < 0.0f) ? 0.1f * y.y : y.y;
    y.z = sc * y.z + sh; y.z = (y.z < 0.0f) ? 0.1f * y.z : y.z;
    y.w = sc * y.w + sh; y.w = (y.w < 0.0f) ? 0.1f * y.w : y.w;
    ((__nv_bfloat162*)&g_Q[e])[0] = __halves2bfloat162(__float2bfloat16(y.x), __float2bfloat16(y.y));
    ((__nv_bfloat162*)&g_Q[e])[1] = __halves2bfloat162(__float2bfloat16(y.z), __float2bfloat16(y.w));
}

// ---------------- BN apply + transpose: K/V ([c][p] -> [p][c], bf16) ---------
// K additionally pre-scaled by cS = log2e / sqrt(dh) (folded softmax scale)
__global__ __launch_bounds__(256) void bn_apply_t(void) {
    __shared__ float t[32][33];
    int z = blockIdx.z;
    int proj = 1 + (z >> 3), b = z & 7;
    int p0 = blockIdx.x * 32, c0 = blockIdx.y * 32;
    int tx = threadIdx.x & 31, ty = threadIdx.x >> 5;
    const float cS = (proj == 1) ? (1.4426950408889634f * 0.08838834764831845f) : 1.0f;
#pragma unroll
    for (int j = 0; j < 4; j++) {
        int c = c0 + ty + 8 * j;
        float sc = g_scale[proj][c], sh = g_shift[proj][c];
        float v = g_Y[(((size_t)proj * NB + b) * COUT + c) * PP + p0 + tx];
        v = sc * v + sh;
        v = (v < 0.0f) ? 0.1f * v : v;
        t[ty + 8 * j][tx] = v * cS;
    }
    __syncthreads();
    bf16* T = (proj == 1) ? g_KT : g_VT;
#pragma unroll
    for (int j = 0; j < 4; j++) {
        float v = t[tx][ty + 8 * j];
        size_t o = ((size_t)b * PP + p0 + ty + 8 * j) * COUT + c0 + tx;
        T[o] = __float2bfloat16(v);
    }
}

// ---------------- launch -----------------------------------------------------
extern "C" void kernel_launch(void* const* d_in, const int* in_sizes, int n_in,
                              void* d_out, int out_size)
{
    (void)in_sizes; (void)n_in; (void)out_size;
    const float* x  = (const float*)d_in[0];
    const float* Wq = (const float*)d_in[1];
    const float* gq = (const float*)d_in[2];
    const float* bq = (const float*)d_in[3];
    const float* Wk = (const float*)d_in[4];
    const float* gk = (const float*)d_in[5];
    const float* bk = (const float*)d_in[6];
    const float* Wv = (const float*)d_in[7];
    const float* gv = (const float*)d_in[8];
    const float* bv = (const float*)d_in[9];
    float* out = (float*)d_out;

    cudaFuncSetAttribute(proj_gemm,  cudaFuncAttributeMaxDynamicSharedMemorySize, SMEM_BYTES);
    cudaFuncSetAttribute(attn_fused, cudaFuncAttributeMaxDynamicSharedMemorySize, SMEM_ATTN);

    // 1) input conversions: W -> bf16, x -> x^T bf16
    convert_w<<<dim3(COUT * CIN / 4 / 256, 1, 3), 256>>>(Wq, Wk, Wv);
    transpose_x<<<dim3(PP / 32, CIN / 32, NB), 256>>>(x);
    // 2) Y = W x (bf16 1-term)
    proj_gemm<<<dim3(PP / 128, COUT / 128, 24), 256, SMEM_BYTES>>>();
    // 3) BN stats
    stats_kernel<<<3 * COUT, 256>>>(gq, bq, gk, bk, gv, bv);
    // 4) BN + LeakyReLU, emit Q / K^T (cS-scaled) / V^T single bf16
    bn_apply_q<<<(unsigned)((size_t)NB * COUT * PP / 4 / 256), 256>>>();
    bn_apply_t<<<dim3(PP / 32, COUT / 32, 16), 256>>>();
    // 5) fused S -> maxless softmax -> O
    attn_fused<<<dim3(16, 64), 256, SMEM_ATTN>>>(out);
}

// round 11
// speedup vs baseline: 2.3696x; 1.0599x over previous
#include <cuda_runtime.h>
#include <cuda_bf16.h>
#include <cstdint>

#define NB   8
#define CIN  512
#define COUT 1024
#define PP   2048
#define NH   8
#define DH   128

typedef __nv_bfloat16 bf16;

// ---------------- device scratch (static: no allocation allowed) -------------
__device__ bf16  g_Yb[(size_t)3 * NB * COUT * PP];                   // 96 MB
__device__ float g_ps[(size_t)24 * 8 * 16 * 256];                    // 3 MB partials
__device__ float g_scale[3][COUT];
__device__ float g_shift[3][COUT];
__device__ bf16  g_W[3][COUT * CIN];
__device__ bf16  g_xT[(size_t)NB * PP * CIN];
__device__ bf16  g_Q[(size_t)NB * COUT * PP];
__device__ bf16  g_KT[(size_t)NB * PP * COUT];    // pre-scaled by log2e/sqrt(dh)
__device__ bf16  g_VT[(size_t)NB * PP * COUT];

// ---------------- PTX helpers (baseline PTX only) ----------------------------
__device__ __forceinline__ uint32_t smem_u32(const void* p) {
    uint32_t a;
    asm("{ .reg .u64 t; cvta.to.shared.u64 t, %1; cvt.u32.u64 %0, t; }" : "=r"(a) : "l"(p));
    return a;
}
__device__ __forceinline__ void cp16(uint32_t saddr, const void* g) {
    asm volatile("cp.async.cg.shared.global [%0], [%1], 16;" :: "r"(saddr), "l"(g));
}
#define CP_COMMIT() asm volatile("cp.async.commit_group;" ::: "memory")
template <int N>
__device__ __forceinline__ void cp_wait() {
    asm volatile("cp.async.wait_group %0;" :: "n"(N) : "memory");
}
__device__ __forceinline__ void lma4(uint32_t* r, uint32_t addr) {
    asm volatile("ldmatrix.sync.aligned.m8n8.x4.shared.b16 {%0,%1,%2,%3}, [%4];"
                 : "=r"(r[0]), "=r"(r[1]), "=r"(r[2]), "=r"(r[3]) : "r"(addr));
}
__device__ __forceinline__ void mma16816(float* d, const uint32_t* a, const uint32_t* b) {
    asm volatile("mma.sync.aligned.m16n8k16.row.col.f32.bf16.bf16.f32 "
                 "{%0,%1,%2,%3}, {%4,%5,%6,%7}, {%8,%9}, {%0,%1,%2,%3};"
                 : "+f"(d[0]), "+f"(d[1]), "+f"(d[2]), "+f"(d[3])
                 : "r"(a[0]), "r"(a[1]), "r"(a[2]), "r"(a[3]), "r"(b[0]), "r"(b[1]));
}
__device__ __forceinline__ float ex2f(float x) {
    float y;
    asm("ex2.approx.ftz.f32 %0, %1;" : "=f"(y) : "f"(x));
    return y;
}

// =============================================================================
// Projection GEMM (single-plane bf16, 1 term) + fused BN partial stats.
// 128x128 tile, K-chunks of 32. Writes Y as bf16 + per-CTA channel sums.
// =============================================================================
#define ROWB   80
#define MATB   (128 * ROWB)
#define STAGEB (2 * MATB)
#define OFF_A  0
#define OFF_B  MATB
#define SMEM_BYTES (2 * STAGEB)          // 40960 (also holds 4x128x2 partials)

__global__ __launch_bounds__(256) void proj_gemm(void) {
    extern __shared__ __align__(128) char smem[];
    const uint32_t sb = smem_u32(smem);
    const int tid = threadIdx.x;
    const int L = tid & 31;
    const int w = tid >> 5;
    const int wm = w >> 2, wn = w & 3;
    const int z = blockIdx.z;             // proj*8 + b
    const int m0 = blockIdx.y * 128, n0 = blockIdx.x * 128;

    const bf16* Am = g_W[z >> 3];
    const bf16* Bm = g_xT + (size_t)(z & 7) * PP * CIN;
    bf16* C = g_Yb + (size_t)z * COUT * PP;

    const int ck0 = tid * 2, ck1 = tid * 2 + 1;
    const int lr0 = ck0 >> 2, lc0 = ck0 & 3;
    const int lr1 = ck1 >> 2, lc1 = ck1 & 3;

    const bf16* pA0 = Am + (size_t)(m0 + lr0) * CIN + lc0 * 8;
    const bf16* pA1 = Am + (size_t)(m0 + lr1) * CIN + lc1 * 8;
    const bf16* pB0 = Bm + (size_t)(n0 + lr0) * CIN + lc0 * 8;
    const bf16* pB1 = Bm + (size_t)(n0 + lr1) * CIN + lc1 * 8;
    const uint32_t so0 = lr0 * ROWB + lc0 * 16;
    const uint32_t so1 = lr1 * ROWB + lc1 * 16;

    float acc[4][4][4];
#pragma unroll
    for (int mt = 0; mt < 4; mt++)
#pragma unroll
        for (int nt = 0; nt < 4; nt++)
#pragma unroll
            for (int i = 0; i < 4; i++) acc[mt][nt][i] = 0.0f;

    const int nch = CIN >> 5;
    {
        uint32_t base = sb;
        cp16(base + OFF_A + so0, pA0); cp16(base + OFF_A + so1, pA1);
        cp16(base + OFF_B + so0, pB0); cp16(base + OFF_B + so1, pB1);
        CP_COMMIT();
    }

    const uint32_t a_row = (uint32_t)(wm * 64 + ((L >> 3) & 1) * 8 + (L & 7));
    const uint32_t a_cc  = (uint32_t)(L >> 4);
    const uint32_t b_row = (uint32_t)(wn * 32 + ((L >> 4) << 3) + (L & 7));
    const uint32_t b_cc  = (uint32_t)((L >> 3) & 1);

    for (int ch = 0; ch < nch; ch++) {
        if (ch + 1 < nch) {
            uint32_t base = sb + ((ch + 1) & 1) * STAGEB;
            int kc = (ch + 1) * 32;
            cp16(base + OFF_A + so0, pA0 + kc); cp16(base + OFF_A + so1, pA1 + kc);
            cp16(base + OFF_B + so0, pB0 + kc); cp16(base + OFF_B + so1, pB1 + kc);
            CP_COMMIT();
            cp_wait<1>();
        } else {
            cp_wait<0>();
        }
        __syncthreads();

        uint32_t base = sb + (ch & 1) * STAGEB;
#pragma unroll
        for (int ks = 0; ks < 2; ks++) {
            uint32_t af[4][4], bf[4][2];
            uint32_t acol = (a_cc + ks * 2) * 16;
            uint32_t bcol = (b_cc + ks * 2) * 16;
#pragma unroll
            for (int mt = 0; mt < 4; mt++)
                lma4(af[mt], base + OFF_A + (a_row + mt * 16) * ROWB + acol);
#pragma unroll
            for (int np = 0; np < 2; np++) {
                uint32_t t4[4];
                lma4(t4, base + OFF_B + (b_row + np * 16) * ROWB + bcol);
                bf[2 * np][0] = t4[0]; bf[2 * np][1] = t4[1];
                bf[2 * np + 1][0] = t4[2]; bf[2 * np + 1][1] = t4[3];
            }
#pragma unroll
            for (int mt = 0; mt < 4; mt++)
#pragma unroll
                for (int nt = 0; nt < 4; nt++)
                    mma16816(acc[mt][nt], af[mt], bf[nt]);
        }
        __syncthreads();
    }

    // ---- epilogue: bf16 store + per-channel partial (sum, sumsq) ----
    const int tg = L >> 2, tp = L & 3;
#pragma unroll
    for (int mt = 0; mt < 4; mt++) {
        int r0 = m0 + wm * 64 + mt * 16 + tg;
#pragma unroll
        for (int nt = 0; nt < 4; nt++) {
            int c = n0 + wn * 32 + nt * 8 + tp * 2;
            *(__nv_bfloat162*)&C[(size_t)r0 * PP + c] =
                __halves2bfloat162(__float2bfloat16(acc[mt][nt][0]), __float2bfloat16(acc[mt][nt][1]));
            *(__nv_bfloat162*)&C[(size_t)(r0 + 8) * PP + c] =
                __halves2bfloat162(__float2bfloat16(acc[mt][nt][2]), __float2bfloat16(acc[mt][nt][3]));
        }
    }

    float* sp = (float*)smem;            // [4 wn][128 r][2] = 4 KB (stages done)
#pragma unroll
    for (int mt = 0; mt < 4; mt++) {
#pragma unroll
        for (int half = 0; half < 2; half++) {
            float s = 0.0f, q = 0.0f;
#pragma unroll
            for (int nt = 0; nt < 4; nt++) {
                float a = acc[mt][nt][2 * half], bq = acc[mt][nt][2 * half + 1];
                s += a + bq;
                q += a * a + bq * bq;
            }
            s += __shfl_xor_sync(0xffffffffu, s, 1);
            s += __shfl_xor_sync(0xffffffffu, s, 2);
            q += __shfl_xor_sync(0xffffffffu, q, 1);
            q += __shfl_xor_sync(0xffffffffu, q, 2);
            if (tp == 0) {
                int r = wm * 64 + mt * 16 + tg + 8 * half;
                sp[(wn * 128 + r) * 2]     = s;
                sp[(wn * 128 + r) * 2 + 1] = q;
            }
        }
    }
    __syncthreads();
    if (tid < 128) {
        float s = sp[tid * 2]             + sp[(128 + tid) * 2]
                + sp[(256 + tid) * 2]     + sp[(384 + tid) * 2];
        float q = sp[tid * 2 + 1]         + sp[(128 + tid) * 2 + 1]
                + sp[(256 + tid) * 2 + 1] + sp[(384 + tid) * 2 + 1];
        size_t o = (((size_t)z * 8 + blockIdx.y) * 16 + blockIdx.x) * 256 + tid * 2;
        g_ps[o] = s;
        g_ps[o + 1] = q;
    }
}

// ---------------- stats finalize: reduce 128 partials per channel ------------
__global__ __launch_bounds__(32) void stats_reduce(const float* __restrict__ gq,
                                                   const float* __restrict__ bq,
                                                   const float* __restrict__ gk,
                                                   const float* __restrict__ bk,
                                                   const float* __restrict__ gv,
                                                   const float* __restrict__ bv) {
    int proj = blockIdx.x >> 10;
    int chn  = blockIdx.x & 1023;
    int my   = chn >> 7, row = chn & 127;
    float s = 0.0f, q = 0.0f;
    for (int i = threadIdx.x; i < 128; i += 32) {
        int b = i >> 4, nx = i & 15;
        size_t o = (((size_t)(proj * 8 + b) * 8 + my) * 16 + nx) * 256 + row * 2;
        s += g_ps[o]; q += g_ps[o + 1];
    }
#pragma unroll
    for (int o = 16; o; o >>= 1) {
        s += __shfl_xor_sync(0xffffffffu, s, o);
        q += __shfl_xor_sync(0xffffffffu, q, o);
    }
    if (threadIdx.x == 0) {
        const float inv_n = 1.0f / (float)(NB * PP);
        float mean = s * inv_n;
        float var  = q * inv_n - mean * mean;
        const float* g  = (proj == 0) ? gq : ((proj == 1) ? gk : gv);
        const float* bb = (proj == 0) ? bq : ((proj == 1) ? bk : bv);
        float sc = g[chn] * rsqrtf(var + 1e-5f);
        float sh = bb[chn] - mean * sc;
        if (proj == 1) {                 // fold cS = log2e/sqrt(dh) into K path
            const float cS = 1.4426950408889634f * 0.08838834764831845f;
            sc *= cS; sh *= cS;
        }
        g_scale[proj][chn] = sc;
        g_shift[proj][chn] = sh;
    }
}

// =============================================================================
// Fused flash attention — identical to round 9 (maxless softmax, K pre-scaled)
// =============================================================================
#define APITCH 272
#define TILEB  (128 * APITCH)
#define SM_K   0
#define SM_VQ  TILEB
#define SM_P   (2 * TILEB)
#define SM_RS  (3 * TILEB)
#define SMEM_ATTN (SM_RS + 2048)         // 106496 -> 2 CTAs/SM

__device__ __forceinline__ void load_plane(uint32_t sb, uint32_t off,
                                           const bf16* __restrict__ src,
                                           size_t stride, int tid) {
#pragma unroll
    for (int i = 0; i < 8; i++) {
        int idx = tid + i * 256;
        int r = idx >> 4, cc = idx & 15;
        cp16(sb + off + r * APITCH + cc * 16, src + (size_t)r * stride + cc * 8);
    }
}

__global__ __launch_bounds__(256, 1) void attn_fused(float* __restrict__ out) {
    extern __shared__ __align__(128) char smem[];
    const uint32_t sb = smem_u32(smem);
    const int tid = threadIdx.x;
    const int L = tid & 31, w = tid >> 5;
    const int wm = w >> 2, wn = w & 3;
    const int tg = L >> 2, tp = L & 3;
    const int it = blockIdx.x;
    const int z = blockIdx.y, b = z >> 3, h = z & 7;

    const bf16* Kp = g_KT + ((size_t)b * PP + it * 128) * COUT + h * DH;
    const bf16* Vp = g_VT + (size_t)b * PP * COUT + h * DH;
    const bf16* Qp = g_Q + ((size_t)b * COUT + h * DH) * PP;

    load_plane(sb, SM_K, Kp, COUT, tid);
    CP_COMMIT(); cp_wait<0>(); __syncthreads();

    const uint32_t a_row = (uint32_t)(wm * 64 + ((L >> 3) & 1) * 8 + (L & 7));
    const uint32_t a_cc  = (uint32_t)(L >> 4);
    const uint32_t b_row = (uint32_t)(wn * 32 + ((L >> 4) << 3) + (L & 7));
    const uint32_t b_cc  = (uint32_t)((L >> 3) & 1);

    float oacc[4][4][4];
    float lrow[4][2];
#pragma unroll
    for (int mt = 0; mt < 4; mt++) {
        lrow[mt][0] = lrow[mt][1] = 0.0f;
#pragma unroll
        for (int nt = 0; nt < 4; nt++)
#pragma unroll
            for (int i = 0; i < 4; i++) oacc[mt][nt][i] = 0.0f;
    }

    for (int jt = 0; jt < 16; jt++) {
        load_plane(sb, SM_VQ, Vp + (size_t)jt * 128 * COUT, COUT, tid);
        CP_COMMIT(); cp_wait<0>(); __syncthreads();

        float sacc[4][4][4];
#pragma unroll
        for (int mt = 0; mt < 4; mt++)
#pragma unroll
            for (int nt = 0; nt < 4; nt++)
#pragma unroll
                for (int i = 0; i < 4; i++) sacc[mt][nt][i] = 0.0f;

#pragma unroll
        for (int ks = 0; ks < 8; ks++) {
            uint32_t af[4][4], bf[4][2];
            uint32_t acol = (a_cc + ks * 2) * 16;
            uint32_t bcol = (b_cc + ks * 2) * 16;
#pragma unroll
            for (int mt = 0; mt < 4; mt++)
                lma4(af[mt], sb + SM_K + (a_row + mt * 16) * APITCH + acol);
#pragma unroll
            for (int np = 0; np < 2; np++) {
                uint32_t t4[4];
                lma4(t4, sb + SM_VQ + (b_row + np * 16) * APITCH + bcol);
                bf[2 * np][0] = t4[0]; bf[2 * np][1] = t4[1];
                bf[2 * np + 1][0] = t4[2]; bf[2 * np + 1][1] = t4[3];
            }
#pragma unroll
            for (int mt = 0; mt < 4; mt++)
#pragma unroll
                for (int nt = 0; nt < 4; nt++)
                    mma16816(sacc[mt][nt], af[mt], bf[nt]);
        }
        __syncthreads();

        load_plane(sb, SM_VQ, Qp + (size_t)jt * 128, PP, tid);
        CP_COMMIT();

#pragma unroll
        for (int mt = 0; mt < 4; mt++) {
#pragma unroll
            for (int half = 0; half < 2; half++) {
                int r = wm * 64 + mt * 16 + tg + half * 8;
                float rs = 0.0f;
#pragma unroll
                for (int nt = 0; nt < 4; nt++) {
                    float p0 = ex2f(sacc[mt][nt][2 * half]);
                    float p1 = ex2f(sacc[mt][nt][2 * half + 1]);
                    rs += p0 + p1;
                    uint32_t col = wn * 32 + nt * 8 + 2 * tp;
                    *(__nv_bfloat162*)(smem + SM_P + r * APITCH + col * 2) =
                        __halves2bfloat162(__float2bfloat16(p0), __float2bfloat16(p1));
                }
                lrow[mt][half] += rs;
            }
        }
        cp_wait<0>();
        __syncthreads();

#pragma unroll
        for (int ks = 0; ks < 8; ks++) {
            uint32_t af[4][4], bf[4][2];
            uint32_t acol = (a_cc + ks * 2) * 16;
            uint32_t bcol = (b_cc + ks * 2) * 16;
#pragma unroll
            for (int mt = 0; mt < 4; mt++)
                lma4(af[mt], sb + SM_P + (a_row + mt * 16) * APITCH + acol);
#pragma unroll
            for (int np = 0; np < 2; np++) {
                uint32_t t4[4];
                lma4(t4, sb + SM_VQ + (b_row + np * 16) * APITCH + bcol);
                bf[2 * np][0] = t4[0]; bf[2 * np][1] = t4[1];
                bf[2 * np + 1][0] = t4[2]; bf[2 * np + 1][1] = t4[3];
            }
#pragma unroll
            for (int mt = 0; mt < 4; mt++)
#pragma unroll
                for (int nt = 0; nt < 4; nt++)
                    mma16816(oacc[mt][nt], af[mt], bf[nt]);
        }
        __syncthreads();
    }

    // ---- one-time row-sum reduction ----
#pragma unroll
    for (int mt = 0; mt < 4; mt++) {
#pragma unroll
        for (int half = 0; half < 2; half++) {
            float l = lrow[mt][half];
            l += __shfl_xor_sync(0xffffffffu, l, 1);
            l += __shfl_xor_sync(0xffffffffu, l, 2);
            lrow[mt][half] = l;
            if (tp == 0) {
                int r = wm * 64 + mt * 16 + tg + half * 8;
                *(float*)(smem + SM_RS + (wn * 128 + r) * 4) = l;
            }
        }
    }
    __syncthreads();
#pragma unroll
    for (int mt = 0; mt < 4; mt++) {
#pragma unroll
        for (int half = 0; half < 2; half++) {
            int r = wm * 64 + mt * 16 + tg + half * 8;
            lrow[mt][half] = *(float*)(smem + SM_RS + r * 4)
                           + *(float*)(smem + SM_RS + (128 + r) * 4)
                           + *(float*)(smem + SM_RS + (256 + r) * 4)
                           + *(float*)(smem + SM_RS + (384 + r) * 4);
        }
    }
    __syncthreads();

    // ---- normalize + transpose via SMEM ----
    float* fbuf = (float*)smem;
#pragma unroll
    for (int mt = 0; mt < 4; mt++) {
#pragma unroll
        for (int half = 0; half < 2; half++) {
            int r = wm * 64 + mt * 16 + tg + half * 8;
            float inv = 1.0f / lrow[mt][half];
#pragma unroll
            for (int nt = 0; nt < 4; nt++) {
                int c = wn * 32 + nt * 8 + 2 * tp;
                fbuf[(size_t)c * 132 + r]       = oacc[mt][nt][2 * half] * inv;
                fbuf[(size_t)(c + 1) * 132 + r] = oacc[mt][nt][2 * half + 1] * inv;
            }
        }
    }
    __syncthreads();
    const size_t obase = ((size_t)b * COUT + h * DH) * PP + (size_t)it * 128;
#pragma unroll
    for (int rr = 0; rr < 16; rr++) {
        int r = w * 16 + rr;
        float4 v = *(float4*)&fbuf[(size_t)r * 132 + L * 4];
        *(float4*)&out[obase + (size_t)r * PP + L * 4] = v;
    }
}

// ---------------- conversions ------------------------------------------------
__global__ __launch_bounds__(256) void convert_w(const float* __restrict__ Wq,
                                                 const float* __restrict__ Wk,
                                                 const float* __restrict__ Wv) {
    int proj = blockIdx.z;
    const float* W = (proj == 0) ? Wq : ((proj == 1) ? Wk : Wv);
    size_t e = ((size_t)blockIdx.x * 256 + threadIdx.x) * 4;
    float4 v = *(const float4*)(W + e);
    ((__nv_bfloat162*)&g_W[proj][e])[0] =
        __halves2bfloat162(__float2bfloat16(v.x), __float2bfloat16(v.y));
    ((__nv_bfloat162*)&g_W[proj][e])[1] =
        __halves2bfloat162(__float2bfloat16(v.z), __float2bfloat16(v.w));
}

__global__ __launch_bounds__(256) void transpose_x(const float* __restrict__ x) {
    __shared__ float t[32][33];
    int b = blockIdx.z;
    int p0 = blockIdx.x * 32, c0 = blockIdx.y * 32;
    int tx = threadIdx.x & 31, ty = threadIdx.x >> 5;
#pragma unroll
    for (int j = 0; j < 4; j++)
        t[ty + 8 * j][tx] = x[((size_t)b * CIN + c0 + ty + 8 * j) * PP + p0 + tx];
    __syncthreads();
#pragma unroll
    for (int j = 0; j < 4; j++) {
        float v = t[tx][ty + 8 * j];
        size_t o = ((size_t)b * PP + p0 + ty + 8 * j) * CIN + c0 + tx;
        g_xT[o] = __float2bfloat16(v);
    }
}

// ---------------- BN apply: Q path (bf16 in, bf16 out, 8 elems/thread) -------
__global__ __launch_bounds__(256) void bn_apply_q(void) {
    size_t e = ((size_t)blockIdx.x * 256 + threadIdx.x) * 8;
    int ch = (int)((e >> 11) & (COUT - 1));
    float sc = g_scale[0][ch], sh = g_shift[0][ch];
    uint4 raw = *(uint4*)&g_Yb[e];
    uint32_t rw[4] = {raw.x, raw.y, raw.z, raw.w};
    uint32_t outp[4];
#pragma unroll
    for (int i = 0; i < 4; i++) {
        __nv_bfloat162 pv = *(__nv_bfloat162*)&rw[i];
        float a = __bfloat162float(__low2bfloat16(pv));
        float c = __bfloat162float(__high2bfloat16(pv));
        a = sc * a + sh; a = (a < 0.0f) ? 0.1f * a : a;
        c = sc * c + sh; c = (c < 0.0f) ? 0.1f * c : c;
        __nv_bfloat162 ov = __halves2bfloat162(__float2bfloat16(a), __float2bfloat16(c));
        outp[i] = *(uint32_t*)&ov;
    }
    *(uint4*)&g_Q[e] = make_uint4(outp[0], outp[1], outp[2], outp[3]);
}

// ---------------- BN apply + transpose: K/V (bf16 Y -> bf16 [p][c]) ----------
// K's cS scale is pre-folded into g_scale/g_shift[1].
__global__ __launch_bounds__(256) void bn_apply_t(void) {
    __shared__ float t[32][33];
    int z = blockIdx.z;
    int proj = 1 + (z >> 3), b = z & 7;
    int p0 = blockIdx.x * 32, c0 = blockIdx.y * 32;
    int tx = threadIdx.x & 31, ty = threadIdx.x >> 5;
#pragma unroll
    for (int j = 0; j < 4; j++) {
        int c = c0 + ty + 8 * j;
        float sc = g_scale[proj][c], sh = g_shift[proj][c];
        float v = __bfloat162float(
            g_Yb[(((size_t)proj * NB + b) * COUT + c) * PP + p0 + tx]);
        v = sc * v + sh;
        v = (v < 0.0f) ? 0.1f * v : v;
        t[ty + 8 * j][tx] = v;
    }
    __syncthreads();
    bf16* T = (proj == 1) ? g_KT : g_VT;
#pragma unroll
    for (int j = 0; j < 4; j++) {
        float v = t[tx][ty + 8 * j];
        size_t o = ((size_t)b * PP + p0 + ty + 8 * j) * COUT + c0 + tx;
        T[o] = __float2bfloat16(v);
    }
}

// ---------------- launch -----------------------------------------------------
extern "C" void kernel_launch(void* const* d_in, const int* in_sizes, int n_in,
                              void* d_out, int out_size)
{
    (void)in_sizes; (void)n_in; (void)out_size;
    const float* x  = (const float*)d_in[0];
    const float* Wq = (const float*)d_in[1];
    const float* gq = (const float*)d_in[2];
    const float* bq = (const float*)d_in[3];
    const float* Wk = (const float*)d_in[4];
    const float* gk = (const float*)d_in[5];
    const float* bk = (const float*)d_in[6];
    const float* Wv = (const float*)d_in[7];
    const float* gv = (const float*)d_in[8];
    const float* bv = (const float*)d_in[9];
    float* out = (float*)d_out;

    cudaFuncSetAttribute(proj_gemm,  cudaFuncAttributeMaxDynamicSharedMemorySize, SMEM_BYTES);
    cudaFuncSetAttribute(attn_fused, cudaFuncAttributeMaxDynamicSharedMemorySize, SMEM_ATTN);

    // 1) input conversions: W -> bf16, x -> x^T bf16
    convert_w<<<dim3(COUT * CIN / 4 / 256, 1, 3), 256>>>(Wq, Wk, Wv);
    transpose_x<<<dim3(PP / 32, CIN / 32, NB), 256>>>(x);
    // 2) Y = W x (bf16), fused per-CTA BN partial stats
    proj_gemm<<<dim3(PP / 128, COUT / 128, 24), 256, SMEM_BYTES>>>();
    // 3) finalize BN stats (tiny reduce; cS folded into K scale/shift)
    stats_reduce<<<3 * COUT, 32>>>(gq, bq, gk, bk, gv, bv);
    // 4) BN + LeakyReLU, emit Q / K^T / V^T single bf16
    bn_apply_q<<<(unsigned)((size_t)NB * COUT * PP / 8 / 256), 256>>>();
    bn_apply_t<<<dim3(PP / 32, COUT / 32, 16), 256>>>();
    // 5) fused S -> maxless softmax -> O
    attn_fused<<<dim3(16, 64), 256, SMEM_ATTN>>>(out);
}

// round 12
// speedup vs baseline: 2.7459x; 1.1588x over previous
#include <cuda_runtime.h>
#include <cuda_bf16.h>
#include <cstdint>

#define NB   8
#define CIN  512
#define COUT 1024
#define PP   2048
#define NH   8
#define DH   128

typedef __nv_bfloat16 bf16;

// ---------------- device scratch (static: no allocation allowed) -------------
__device__ bf16  g_Yb[(size_t)3 * NB * COUT * PP];                   // 96 MB
__device__ float g_ps[(size_t)24 * 8 * 16 * 256];                    // 3 MB partials
__device__ float g_scale[3][COUT];
__device__ float g_shift[3][COUT];
__device__ bf16  g_W[3][COUT * CIN];
__device__ bf16  g_xT[(size_t)NB * PP * CIN];
__device__ bf16  g_Q[(size_t)NB * COUT * PP];
__device__ bf16  g_KT[(size_t)NB * PP * COUT];    // pre-scaled by log2e/sqrt(dh)
__device__ bf16  g_VT[(size_t)NB * PP * COUT];

// ---------------- PTX helpers (baseline PTX only) ----------------------------
__device__ __forceinline__ uint32_t smem_u32(const void* p) {
    uint32_t a;
    asm("{ .reg .u64 t; cvta.to.shared.u64 t, %1; cvt.u32.u64 %0, t; }" : "=r"(a) : "l"(p));
    return a;
}
__device__ __forceinline__ void cp16(uint32_t saddr, const void* g) {
    asm volatile("cp.async.cg.shared.global [%0], [%1], 16;" :: "r"(saddr), "l"(g));
}
#define CP_COMMIT() asm volatile("cp.async.commit_group;" ::: "memory")
template <int N>
__device__ __forceinline__ void cp_wait() {
    asm volatile("cp.async.wait_group %0;" :: "n"(N) : "memory");
}
__device__ __forceinline__ void lma4(uint32_t* r, uint32_t addr) {
    asm volatile("ldmatrix.sync.aligned.m8n8.x4.shared.b16 {%0,%1,%2,%3}, [%4];"
                 : "=r"(r[0]), "=r"(r[1]), "=r"(r[2]), "=r"(r[3]) : "r"(addr));
}
__device__ __forceinline__ void mma16816(float* d, const uint32_t* a, const uint32_t* b) {
    asm volatile("mma.sync.aligned.m16n8k16.row.col.f32.bf16.bf16.f32 "
                 "{%0,%1,%2,%3}, {%4,%5,%6,%7}, {%8,%9}, {%0,%1,%2,%3};"
                 : "+f"(d[0]), "+f"(d[1]), "+f"(d[2]), "+f"(d[3])
                 : "r"(a[0]), "r"(a[1]), "r"(a[2]), "r"(a[3]), "r"(b[0]), "r"(b[1]));
}
__device__ __forceinline__ float ex2f(float x) {
    float y;
    asm("ex2.approx.ftz.f32 %0, %1;" : "=f"(y) : "f"(x));
    return y;
}
// pack two fp32 -> bf16x2 in one cvt (hi = first operand's bf16 in high half)
__device__ __forceinline__ uint32_t cvt_bf16x2(float hi, float lo) {
    uint32_t r;
    asm("cvt.rn.bf16x2.f32 %0, %1, %2;" : "=r"(r) : "f"(hi), "f"(lo));
    return r;
}

// =============================================================================
// Projection GEMM (single-plane bf16, 1 term) + fused BN partial stats.
// =============================================================================
#define ROWB   80
#define MATB   (128 * ROWB)
#define STAGEB (2 * MATB)
#define OFF_A  0
#define OFF_B  MATB
#define SMEM_BYTES (2 * STAGEB)          // 40960

__global__ __launch_bounds__(256) void proj_gemm(void) {
    extern __shared__ __align__(128) char smem[];
    const uint32_t sb = smem_u32(smem);
    const int tid = threadIdx.x;
    const int L = tid & 31;
    const int w = tid >> 5;
    const int wm = w >> 2, wn = w & 3;
    const int z = blockIdx.z;             // proj*8 + b
    const int m0 = blockIdx.y * 128, n0 = blockIdx.x * 128;

    const bf16* Am = g_W[z >> 3];
    const bf16* Bm = g_xT + (size_t)(z & 7) * PP * CIN;
    bf16* C = g_Yb + (size_t)z * COUT * PP;

    const int ck0 = tid * 2, ck1 = tid * 2 + 1;
    const int lr0 = ck0 >> 2, lc0 = ck0 & 3;
    const int lr1 = ck1 >> 2, lc1 = ck1 & 3;

    const bf16* pA0 = Am + (size_t)(m0 + lr0) * CIN + lc0 * 8;
    const bf16* pA1 = Am + (size_t)(m0 + lr1) * CIN + lc1 * 8;
    const bf16* pB0 = Bm + (size_t)(n0 + lr0) * CIN + lc0 * 8;
    const bf16* pB1 = Bm + (size_t)(n0 + lr1) * CIN + lc1 * 8;
    const uint32_t so0 = lr0 * ROWB + lc0 * 16;
    const uint32_t so1 = lr1 * ROWB + lc1 * 16;

    float acc[4][4][4];
#pragma unroll
    for (int mt = 0; mt < 4; mt++)
#pragma unroll
        for (int nt = 0; nt < 4; nt++)
#pragma unroll
            for (int i = 0; i < 4; i++) acc[mt][nt][i] = 0.0f;

    const int nch = CIN >> 5;
    {
        uint32_t base = sb;
        cp16(base + OFF_A + so0, pA0); cp16(base + OFF_A + so1, pA1);
        cp16(base + OFF_B + so0, pB0); cp16(base + OFF_B + so1, pB1);
        CP_COMMIT();
    }

    const uint32_t a_row = (uint32_t)(wm * 64 + ((L >> 3) & 1) * 8 + (L & 7));
    const uint32_t a_cc  = (uint32_t)(L >> 4);
    const uint32_t b_row = (uint32_t)(wn * 32 + ((L >> 4) << 3) + (L & 7));
    const uint32_t b_cc  = (uint32_t)((L >> 3) & 1);

    for (int ch = 0; ch < nch; ch++) {
        if (ch + 1 < nch) {
            uint32_t base = sb + ((ch + 1) & 1) * STAGEB;
            int kc = (ch + 1) * 32;
            cp16(base + OFF_A + so0, pA0 + kc); cp16(base + OFF_A + so1, pA1 + kc);
            cp16(base + OFF_B + so0, pB0 + kc); cp16(base + OFF_B + so1, pB1 + kc);
            CP_COMMIT();
            cp_wait<1>();
        } else {
            cp_wait<0>();
        }
        __syncthreads();

        uint32_t base = sb + (ch & 1) * STAGEB;
#pragma unroll
        for (int ks = 0; ks < 2; ks++) {
            uint32_t af[4][4], bf[4][2];
            uint32_t acol = (a_cc + ks * 2) * 16;
            uint32_t bcol = (b_cc + ks * 2) * 16;
#pragma unroll
            for (int mt = 0; mt < 4; mt++)
                lma4(af[mt], base + OFF_A + (a_row + mt * 16) * ROWB + acol);
#pragma unroll
            for (int np = 0; np < 2; np++) {
                uint32_t t4[4];
                lma4(t4, base + OFF_B + (b_row + np * 16) * ROWB + bcol);
                bf[2 * np][0] = t4[0]; bf[2 * np][1] = t4[1];
                bf[2 * np + 1][0] = t4[2]; bf[2 * np + 1][1] = t4[3];
            }
#pragma unroll
            for (int mt = 0; mt < 4; mt++)
#pragma unroll
                for (int nt = 0; nt < 4; nt++)
                    mma16816(acc[mt][nt], af[mt], bf[nt]);
        }
        __syncthreads();
    }

    // ---- epilogue: bf16 store + per-channel partial (sum, sumsq) ----
    const int tg = L >> 2, tp = L & 3;
#pragma unroll
    for (int mt = 0; mt < 4; mt++) {
        int r0 = m0 + wm * 64 + mt * 16 + tg;
#pragma unroll
        for (int nt = 0; nt < 4; nt++) {
            int c = n0 + wn * 32 + nt * 8 + tp * 2;
            *(uint32_t*)&C[(size_t)r0 * PP + c]       = cvt_bf16x2(acc[mt][nt][1], acc[mt][nt][0]);
            *(uint32_t*)&C[(size_t)(r0 + 8) * PP + c] = cvt_bf16x2(acc[mt][nt][3], acc[mt][nt][2]);
        }
    }

    float* sp = (float*)smem;
#pragma unroll
    for (int mt = 0; mt < 4; mt++) {
#pragma unroll
        for (int half = 0; half < 2; half++) {
            float s = 0.0f, q = 0.0f;
#pragma unroll
            for (int nt = 0; nt < 4; nt++) {
                float a = acc[mt][nt][2 * half], bq = acc[mt][nt][2 * half + 1];
                s += a + bq;
                q += a * a + bq * bq;
            }
            s += __shfl_xor_sync(0xffffffffu, s, 1);
            s += __shfl_xor_sync(0xffffffffu, s, 2);
            q += __shfl_xor_sync(0xffffffffu, q, 1);
            q += __shfl_xor_sync(0xffffffffu, q, 2);
            if (tp == 0) {
                int r = wm * 64 + mt * 16 + tg + 8 * half;
                sp[(wn * 128 + r) * 2]     = s;
                sp[(wn * 128 + r) * 2 + 1] = q;
            }
        }
    }
    __syncthreads();
    if (tid < 128) {
        float s = sp[tid * 2]             + sp[(128 + tid) * 2]
                + sp[(256 + tid) * 2]     + sp[(384 + tid) * 2];
        float q = sp[tid * 2 + 1]         + sp[(128 + tid) * 2 + 1]
                + sp[(256 + tid) * 2 + 1] + sp[(384 + tid) * 2 + 1];
        size_t o = (((size_t)z * 8 + blockIdx.y) * 16 + blockIdx.x) * 256 + tid * 2;
        g_ps[o] = s;
        g_ps[o + 1] = q;
    }
}

// ---------------- stats finalize ---------------------------------------------
__global__ __launch_bounds__(32) void stats_reduce(const float* __restrict__ gq,
                                                   const float* __restrict__ bq,
                                                   const float* __restrict__ gk,
                                                   const float* __restrict__ bk,
                                                   const float* __restrict__ gv,
                                                   const float* __restrict__ bv) {
    int proj = blockIdx.x >> 10;
    int chn  = blockIdx.x & 1023;
    int my   = chn >> 7, row = chn & 127;
    float s = 0.0f, q = 0.0f;
    for (int i = threadIdx.x; i < 128; i += 32) {
        int b = i >> 4, nx = i & 15;
        size_t o = (((size_t)(proj * 8 + b) * 8 + my) * 16 + nx) * 256 + row * 2;
        s += g_ps[o]; q += g_ps[o + 1];
    }
#pragma unroll
    for (int o = 16; o; o >>= 1) {
        s += __shfl_xor_sync(0xffffffffu, s, o);
        q += __shfl_xor_sync(0xffffffffu, q, o);
    }
    if (threadIdx.x == 0) {
        const float inv_n = 1.0f / (float)(NB * PP);
        float mean = s * inv_n;
        float var  = q * inv_n - mean * mean;
        const float* g  = (proj == 0) ? gq : ((proj == 1) ? gk : gv);
        const float* bb = (proj == 0) ? bq : ((proj == 1) ? bk : bv);
        float sc = g[chn] * rsqrtf(var + 1e-5f);
        float sh = bb[chn] - mean * sc;
        if (proj == 1) {
            const float cS = 1.4426950408889634f * 0.08838834764831845f;
            sc *= cS; sh *= cS;
        }
        g_scale[proj][chn] = sc;
        g_shift[proj][chn] = sh;
    }
}

// =============================================================================
// Fused flash attention — maxless softmax; V and Q fully double-buffered
// =============================================================================
#define APITCH 272
#define TILEB  (128 * APITCH)
#define SM_K   0
#define SM_V0  (1 * TILEB)
#define SM_V1  (2 * TILEB)
#define SM_Q0  (3 * TILEB)
#define SM_Q1  (4 * TILEB)
#define SM_P   (5 * TILEB)
#define SM_RS  (6 * TILEB)
#define SMEM_ATTN (SM_RS + 2048)         // 210944

__device__ __forceinline__ void load_plane(uint32_t sb, uint32_t off,
                                           const bf16* __restrict__ src,
                                           size_t stride, int tid) {
#pragma unroll
    for (int i = 0; i < 8; i++) {
        int idx = tid + i * 256;
        int r = idx >> 4, cc = idx & 15;
        cp16(sb + off + r * APITCH + cc * 16, src + (size_t)r * stride + cc * 8);
    }
}

__global__ __launch_bounds__(256, 1) void attn_fused(float* __restrict__ out) {
    extern __shared__ __align__(128) char smem[];
    const uint32_t sb = smem_u32(smem);
    const int tid = threadIdx.x;
    const int L = tid & 31, w = tid >> 5;
    const int wm = w >> 2, wn = w & 3;
    const int tg = L >> 2, tp = L & 3;
    const int it = blockIdx.x;
    const int z = blockIdx.y, b = z >> 3, h = z & 7;

    const bf16* Kp = g_KT + ((size_t)b * PP + it * 128) * COUT + h * DH;
    const bf16* Vp = g_VT + (size_t)b * PP * COUT + h * DH;
    const bf16* Qp = g_Q + ((size_t)b * COUT + h * DH) * PP;

    // prologue: group(K + V0), then group(Q0)
    load_plane(sb, SM_K, Kp, COUT, tid);
    load_plane(sb, SM_V0, Vp, COUT, tid);
    CP_COMMIT();
    load_plane(sb, SM_Q0, Qp, PP, tid);
    CP_COMMIT();

    const uint32_t a_row = (uint32_t)(wm * 64 + ((L >> 3) & 1) * 8 + (L & 7));
    const uint32_t a_cc  = (uint32_t)(L >> 4);
    const uint32_t b_row = (uint32_t)(wn * 32 + ((L >> 4) << 3) + (L & 7));
    const uint32_t b_cc  = (uint32_t)((L >> 3) & 1);

    float oacc[4][4][4];
    float lrow[4][2];
#pragma unroll
    for (int mt = 0; mt < 4; mt++) {
        lrow[mt][0] = lrow[mt][1] = 0.0f;
#pragma unroll
        for (int nt = 0; nt < 4; nt++)
#pragma unroll
            for (int i = 0; i < 4; i++) oacc[mt][nt][i] = 0.0f;
    }

    for (int jt = 0; jt < 16; jt++) {
        const uint32_t vbase = sb + SM_V0 + (uint32_t)(jt & 1) * TILEB;
        const uint32_t qbase = sb + SM_Q0 + (uint32_t)(jt & 1) * TILEB;

        // wait V(jt) (leave Q(jt) in flight)
        cp_wait<1>();
        __syncthreads();

        // issue V(jt+1) into the alternate buffer (hidden under S-MMA + exp)
        if (jt + 1 < 16) {
            load_plane(sb, SM_V0 + (uint32_t)((jt + 1) & 1) * TILEB,
                       Vp + (size_t)(jt + 1) * 128 * COUT, COUT, tid);
            CP_COMMIT();
        }

        // ---- S' = (cS K_I)^T V_J ----
        float sacc[4][4][4];
#pragma unroll
        for (int mt = 0; mt < 4; mt++)
#pragma unroll
            for (int nt = 0; nt < 4; nt++)
#pragma unroll
                for (int i = 0; i < 4; i++) sacc[mt][nt][i] = 0.0f;

#pragma unroll
        for (int ks = 0; ks < 8; ks++) {
            uint32_t af[4][4], bf[4][2];
            uint32_t acol = (a_cc + ks * 2) * 16;
            uint32_t bcol = (b_cc + ks * 2) * 16;
#pragma unroll
            for (int mt = 0; mt < 4; mt++)
                lma4(af[mt], sb + SM_K + (a_row + mt * 16) * APITCH + acol);
#pragma unroll
            for (int np = 0; np < 2; np++) {
                uint32_t t4[4];
                lma4(t4, vbase + (b_row + np * 16) * APITCH + bcol);
                bf[2 * np][0] = t4[0]; bf[2 * np][1] = t4[1];
                bf[2 * np + 1][0] = t4[2]; bf[2 * np + 1][1] = t4[3];
            }
#pragma unroll
            for (int mt = 0; mt < 4; mt++)
#pragma unroll
                for (int nt = 0; nt < 4; nt++)
                    mma16816(sacc[mt][nt], af[mt], bf[nt]);
        }

        // ---- maxless softmax numerator ----
#pragma unroll
        for (int mt = 0; mt < 4; mt++) {
#pragma unroll
            for (int half = 0; half < 2; half++) {
                int r = wm * 64 + mt * 16 + tg + half * 8;
                float rs = 0.0f;
#pragma unroll
                for (int nt = 0; nt < 4; nt++) {
                    float p0 = ex2f(sacc[mt][nt][2 * half]);
                    float p1 = ex2f(sacc[mt][nt][2 * half + 1]);
                    rs += p0 + p1;
                    uint32_t col = wn * 32 + nt * 8 + 2 * tp;
                    *(uint32_t*)(smem + SM_P + r * APITCH + col * 2) = cvt_bf16x2(p1, p0);
                }
                lrow[mt][half] += rs;
            }
        }

        // wait Q(jt) (leave V(jt+1) in flight if any)
        if (jt + 1 < 16) cp_wait<1>(); else cp_wait<0>();
        __syncthreads();                 // P visible + Q(jt) ready

        // issue Q(jt+1) into the alternate buffer (hidden under O-MMA)
        if (jt + 1 < 16) {
            load_plane(sb, SM_Q0 + (uint32_t)((jt + 1) & 1) * TILEB,
                       Qp + (size_t)(jt + 1) * 128, PP, tid);
            CP_COMMIT();
        }

        // ---- O += P Q ----
#pragma unroll
        for (int ks = 0; ks < 8; ks++) {
            uint32_t af[4][4], bf[4][2];
            uint32_t acol = (a_cc + ks * 2) * 16;
            uint32_t bcol = (b_cc + ks * 2) * 16;
#pragma unroll
            for (int mt = 0; mt < 4; mt++)
                lma4(af[mt], sb + SM_P + (a_row + mt * 16) * APITCH + acol);
#pragma unroll
            for (int np = 0; np < 2; np++) {
                uint32_t t4[4];
                lma4(t4, qbase + (b_row + np * 16) * APITCH + bcol);
                bf[2 * np][0] = t4[0]; bf[2 * np][1] = t4[1];
                bf[2 * np + 1][0] = t4[2]; bf[2 * np + 1][1] = t4[3];
            }
#pragma unroll
            for (int mt = 0; mt < 4; mt++)
#pragma unroll
                for (int nt = 0; nt < 4; nt++)
                    mma16816(oacc[mt][nt], af[mt], bf[nt]);
        }
        __syncthreads();                 // P buffer free for next iteration
    }

    // ---- one-time row-sum reduction ----
#pragma unroll
    for (int mt = 0; mt < 4; mt++) {
#pragma unroll
        for (int half = 0; half < 2; half++) {
            float l = lrow[mt][half];
            l += __shfl_xor_sync(0xffffffffu, l, 1);
            l += __shfl_xor_sync(0xffffffffu, l, 2);
            lrow[mt][half] = l;
            if (tp == 0) {
                int r = wm * 64 + mt * 16 + tg + half * 8;
                *(float*)(smem + SM_RS + (wn * 128 + r) * 4) = l;
            }
        }
    }
    __syncthreads();
#pragma unroll
    for (int mt = 0; mt < 4; mt++) {
#pragma unroll
        for (int half = 0; half < 2; half++) {
            int r = wm * 64 + mt * 16 + tg + half * 8;
            lrow[mt][half] = *(float*)(smem + SM_RS + r * 4)
                           + *(float*)(smem + SM_RS + (128 + r) * 4)
                           + *(float*)(smem + SM_RS + (256 + r) * 4)
                           + *(float*)(smem + SM_RS + (384 + r) * 4);
        }
    }
    __syncthreads();

    // ---- normalize + transpose via SMEM ----
    float* fbuf = (float*)smem;
#pragma unroll
    for (int mt = 0; mt < 4; mt++) {
#pragma unroll
        for (int half = 0; half < 2; half++) {
            int r = wm * 64 + mt * 16 + tg + half * 8;
            float inv = 1.0f / lrow[mt][half];
#pragma unroll
            for (int nt = 0; nt < 4; nt++) {
                int c = wn * 32 + nt * 8 + 2 * tp;
                fbuf[(size_t)c * 132 + r]       = oacc[mt][nt][2 * half] * inv;
                fbuf[(size_t)(c + 1) * 132 + r] = oacc[mt][nt][2 * half + 1] * inv;
            }
        }
    }
    __syncthreads();
    const size_t obase = ((size_t)b * COUT + h * DH) * PP + (size_t)it * 128;
#pragma unroll
    for (int rr = 0; rr < 16; rr++) {
        int r = w * 16 + rr;
        float4 v = *(float4*)&fbuf[(size_t)r * 132 + L * 4];
        *(float4*)&out[obase + (size_t)r * PP + L * 4] = v;
    }
}

// ---------------- conversions ------------------------------------------------
__global__ __launch_bounds__(256) void convert_w(const float* __restrict__ Wq,
                                                 const float* __restrict__ Wk,
                                                 const float* __restrict__ Wv) {
    int proj = blockIdx.z;
    const float* W = (proj == 0) ? Wq : ((proj == 1) ? Wk : Wv);
    size_t e = ((size_t)blockIdx.x * 256 + threadIdx.x) * 4;
    float4 v = *(const float4*)(W + e);
    ((uint32_t*)&g_W[proj][e])[0] = cvt_bf16x2(v.y, v.x);
    ((uint32_t*)&g_W[proj][e])[1] = cvt_bf16x2(v.w, v.z);
}

__global__ __launch_bounds__(256) void transpose_x(const float* __restrict__ x) {
    __shared__ float t[32][33];
    int b = blockIdx.z;
    int p0 = blockIdx.x * 32, c0 = blockIdx.y * 32;
    int tx = threadIdx.x & 31, ty = threadIdx.x >> 5;
#pragma unroll
    for (int j = 0; j < 4; j++)
        t[ty + 8 * j][tx] = x[((size_t)b * CIN + c0 + ty + 8 * j) * PP + p0 + tx];
    __syncthreads();
#pragma unroll
    for (int j = 0; j < 4; j++) {
        float v = t[tx][ty + 8 * j];
        size_t o = ((size_t)b * PP + p0 + ty + 8 * j) * CIN + c0 + tx;
        g_xT[o] = __float2bfloat16(v);
    }
}

// ---------------- BN apply: Q path -------------------------------------------
__global__ __launch_bounds__(256) void bn_apply_q(void) {
    size_t e = ((size_t)blockIdx.x * 256 + threadIdx.x) * 8;
    int ch = (int)((e >> 11) & (COUT - 1));
    float sc = g_scale[0][ch], sh = g_shift[0][ch];
    uint4 raw = *(uint4*)&g_Yb[e];
    uint32_t rw[4] = {raw.x, raw.y, raw.z, raw.w};
    uint32_t outp[4];
#pragma unroll
    for (int i = 0; i < 4; i++) {
        __nv_bfloat162 pv = *(__nv_bfloat162*)&rw[i];
        float a = __bfloat162float(__low2bfloat16(pv));
        float c = __bfloat162float(__high2bfloat16(pv));
        a = sc * a + sh; a = (a < 0.0f) ? 0.1f * a : a;
        c = sc * c + sh; c = (c < 0.0f) ? 0.1f * c : c;
        outp[i] = cvt_bf16x2(c, a);
    }
    *(uint4*)&g_Q[e] = make_uint4(outp[0], outp[1], outp[2], outp[3]);
}

// ---------------- BN apply + transpose: K/V ----------------------------------
__global__ __launch_bounds__(256) void bn_apply_t(void) {
    __shared__ float t[32][33];
    int z = blockIdx.z;
    int proj = 1 + (z >> 3), b = z & 7;
    int p0 = blockIdx.x * 32, c0 = blockIdx.y * 32;
    int tx = threadIdx.x & 31, ty = threadIdx.x >> 5;
#pragma unroll
    for (int j = 0; j < 4; j++) {
        int c = c0 + ty + 8 * j;
        float sc = g_scale[proj][c], sh = g_shift[proj][c];
        float v = __bfloat162float(
            g_Yb[(((size_t)proj * NB + b) * COUT + c) * PP + p0 + tx]);
        v = sc * v + sh;
        v = (v < 0.0f) ? 0.1f * v : v;
        t[ty + 8 * j][tx] = v;
    }
    __syncthreads();
    bf16* T = (proj == 1) ? g_KT : g_VT;
#pragma unroll
    for (int j = 0; j < 4; j++) {
        float v = t[tx][ty + 8 * j];
        size_t o = ((size_t)b * PP + p0 + ty + 8 * j) * COUT + c0 + tx;
        T[o] = __float2bfloat16(v);
    }
}

// ---------------- launch -----------------------------------------------------
extern "C" void kernel_launch(void* const* d_in, const int* in_sizes, int n_in,
                              void* d_out, int out_size)
{
    (void)in_sizes; (void)n_in; (void)out_size;
    const float* x  = (const float*)d_in[0];
    const float* Wq = (const float*)d_in[1];
    const float* gq = (const float*)d_in[2];
    const float* bq = (const float*)d_in[3];
    const float* Wk = (const float*)d_in[4];
    const float* gk = (const float*)d_in[5];
    const float* bk = (const float*)d_in[6];
    const float* Wv = (const float*)d_in[7];
    const float* gv = (const float*)d_in[8];
    const float* bv = (const float*)d_in[9];
    float* out = (float*)d_out;

    cudaFuncSetAttribute(proj_gemm,  cudaFuncAttributeMaxDynamicSharedMemorySize, SMEM_BYTES);
    cudaFuncSetAttribute(attn_fused, cudaFuncAttributeMaxDynamicSharedMemorySize, SMEM_ATTN);

    // 1) input conversions
    convert_w<<<dim3(COUT * CIN / 4 / 256, 1, 3), 256>>>(Wq, Wk, Wv);
    transpose_x<<<dim3(PP / 32, CIN / 32, NB), 256>>>(x);
    // 2) Y = W x (bf16), fused BN partial stats
    proj_gemm<<<dim3(PP / 128, COUT / 128, 24), 256, SMEM_BYTES>>>();
    // 3) finalize BN stats (cS folded into K)
    stats_reduce<<<3 * COUT, 32>>>(gq, bq, gk, bk, gv, bv);
    // 4) BN + LeakyReLU, emit Q / K^T / V^T single bf16
    bn_apply_q<<<(unsigned)((size_t)NB * COUT * PP / 8 / 256), 256>>>();
    bn_apply_t<<<dim3(PP / 32, COUT / 32, 16), 256>>>();
    // 5) fused S -> maxless softmax -> O (double-buffered V/Q)
    attn_fused<<<dim3(16, 64), 256, SMEM_ATTN>>>(out);
}

// round 13
// speedup vs baseline: 2.7469x; 1.0004x over previous
#include <cuda_runtime.h>
#include <cuda_bf16.h>
#include <cstdint>

#define NB   8
#define CIN  512
#define COUT 1024
#define PP   2048
#define NH   8
#define DH   128

typedef __nv_bfloat16 bf16;

// ---------------- device scratch (static: no allocation allowed) -------------
__device__ bf16  g_Yb[(size_t)3 * NB * COUT * PP];                   // 96 MB
__device__ float g_ps[(size_t)24 * 8 * 16 * 256];                    // 3 MB partials
__device__ float g_scale[3][COUT];
__device__ float g_shift[3][COUT];
__device__ bf16  g_W[3][COUT * CIN];
__device__ bf16  g_xT[(size_t)NB * PP * CIN];
__device__ bf16  g_Q[(size_t)NB * COUT * PP];
__device__ bf16  g_KT[(size_t)NB * PP * COUT];    // pre-scaled by log2e/sqrt(dh)
__device__ bf16  g_VT[(size_t)NB * PP * COUT];

// ---------------- PTX helpers (baseline PTX only) ----------------------------
__device__ __forceinline__ uint32_t smem_u32(const void* p) {
    uint32_t a;
    asm("{ .reg .u64 t; cvta.to.shared.u64 t, %1; cvt.u32.u64 %0, t; }" : "=r"(a) : "l"(p));
    return a;
}
__device__ __forceinline__ void cp16(uint32_t saddr, const void* g) {
    asm volatile("cp.async.cg.shared.global [%0], [%1], 16;" :: "r"(saddr), "l"(g));
}
#define CP_COMMIT() asm volatile("cp.async.commit_group;" ::: "memory")
template <int N>
__device__ __forceinline__ void cp_wait() {
    asm volatile("cp.async.wait_group %0;" :: "n"(N) : "memory");
}
__device__ __forceinline__ void lma4(uint32_t* r, uint32_t addr) {
    asm volatile("ldmatrix.sync.aligned.m8n8.x4.shared.b16 {%0,%1,%2,%3}, [%4];"
                 : "=r"(r[0]), "=r"(r[1]), "=r"(r[2]), "=r"(r[3]) : "r"(addr));
}
__device__ __forceinline__ void mma16816(float* d, const uint32_t* a, const uint32_t* b) {
    asm volatile("mma.sync.aligned.m16n8k16.row.col.f32.bf16.bf16.f32 "
                 "{%0,%1,%2,%3}, {%4,%5,%6,%7}, {%8,%9}, {%0,%1,%2,%3};"
                 : "+f"(d[0]), "+f"(d[1]), "+f"(d[2]), "+f"(d[3])
                 : "r"(a[0]), "r"(a[1]), "r"(a[2]), "r"(a[3]), "r"(b[0]), "r"(b[1]));
}
__device__ __forceinline__ float ex2f(float x) {
    float y;
    asm("ex2.approx.ftz.f32 %0, %1;" : "=f"(y) : "f"(x));
    return y;
}
__device__ __forceinline__ uint32_t cvt_bf16x2(float hi, float lo) {
    uint32_t r;
    asm("cvt.rn.bf16x2.f32 %0, %1, %2;" : "=r"(r) : "f"(hi), "f"(lo));
    return r;
}

// =============================================================================
// Projection GEMM (single-plane bf16, 1 term) + fused BN partial stats.
// (unchanged from round 11)
// =============================================================================
#define ROWB   80
#define MATB   (128 * ROWB)
#define STAGEB (2 * MATB)
#define OFF_A  0
#define OFF_B  MATB
#define SMEM_BYTES (2 * STAGEB)          // 40960

__global__ __launch_bounds__(256) void proj_gemm(void) {
    extern __shared__ __align__(128) char smem[];
    const uint32_t sb = smem_u32(smem);
    const int tid = threadIdx.x;
    const int L = tid & 31;
    const int w = tid >> 5;
    const int wm = w >> 2, wn = w & 3;
    const int z = blockIdx.z;
    const int m0 = blockIdx.y * 128, n0 = blockIdx.x * 128;

    const bf16* Am = g_W[z >> 3];
    const bf16* Bm = g_xT + (size_t)(z & 7) * PP * CIN;
    bf16* C = g_Yb + (size_t)z * COUT * PP;

    const int ck0 = tid * 2, ck1 = tid * 2 + 1;
    const int lr0 = ck0 >> 2, lc0 = ck0 & 3;
    const int lr1 = ck1 >> 2, lc1 = ck1 & 3;

    const bf16* pA0 = Am + (size_t)(m0 + lr0) * CIN + lc0 * 8;
    const bf16* pA1 = Am + (size_t)(m0 + lr1) * CIN + lc1 * 8;
    const bf16* pB0 = Bm + (size_t)(n0 + lr0) * CIN + lc0 * 8;
    const bf16* pB1 = Bm + (size_t)(n0 + lr1) * CIN + lc1 * 8;
    const uint32_t so0 = lr0 * ROWB + lc0 * 16;
    const uint32_t so1 = lr1 * ROWB + lc1 * 16;

    float acc[4][4][4];
#pragma unroll
    for (int mt = 0; mt < 4; mt++)
#pragma unroll
        for (int nt = 0; nt < 4; nt++)
#pragma unroll
            for (int i = 0; i < 4; i++) acc[mt][nt][i] = 0.0f;

    const int nch = CIN >> 5;
    {
        uint32_t base = sb;
        cp16(base + OFF_A + so0, pA0); cp16(base + OFF_A + so1, pA1);
        cp16(base + OFF_B + so0, pB0); cp16(base + OFF_B + so1, pB1);
        CP_COMMIT();
    }

    const uint32_t a_row = (uint32_t)(wm * 64 + ((L >> 3) & 1) * 8 + (L & 7));
    const uint32_t a_cc  = (uint32_t)(L >> 4);
    const uint32_t b_row = (uint32_t)(wn * 32 + ((L >> 4) << 3) + (L & 7));
    const uint32_t b_cc  = (uint32_t)((L >> 3) & 1);

    for (int ch = 0; ch < nch; ch++) {
        if (ch + 1 < nch) {
            uint32_t base = sb + ((ch + 1) & 1) * STAGEB;
            int kc = (ch + 1) * 32;
            cp16(base + OFF_A + so0, pA0 + kc); cp16(base + OFF_A + so1, pA1 + kc);
            cp16(base + OFF_B + so0, pB0 + kc); cp16(base + OFF_B + so1, pB1 + kc);
            CP_COMMIT();
            cp_wait<1>();
        } else {
            cp_wait<0>();
        }
        __syncthreads();

        uint32_t base = sb + (ch & 1) * STAGEB;
#pragma unroll
        for (int ks = 0; ks < 2; ks++) {
            uint32_t af[4][4], bf[4][2];
            uint32_t acol = (a_cc + ks * 2) * 16;
            uint32_t bcol = (b_cc + ks * 2) * 16;
#pragma unroll
            for (int mt = 0; mt < 4; mt++)
                lma4(af[mt], base + OFF_A + (a_row + mt * 16) * ROWB + acol);
#pragma unroll
            for (int np = 0; np < 2; np++) {
                uint32_t t4[4];
                lma4(t4, base + OFF_B + (b_row + np * 16) * ROWB + bcol);
                bf[2 * np][0] = t4[0]; bf[2 * np][1] = t4[1];
                bf[2 * np + 1][0] = t4[2]; bf[2 * np + 1][1] = t4[3];
            }
#pragma unroll
            for (int mt = 0; mt < 4; mt++)
#pragma unroll
                for (int nt = 0; nt < 4; nt++)
                    mma16816(acc[mt][nt], af[mt], bf[nt]);
        }
        __syncthreads();
    }

    const int tg = L >> 2, tp = L & 3;
#pragma unroll
    for (int mt = 0; mt < 4; mt++) {
        int r0 = m0 + wm * 64 + mt * 16 + tg;
#pragma unroll
        for (int nt = 0; nt < 4; nt++) {
            int c = n0 + wn * 32 + nt * 8 + tp * 2;
            *(uint32_t*)&C[(size_t)r0 * PP + c]       = cvt_bf16x2(acc[mt][nt][1], acc[mt][nt][0]);
            *(uint32_t*)&C[(size_t)(r0 + 8) * PP + c] = cvt_bf16x2(acc[mt][nt][3], acc[mt][nt][2]);
        }
    }

    float* sp = (float*)smem;
#pragma unroll
    for (int mt = 0; mt < 4; mt++) {
#pragma unroll
        for (int half = 0; half < 2; half++) {
            float s = 0.0f, q = 0.0f;
#pragma unroll
            for (int nt = 0; nt < 4; nt++) {
                float a = acc[mt][nt][2 * half], bq = acc[mt][nt][2 * half + 1];
                s += a + bq;
                q += a * a + bq * bq;
            }
            s += __shfl_xor_sync(0xffffffffu, s, 1);
            s += __shfl_xor_sync(0xffffffffu, s, 2);
            q += __shfl_xor_sync(0xffffffffu, q, 1);
            q += __shfl_xor_sync(0xffffffffu, q, 2);
            if (tp == 0) {
                int r = wm * 64 + mt * 16 + tg + 8 * half;
                sp[(wn * 128 + r) * 2]     = s;
                sp[(wn * 128 + r) * 2 + 1] = q;
            }
        }
    }
    __syncthreads();
    if (tid < 128) {
        float s = sp[tid * 2]             + sp[(128 + tid) * 2]
                + sp[(256 + tid) * 2]     + sp[(384 + tid) * 2];
        float q = sp[tid * 2 + 1]         + sp[(128 + tid) * 2 + 1]
                + sp[(256 + tid) * 2 + 1] + sp[(384 + tid) * 2 + 1];
        size_t o = (((size_t)z * 8 + blockIdx.y) * 16 + blockIdx.x) * 256 + tid * 2;
        g_ps[o] = s;
        g_ps[o + 1] = q;
    }
}

// ---------------- stats finalize ---------------------------------------------
__global__ __launch_bounds__(32) void stats_reduce(const float* __restrict__ gq,
                                                   const float* __restrict__ bq,
                                                   const float* __restrict__ gk,
                                                   const float* __restrict__ bk,
                                                   const float* __restrict__ gv,
                                                   const float* __restrict__ bv) {
    int proj = blockIdx.x >> 10;
    int chn  = blockIdx.x & 1023;
    int my   = chn >> 7, row = chn & 127;
    float s = 0.0f, q = 0.0f;
    for (int i = threadIdx.x; i < 128; i += 32) {
        int b = i >> 4, nx = i & 15;
        size_t o = (((size_t)(proj * 8 + b) * 8 + my) * 16 + nx) * 256 + row * 2;
        s += g_ps[o]; q += g_ps[o + 1];
    }
#pragma unroll
    for (int o = 16; o; o >>= 1) {
        s += __shfl_xor_sync(0xffffffffu, s, o);
        q += __shfl_xor_sync(0xffffffffu, q, o);
    }
    if (threadIdx.x == 0) {
        const float inv_n = 1.0f / (float)(NB * PP);
        float mean = s * inv_n;
        float var  = q * inv_n - mean * mean;
        const float* g  = (proj == 0) ? gq : ((proj == 1) ? gk : gv);
        const float* bb = (proj == 0) ? bq : ((proj == 1) ? bk : bv);
        float sc = g[chn] * rsqrtf(var + 1e-5f);
        float sh = bb[chn] - mean * sc;
        if (proj == 1) {
            const float cS = 1.4426950408889634f * 0.08838834764831845f;
            sc *= cS; sh *= cS;
        }
        g_scale[proj][chn] = sc;
        g_shift[proj][chn] = sh;
    }
}

// =============================================================================
// Fused flash attention — 512 threads (16 warps, 4/SMSP), maxless softmax,
// double-buffered V/Q. Warp (wm 0..3) x (wn 0..3): 32 i-rows x 32 j-cols.
// =============================================================================
#define APITCH 272
#define TILEB  (128 * APITCH)
#define SM_K   0
#define SM_V0  (1 * TILEB)
#define SM_V1  (2 * TILEB)
#define SM_Q0  (3 * TILEB)
#define SM_Q1  (4 * TILEB)
#define SM_P   (5 * TILEB)
#define SM_RS  (6 * TILEB)
#define SMEM_ATTN (SM_RS + 2048)         // 210944

__device__ __forceinline__ void load_plane512(uint32_t sb, uint32_t off,
                                              const bf16* __restrict__ src,
                                              size_t stride, int tid) {
#pragma unroll
    for (int i = 0; i < 4; i++) {
        int idx = tid + i * 512;
        int r = idx >> 4, cc = idx & 15;
        cp16(sb + off + r * APITCH + cc * 16, src + (size_t)r * stride + cc * 8);
    }
}

__global__ __launch_bounds__(512, 1) void attn_fused(float* __restrict__ out) {
    extern __shared__ __align__(128) char smem[];
    const uint32_t sb = smem_u32(smem);
    const int tid = threadIdx.x;
    const int L = tid & 31, w = tid >> 5;
    const int wm = w >> 2, wn = w & 3;      // wm 0..3, wn 0..3
    const int tg = L >> 2, tp = L & 3;
    const int it = blockIdx.x;
    const int z = blockIdx.y, b = z >> 3, h = z & 7;

    const bf16* Kp = g_KT + ((size_t)b * PP + it * 128) * COUT + h * DH;
    const bf16* Vp = g_VT + (size_t)b * PP * COUT + h * DH;
    const bf16* Qp = g_Q + ((size_t)b * COUT + h * DH) * PP;

    // prologue: group(K + V0), then group(Q0)
    load_plane512(sb, SM_K, Kp, COUT, tid);
    load_plane512(sb, SM_V0, Vp, COUT, tid);
    CP_COMMIT();
    load_plane512(sb, SM_Q0, Qp, PP, tid);
    CP_COMMIT();

    const uint32_t a_row = (uint32_t)(wm * 32 + ((L >> 3) & 1) * 8 + (L & 7));
    const uint32_t a_cc  = (uint32_t)(L >> 4);
    const uint32_t b_row = (uint32_t)(wn * 32 + ((L >> 4) << 3) + (L & 7));
    const uint32_t b_cc  = (uint32_t)((L >> 3) & 1);

    float oacc[2][4][4];
    float lrow[2][2];
#pragma unroll
    for (int mt = 0; mt < 2; mt++) {
        lrow[mt][0] = lrow[mt][1] = 0.0f;
#pragma unroll
        for (int nt = 0; nt < 4; nt++)
#pragma unroll
            for (int i = 0; i < 4; i++) oacc[mt][nt][i] = 0.0f;
    }

    for (int jt = 0; jt < 16; jt++) {
        const uint32_t vbase = sb + SM_V0 + (uint32_t)(jt & 1) * TILEB;
        const uint32_t qbase = sb + SM_Q0 + (uint32_t)(jt & 1) * TILEB;

        cp_wait<1>();                    // V(jt) ready (Q(jt) may be in flight)
        __syncthreads();

        if (jt + 1 < 16) {
            load_plane512(sb, SM_V0 + (uint32_t)((jt + 1) & 1) * TILEB,
                          Vp + (size_t)(jt + 1) * 128 * COUT, COUT, tid);
            CP_COMMIT();
        }

        // ---- S' = (cS K_I)^T V_J ----
        float sacc[2][4][4];
#pragma unroll
        for (int mt = 0; mt < 2; mt++)
#pragma unroll
            for (int nt = 0; nt < 4; nt++)
#pragma unroll
                for (int i = 0; i < 4; i++) sacc[mt][nt][i] = 0.0f;

#pragma unroll
        for (int ks = 0; ks < 8; ks++) {
            uint32_t af[2][4], bf[4][2];
            uint32_t acol = (a_cc + ks * 2) * 16;
            uint32_t bcol = (b_cc + ks * 2) * 16;
#pragma unroll
            for (int mt = 0; mt < 2; mt++)
                lma4(af[mt], sb + SM_K + (a_row + mt * 16) * APITCH + acol);
#pragma unroll
            for (int np = 0; np < 2; np++) {
                uint32_t t4[4];
                lma4(t4, vbase + (b_row + np * 16) * APITCH + bcol);
                bf[2 * np][0] = t4[0]; bf[2 * np][1] = t4[1];
                bf[2 * np + 1][0] = t4[2]; bf[2 * np + 1][1] = t4[3];
            }
#pragma unroll
            for (int mt = 0; mt < 2; mt++)
#pragma unroll
                for (int nt = 0; nt < 4; nt++)
                    mma16816(sacc[mt][nt], af[mt], bf[nt]);
        }

        // ---- maxless softmax numerator ----
#pragma unroll
        for (int mt = 0; mt < 2; mt++) {
#pragma unroll
            for (int half = 0; half < 2; half++) {
                int r = wm * 32 + mt * 16 + tg + half * 8;
                float rs = 0.0f;
#pragma unroll
                for (int nt = 0; nt < 4; nt++) {
                    float p0 = ex2f(sacc[mt][nt][2 * half]);
                    float p1 = ex2f(sacc[mt][nt][2 * half + 1]);
                    rs += p0 + p1;
                    uint32_t col = wn * 32 + nt * 8 + 2 * tp;
                    *(uint32_t*)(smem + SM_P + r * APITCH + col * 2) = cvt_bf16x2(p1, p0);
                }
                lrow[mt][half] += rs;
            }
        }

        if (jt + 1 < 16) cp_wait<1>(); else cp_wait<0>();
        __syncthreads();                 // P visible + Q(jt) ready

        if (jt + 1 < 16) {
            load_plane512(sb, SM_Q0 + (uint32_t)((jt + 1) & 1) * TILEB,
                          Qp + (size_t)(jt + 1) * 128, PP, tid);
            CP_COMMIT();
        }

        // ---- O += P Q ----
#pragma unroll
        for (int ks = 0; ks < 8; ks++) {
            uint32_t af[2][4], bf[4][2];
            uint32_t acol = (a_cc + ks * 2) * 16;
            uint32_t bcol = (b_cc + ks * 2) * 16;
#pragma unroll
            for (int mt = 0; mt < 2; mt++)
                lma4(af[mt], sb + SM_P + (a_row + mt * 16) * APITCH + acol);
#pragma unroll
            for (int np = 0; np < 2; np++) {
                uint32_t t4[4];
                lma4(t4, qbase + (b_row + np * 16) * APITCH + bcol);
                bf[2 * np][0] = t4[0]; bf[2 * np][1] = t4[1];
                bf[2 * np + 1][0] = t4[2]; bf[2 * np + 1][1] = t4[3];
            }
#pragma unroll
            for (int mt = 0; mt < 2; mt++)
#pragma unroll
                for (int nt = 0; nt < 4; nt++)
                    mma16816(oacc[mt][nt], af[mt], bf[nt]);
        }
        __syncthreads();                 // P buffer free for next iteration
    }

    // ---- one-time row-sum reduction: quads then across the 4 wn warps ----
#pragma unroll
    for (int mt = 0; mt < 2; mt++) {
#pragma unroll
        for (int half = 0; half < 2; half++) {
            float l = lrow[mt][half];
            l += __shfl_xor_sync(0xffffffffu, l, 1);
            l += __shfl_xor_sync(0xffffffffu, l, 2);
            if (tp == 0) {
                int r = wm * 32 + mt * 16 + tg + half * 8;
                *(float*)(smem + SM_RS + (wn * 128 + r) * 4) = l;
            }
        }
    }
    __syncthreads();
#pragma unroll
    for (int mt = 0; mt < 2; mt++) {
#pragma unroll
        for (int half = 0; half < 2; half++) {
            int r = wm * 32 + mt * 16 + tg + half * 8;
            lrow[mt][half] = *(float*)(smem + SM_RS + r * 4)
                           + *(float*)(smem + SM_RS + (128 + r) * 4)
                           + *(float*)(smem + SM_RS + (256 + r) * 4)
                           + *(float*)(smem + SM_RS + (384 + r) * 4);
        }
    }
    __syncthreads();

    // ---- normalize + transpose via SMEM ----
    float* fbuf = (float*)smem;          // 128 x 132 floats
#pragma unroll
    for (int mt = 0; mt < 2; mt++) {
#pragma unroll
        for (int half = 0; half < 2; half++) {
            int r = wm * 32 + mt * 16 + tg + half * 8;
            float inv = 1.0f / lrow[mt][half];
#pragma unroll
            for (int nt = 0; nt < 4; nt++) {
                int c = wn * 32 + nt * 8 + 2 * tp;
                fbuf[(size_t)c * 132 + r]       = oacc[mt][nt][2 * half] * inv;
                fbuf[(size_t)(c + 1) * 132 + r] = oacc[mt][nt][2 * half + 1] * inv;
            }
        }
    }
    __syncthreads();
    const size_t obase = ((size_t)b * COUT + h * DH) * PP + (size_t)it * 128;
#pragma unroll
    for (int rr = 0; rr < 8; rr++) {
        int r = w * 8 + rr;
        float4 v = *(float4*)&fbuf[(size_t)r * 132 + L * 4];
        *(float4*)&out[obase + (size_t)r * PP + L * 4] = v;
    }
}

// ---------------- conversions ------------------------------------------------
__global__ __launch_bounds__(256) void convert_w(const float* __restrict__ Wq,
                                                 const float* __restrict__ Wk,
                                                 const float* __restrict__ Wv) {
    int proj = blockIdx.z;
    const float* W = (proj == 0) ? Wq : ((proj == 1) ? Wk : Wv);
    size_t e = ((size_t)blockIdx.x * 256 + threadIdx.x) * 4;
    float4 v = *(const float4*)(W + e);
    ((uint32_t*)&g_W[proj][e])[0] = cvt_bf16x2(v.y, v.x);
    ((uint32_t*)&g_W[proj][e])[1] = cvt_bf16x2(v.w, v.z);
}

__global__ __launch_bounds__(256) void transpose_x(const float* __restrict__ x) {
    __shared__ float t[32][33];
    int b = blockIdx.z;
    int p0 = blockIdx.x * 32, c0 = blockIdx.y * 32;
    int tx = threadIdx.x & 31, ty = threadIdx.x >> 5;
#pragma unroll
    for (int j = 0; j < 4; j++)
        t[ty + 8 * j][tx] = x[((size_t)b * CIN + c0 + ty + 8 * j) * PP + p0 + tx];
    __syncthreads();
#pragma unroll
    for (int j = 0; j < 4; j++) {
        float v = t[tx][ty + 8 * j];
        size_t o = ((size_t)b * PP + p0 + ty + 8 * j) * CIN + c0 + tx;
        g_xT[o] = __float2bfloat16(v);
    }
}

// ---------------- BN apply: Q path -------------------------------------------
__global__ __launch_bounds__(256) void bn_apply_q(void) {
    size_t e = ((size_t)blockIdx.x * 256 + threadIdx.x) * 8;
    int ch = (int)((e >> 11) & (COUT - 1));
    float sc = g_scale[0][ch], sh = g_shift[0][ch];
    uint4 raw = *(uint4*)&g_Yb[e];
    uint32_t rw[4] = {raw.x, raw.y, raw.z, raw.w};
    uint32_t outp[4];
#pragma unroll
    for (int i = 0; i < 4; i++) {
        __nv_bfloat162 pv = *(__nv_bfloat162*)&rw[i];
        float a = __bfloat162float(__low2bfloat16(pv));
        float c = __bfloat162float(__high2bfloat16(pv));
        a = sc * a + sh; a = (a < 0.0f) ? 0.1f * a : a;
        c = sc * c + sh; c = (c < 0.0f) ? 0.1f * c : c;
        outp[i] = cvt_bf16x2(c, a);
    }
    *(uint4*)&g_Q[e] = make_uint4(outp[0], outp[1], outp[2], outp[3]);
}

// ---------------- BN apply + transpose: K/V ----------------------------------
__global__ __launch_bounds__(256) void bn_apply_t(void) {
    __shared__ float t[32][33];
    int z = blockIdx.z;
    int proj = 1 + (z >> 3), b = z & 7;
    int p0 = blockIdx.x * 32, c0 = blockIdx.y * 32;
    int tx = threadIdx.x & 31, ty = threadIdx.x >> 5;
#pragma unroll
    for (int j = 0; j < 4; j++) {
        int c = c0 + ty + 8 * j;
        float sc = g_scale[proj][c], sh = g_shift[proj][c];
        float v = __bfloat162float(
            g_Yb[(((size_t)proj * NB + b) * COUT + c) * PP + p0 + tx]);
        v = sc * v + sh;
        v = (v < 0.0f) ? 0.1f * v : v;
        t[ty + 8 * j][tx] = v;
    }
    __syncthreads();
    bf16* T = (proj == 1) ? g_KT : g_VT;
#pragma unroll
    for (int j = 0; j < 4; j++) {
        float v = t[tx][ty + 8 * j];
        size_t o = ((size_t)b * PP + p0 + ty + 8 * j) * COUT + c0 + tx;
        T[o] = __float2bfloat16(v);
    }
}

// ---------------- launch -----------------------------------------------------
extern "C" void kernel_launch(void* const* d_in, const int* in_sizes, int n_in,
                              void* d_out, int out_size)
{
    (void)in_sizes; (void)n_in; (void)out_size;
    const float* x  = (const float*)d_in[0];
    const float* Wq = (const float*)d_in[1];
    const float* gq = (const float*)d_in[2];
    const float* bq = (const float*)d_in[3];
    const float* Wk = (const float*)d_in[4];
    const float* gk = (const float*)d_in[5];
    const float* bk = (const float*)d_in[6];
    const float* Wv = (const float*)d_in[7];
    const float* gv = (const float*)d_in[8];
    const float* bv = (const float*)d_in[9];
    float* out = (float*)d_out;

    cudaFuncSetAttribute(proj_gemm,  cudaFuncAttributeMaxDynamicSharedMemorySize, SMEM_BYTES);
    cudaFuncSetAttribute(attn_fused, cudaFuncAttributeMaxDynamicSharedMemorySize, SMEM_ATTN);

    // 1) input conversions
    convert_w<<<dim3(COUT * CIN / 4 / 256, 1, 3), 256>>>(Wq, Wk, Wv);
    transpose_x<<<dim3(PP / 32, CIN / 32, NB), 256>>>(x);
    // 2) Y = W x (bf16), fused BN partial stats
    proj_gemm<<<dim3(PP / 128, COUT / 128, 24), 256, SMEM_BYTES>>>();
    // 3) finalize BN stats (cS folded into K)
    stats_reduce<<<3 * COUT, 32>>>(gq, bq, gk, bk, gv, bv);
    // 4) BN + LeakyReLU, emit Q / K^T / V^T single bf16
    bn_apply_q<<<(unsigned)((size_t)NB * COUT * PP / 8 / 256), 256>>>();
    bn_apply_t<<<dim3(PP / 32, COUT / 32, 16), 256>>>();
    // 5) fused S -> maxless softmax -> O (512 threads, 4 warps/SMSP)
    attn_fused<<<dim3(16, 64), 512, SMEM_ATTN>>>(out);
}